// round 4
// baseline (speedup 1.0000x reference)
#include <cuda_runtime.h>
#include <cuda_bf16.h>
#include <math.h>
#include <stdint.h>

// ---------------------------------------------------------------------------
// Problem constants
// ---------------------------------------------------------------------------
#define NB   16
#define CIN  512
#define WID  128
#define OUP  512
#define HH   56
#define WW   56
#define HW   (HH*WW)     // 3136
#define MIP  16

// ---------------------------------------------------------------------------
// Scratch — __device__ globals, referenced ONLY inside device code.
// (Passing these as kernel args from host was the round-1..3 bug: host code
// resolves the symbol to the host shadow object; with ATS the kernels silently
// read/write host memory while device-side readers saw zero-init globals.)
// ---------------------------------------------------------------------------
__device__ __align__(16) float s_h1[NB*WID*HW];
__device__ __align__(16) float s_h2[NB*WID*HW];
__device__ __align__(16) float s_sm [NB*HW];
__device__ __align__(16) float s_smd[NB*HW];
__device__ __align__(16) float s_px [NB*CIN];
__device__ __align__(16) float s_p1 [NB*WID];
__device__ __align__(16) float s_p2 [NB*WID];
__device__ __align__(16) float s_c1 [NB*WID];
__device__ __align__(16) float s_c2 [NB*WID];
__device__ __align__(16) float s_c3 [NB*OUP];
__device__ __align__(16) float s_xh [NB*OUP*HH];
__device__ __align__(16) float s_xw [NB*OUP*WW];
__device__ __align__(16) float s_ah [NB*OUP*HH];
__device__ __align__(16) float s_aw [NB*OUP*WW];

// ---------------------------------------------------------------------------
// spatial mask: s_sm[b,p] = (sum_c x[b,c,p]*smw[c] + smb > 0)
// ---------------------------------------------------------------------------
__global__ void kA_smask(const float* __restrict__ x,
                         const float* __restrict__ smw,
                         const float* __restrict__ smb)
{
    __shared__ float w[CIN];
    int b = blockIdx.y;
    for (int i = threadIdx.x; i < CIN; i += blockDim.x) w[i] = smw[i];
    __syncthreads();
    int p = blockIdx.x * blockDim.x + threadIdx.x;
    if (p >= HW) return;
    const float* xb = x + ((size_t)b * CIN) * HW + p;
    float a0 = 0.f, a1 = 0.f;
    for (int c = 0; c < CIN; c += 2) {
        a0 += xb[(size_t)(c+0)*HW] * w[c+0];
        a1 += xb[(size_t)(c+1)*HW] * w[c+1];
    }
    s_sm[b * HW + p] = (a0 + a1 + smb[0]) > 0.f ? 1.f : 0.f;
}

// ---------------------------------------------------------------------------
// 3x3 max dilation of s_sm -> s_smd
// ---------------------------------------------------------------------------
__global__ void kB_dilate()
{
    __shared__ float s[HW];
    int b = blockIdx.x;
    for (int i = threadIdx.x; i < HW; i += blockDim.x) s[i] = s_sm[b*HW + i];
    __syncthreads();
    for (int i = threadIdx.x; i < HW; i += blockDim.x) {
        int h = i / WW, w = i % WW;
        float m = 0.f;
        for (int dy = -1; dy <= 1; dy++) {
            int y = h + dy; if (y < 0 || y >= HH) continue;
            for (int dx = -1; dx <= 1; dx++) {
                int xx = w + dx; if (xx < 0 || xx >= WW) continue;
                m = fmaxf(m, s[y*WW + xx]);
            }
        }
        s_smd[b*HW + i] = m;
    }
}

// ---------------------------------------------------------------------------
// mean over HW. MODE 0: x(param)->s_px, 1: s_h1->s_p1, 2: s_h2->s_p2
// src/dst selected INSIDE device code.
// ---------------------------------------------------------------------------
template<int MODE>
__global__ void kC_meanhw(const float* __restrict__ xin)
{
    const float* src = (MODE == 0) ? xin : (MODE == 1 ? s_h1 : s_h2);
    float*       dst = (MODE == 0) ? s_px : (MODE == 1 ? s_p1 : s_p2);
    int bc = blockIdx.x;
    const float* p = src + (size_t)bc * HW;
    float s = 0.f;
    for (int i = threadIdx.x; i < HW; i += 256) s += p[i];
    __shared__ float red[256];
    red[threadIdx.x] = s;
    __syncthreads();
    for (int o = 128; o > 0; o >>= 1) {
        if (threadIdx.x < o) red[threadIdx.x] += red[threadIdx.x + o];
        __syncthreads();
    }
    if (threadIdx.x == 0) dst[bc] = red[0] * (1.f / HW);
}

// ---------------------------------------------------------------------------
// channel mask. STAGE 1: s_px(512)->s_c1(128); 2: s_p1(128)->s_c2(128);
// STAGE 3: s_p2(128)->s_c3(512). Scratch selected inside device code.
// ---------------------------------------------------------------------------
template<int STAGE>
__global__ void kD_cmask(const float* __restrict__ w,
                         const float* __restrict__ bias)
{
    constexpr int CI = (STAGE == 1) ? CIN : WID;
    constexpr int CO = (STAGE == 3) ? OUP : WID;
    const float* pooled = (STAGE == 1) ? s_px : (STAGE == 2 ? s_p1 : s_p2);
    float*       mask   = (STAGE == 1) ? s_c1 : (STAGE == 2 ? s_c2 : s_c3);
    int b = blockIdx.x;
    __shared__ float pr[CI];
    for (int i = threadIdx.x; i < CI; i += blockDim.x) pr[i] = pooled[b*CI + i];
    __syncthreads();
    for (int o = threadIdx.x; o < CO; o += blockDim.x) {
        const float* wr = w + (size_t)o * CI;
        float s = bias[o];
        for (int c = 0; c < CI; c++) s += pr[c] * wr[c];
        mask[b*CO + o] = s > 0.f ? 1.f : 0.f;
    }
}

// ---------------------------------------------------------------------------
// conv1: 1x1, 512->128, epilogue relu * cm1 * smask_dil.
// 128 threads: each thread 2 output channels (oa, oa+64) x 8 pixels.
// ---------------------------------------------------------------------------
__global__ __launch_bounds__(128)
void kE_conv1(const float* __restrict__ x,
              const float* __restrict__ w1,
              const float* __restrict__ b1)
{
    __shared__ float xs[CIN * 16];              // 32 KB
    const int b  = blockIdx.y;
    const int p0 = blockIdx.x * 16;
    const int tid = threadIdx.x;

    for (int idx = tid; idx < CIN * 16; idx += 128) {
        int c = idx >> 4, p = idx & 15;
        xs[idx] = x[((size_t)b * CIN + c) * HW + p0 + p];
    }
    __syncthreads();

    const int oa = tid & 63;
    const int ob = oa + 64;
    const int ps = (tid >> 6) * 8;              // 0 or 8
    const float* wra = w1 + (size_t)oa * CIN;
    const float* wrb = w1 + (size_t)ob * CIN;

    float acca[8], accb[8];
    #pragma unroll
    for (int j = 0; j < 8; j++) { acca[j] = 0.f; accb[j] = 0.f; }
    for (int c = 0; c < CIN; c++) {
        float wa = wra[c], wb = wrb[c];
        const float* xr = &xs[c * 16 + ps];
        #pragma unroll
        for (int j = 0; j < 8; j++) {
            float v = xr[j];
            acca[j] += wa * v;
            accb[j] += wb * v;
        }
    }

    float cma = s_c1[b * WID + oa], cmb = s_c1[b * WID + ob];
    float ba = b1[oa], bb = b1[ob];
    float* ora = s_h1 + ((size_t)b * WID + oa) * HW + p0 + ps;
    float* orb = s_h1 + ((size_t)b * WID + ob) * HW + p0 + ps;
    const float* pmr = s_smd + b * HW + p0 + ps;
    #pragma unroll
    for (int j = 0; j < 8; j++) {
        float m = pmr[j];
        ora[j] = fmaxf(acca[j] + ba, 0.f) * cma * m;
        orb[j] = fmaxf(accb[j] + bb, 0.f) * cmb * m;
    }
}

// ---------------------------------------------------------------------------
// conv2: 3x3 pad 1, 128->128, epilogue relu * cm2 * smask.
// 8x8 output tile per block; 256 threads = 128 o x 2 row-halves.
// Sliding 3-row register window: ~4.8 FMA per shared load.
// ---------------------------------------------------------------------------
__global__ __launch_bounds__(256)
void kF_conv2(const float* __restrict__ w2,
              const float* __restrict__ b2)
{
    constexpr int CC = 16;
    __shared__ float tile[CC][100];             // 10x10 halo per channel
    const int b   = blockIdx.z;
    const int gx0 = blockIdx.x * 8;
    const int gy0 = blockIdx.y * 8;
    const int tid = threadIdx.x;
    const int o    = tid & 127;
    const int ry0  = (tid >> 7) * 4;            // output rows ry0..ry0+3

    float acc[4][8];
    #pragma unroll
    for (int i = 0; i < 4; i++)
        #pragma unroll
        for (int j = 0; j < 8; j++) acc[i][j] = 0.f;

    for (int c0 = 0; c0 < WID; c0 += CC) {
        for (int idx = tid; idx < CC * 100; idx += 256) {
            int cc = idx / 100, r = idx - cc * 100;
            int ty = r / 10, tx = r - ty * 10;
            int gy = gy0 + ty - 1, gx = gx0 + tx - 1;
            float v = 0.f;
            if (gy >= 0 && gy < HH && gx >= 0 && gx < WW)
                v = s_h1[((size_t)b * WID + c0 + cc) * HW + gy * WW + gx];
            tile[cc][r] = v;
        }
        __syncthreads();

        for (int cc = 0; cc < CC; cc++) {
            float w9[9];
            const float* wr = w2 + (size_t)o * (WID * 9) + (c0 + cc) * 9;
            #pragma unroll
            for (int r = 0; r < 9; r++) w9[r] = wr[r];

            float r0[10], r1[10], r2[10];
            #pragma unroll
            for (int i = 0; i < 10; i++) {
                r0[i] = tile[cc][(ry0 + 0) * 10 + i];
                r1[i] = tile[cc][(ry0 + 1) * 10 + i];
            }
            #pragma unroll
            for (int py = 0; py < 4; py++) {
                #pragma unroll
                for (int i = 0; i < 10; i++) r2[i] = tile[cc][(ry0 + py + 2) * 10 + i];
                #pragma unroll
                for (int px = 0; px < 8; px++) {
                    float s;
                    s  = w9[0]*r0[px] + w9[1]*r0[px+1] + w9[2]*r0[px+2];
                    s += w9[3]*r1[px] + w9[4]*r1[px+1] + w9[5]*r1[px+2];
                    s += w9[6]*r2[px] + w9[7]*r2[px+1] + w9[8]*r2[px+2];
                    acc[py][px] += s;
                }
                #pragma unroll
                for (int i = 0; i < 10; i++) { r0[i] = r1[i]; r1[i] = r2[i]; }
            }
        }
        __syncthreads();
    }

    float cmv = s_c2[b * WID + o];
    float bv  = b2[o];
    #pragma unroll
    for (int py = 0; py < 4; py++)
        #pragma unroll
        for (int px = 0; px < 8; px++) {
            int p = (gy0 + ry0 + py) * WW + gx0 + px;
            float v = fmaxf(acc[py][px] + bv, 0.f);
            s_h2[((size_t)b * WID + o) * HW + p] = v * cmv * s_sm[b * HW + p];
        }
}

// ---------------------------------------------------------------------------
// conv3: 1x1, 128->512, epilogue (no relu) * cm3 * smask -> d_out
// 256 threads: 2 output channels (tid, tid+256) x 16 pixels.
// ---------------------------------------------------------------------------
__global__ __launch_bounds__(256)
void kG_conv3(const float* __restrict__ w3,
              const float* __restrict__ b3,
              float* __restrict__ xout)
{
    __shared__ float xs[WID * 16];              // 8 KB
    const int b  = blockIdx.y;
    const int p0 = blockIdx.x * 16;
    const int tid = threadIdx.x;

    for (int idx = tid; idx < WID * 16; idx += 256) {
        int c = idx >> 4, p = idx & 15;
        xs[idx] = s_h2[((size_t)b * WID + c) * HW + p0 + p];
    }
    __syncthreads();

    const int oa = tid;
    const int ob = tid + 256;
    const float* wra = w3 + (size_t)oa * WID;
    const float* wrb = w3 + (size_t)ob * WID;

    float acca[16], accb[16];
    #pragma unroll
    for (int j = 0; j < 16; j++) { acca[j] = 0.f; accb[j] = 0.f; }
    for (int c = 0; c < WID; c++) {
        float wa = wra[c], wb = wrb[c];
        const float* xr = &xs[c * 16];
        #pragma unroll
        for (int j = 0; j < 16; j++) {
            float v = xr[j];
            acca[j] += wa * v;
            accb[j] += wb * v;
        }
    }

    float cma = s_c3[b * OUP + oa], cmb = s_c3[b * OUP + ob];
    float ba = b3[oa], bb = b3[ob];
    float* ora = xout + ((size_t)b * OUP + oa) * HW + p0;
    float* orb = xout + ((size_t)b * OUP + ob) * HW + p0;
    const float* pmr = s_sm + b * HW + p0;
    #pragma unroll
    for (int j = 0; j < 16; j++) {
        float m = pmr[j];
        ora[j] = (acca[j] + ba) * cma * m;
        orb[j] = (accb[j] + bb) * cmb * m;
    }
}

// ---------------------------------------------------------------------------
// row/col means of h3 (in d_out) -> s_xh, s_xw
// ---------------------------------------------------------------------------
__global__ void kH_rowcol(const float* __restrict__ h3)
{
    int bc = blockIdx.x;
    const float* img = h3 + (size_t)bc * HW;
    int t = threadIdx.x;
    if (t < WW) {
        float s = 0.f;
        for (int h = 0; h < HH; h++) s += img[h * WW + t];
        s_xw[bc * WW + t] = s * (1.f / HH);
        float r = 0.f;
        for (int w = 0; w < WW; w++) r += img[t * WW + w];
        s_xh[bc * HH + t] = r * (1.f / WW);
    }
}

// ---------------------------------------------------------------------------
// coordinate attention -> s_ah, s_aw
// ---------------------------------------------------------------------------
__global__ void kI_coord(const float* __restrict__ w1, const float* __restrict__ b1,
                         const float* __restrict__ wh, const float* __restrict__ bh,
                         const float* __restrict__ ww, const float* __restrict__ bw)
{
    int b = blockIdx.x;
    int t = threadIdx.x;                        // 128 threads
    __shared__ float w1s[MIP * OUP];            // 32 KB
    __shared__ float ys[2 * HH][MIP];
    for (int i = t; i < MIP * OUP; i += 128) w1s[i] = w1[i];
    __syncthreads();

    if (t < 2 * HH) {
        float acc[MIP];
        #pragma unroll
        for (int m = 0; m < MIP; m++) acc[m] = b1[m];
        const float* src = (t < HH)
            ? (s_xh + (size_t)b * OUP * HH + t)
            : (s_xw + (size_t)b * OUP * WW + (t - HH));
        for (int c = 0; c < OUP; c++) {
            float v = src[(size_t)c * HH];
            #pragma unroll
            for (int m = 0; m < MIP; m++) acc[m] += v * w1s[m * OUP + c];
        }
        #pragma unroll
        for (int m = 0; m < MIP; m++) {
            float u = acc[m];
            float r6 = fminf(fmaxf(u + 3.f, 0.f), 6.f);
            ys[t][m] = u * r6 * (1.f / 6.f);
        }
    }
    __syncthreads();

    for (int c = t; c < OUP; c += 128) {
        float whr[MIP], wwr[MIP];
        #pragma unroll
        for (int m = 0; m < MIP; m++) { whr[m] = wh[c*MIP + m]; wwr[m] = ww[c*MIP + m]; }
        float bhc = bh[c], bwc = bw[c];
        for (int j = 0; j < HH; j++) {
            float sh = bhc, sw = bwc;
            #pragma unroll
            for (int m = 0; m < MIP; m++) {
                sh += ys[j][m]       * whr[m];
                sw += ys[HH + j][m]  * wwr[m];
            }
            s_ah[((size_t)b * OUP + c) * HH + j] = 1.f / (1.f + expf(-sh));
            s_aw[((size_t)b * OUP + c) * WW + j] = 1.f / (1.f + expf(-sw));
        }
    }
}

// ---------------------------------------------------------------------------
// final: out = relu(h3 * ah * aw + x), in place on d_out
// ---------------------------------------------------------------------------
__global__ void kJ_final(const float* __restrict__ x, float* __restrict__ out)
{
    size_t i = (size_t)blockIdx.x * blockDim.x + threadIdx.x;
    const size_t total4 = (size_t)NB * OUP * HW / 4;
    if (i >= total4) return;
    size_t e   = i * 4;
    size_t row = e / WW;
    int    w   = (int)(e - row * WW);
    size_t bc  = row / HH;
    float a_h  = s_ah[row];
    const float* awp = s_aw + bc * WW + w;
    float4 hv = *(float4*)(out + e);
    float4 xv = *(const float4*)(x + e);
    float4 r;
    r.x = fmaxf(hv.x * a_h * awp[0] + xv.x, 0.f);
    r.y = fmaxf(hv.y * a_h * awp[1] + xv.y, 0.f);
    r.z = fmaxf(hv.z * a_h * awp[2] + xv.z, 0.f);
    r.w = fmaxf(hv.w * a_h * awp[3] + xv.w, 0.f);
    *(float4*)(out + e) = r;
}

// ---------------------------------------------------------------------------
// Launch — only harness pointers are ever passed as kernel arguments.
// ---------------------------------------------------------------------------
extern "C" void kernel_launch(void* const* d_in, const int* in_sizes, int n_in,
                              void* d_out, int out_size)
{
    const float* x     = (const float*)d_in[0];
    const float* sm_w  = (const float*)d_in[1];
    const float* sm_b  = (const float*)d_in[2];
    const float* cm1_w = (const float*)d_in[3];
    const float* cm1_b = (const float*)d_in[4];
    const float* cm2_w = (const float*)d_in[5];
    const float* cm2_b = (const float*)d_in[6];
    const float* cm3_w = (const float*)d_in[7];
    const float* cm3_b = (const float*)d_in[8];
    const float* w1    = (const float*)d_in[9];
    const float* b1    = (const float*)d_in[10];
    const float* w2    = (const float*)d_in[11];
    const float* b2    = (const float*)d_in[12];
    const float* w3    = (const float*)d_in[13];
    const float* b3    = (const float*)d_in[14];
    const float* ca_w1 = (const float*)d_in[15];
    const float* ca_b1 = (const float*)d_in[16];
    const float* ca_wh = (const float*)d_in[17];
    const float* ca_bh = (const float*)d_in[18];
    const float* ca_ww = (const float*)d_in[19];
    const float* ca_bw = (const float*)d_in[20];
    float* out = (float*)d_out;

    kA_smask<<<dim3((HW + 255) / 256, NB), 256>>>(x, sm_w, sm_b);
    kB_dilate<<<NB, 256>>>();
    kC_meanhw<0><<<NB * CIN, 256>>>(x);
    kD_cmask<1><<<NB, 256>>>(cm1_w, cm1_b);

    kE_conv1<<<dim3(HW / 16, NB), 128>>>(x, w1, b1);

    kC_meanhw<1><<<NB * WID, 256>>>(x);
    kD_cmask<2><<<NB, 256>>>(cm2_w, cm2_b);

    kF_conv2<<<dim3(WW / 8, HH / 8, NB), 256>>>(w2, b2);

    kC_meanhw<2><<<NB * WID, 256>>>(x);
    kD_cmask<3><<<NB, 256>>>(cm3_w, cm3_b);

    kG_conv3<<<dim3(HW / 16, NB), 256>>>(w3, b3, out);

    kH_rowcol<<<NB * OUP, 64>>>(out);
    kI_coord<<<NB, 128>>>(ca_w1, ca_b1, ca_wh, ca_bh, ca_ww, ca_bw);

    {
        size_t total4 = (size_t)NB * OUP * HW / 4;
        kJ_final<<<(unsigned)((total4 + 255) / 256), 256>>>(x, out);
    }
}

// round 5
// speedup vs baseline: 2.7904x; 2.7904x over previous
#include <cuda_runtime.h>
#include <cuda_bf16.h>
#include <math.h>
#include <stdint.h>

// ---------------------------------------------------------------------------
// Problem constants
// ---------------------------------------------------------------------------
#define NB   16
#define CIN  512
#define WID  128
#define OUP  512
#define HH   56
#define WW   56
#define HW   (HH*WW)     // 3136
#define MIP  16

// ---------------------------------------------------------------------------
// Scratch — __device__ globals, referenced ONLY inside device code.
// ---------------------------------------------------------------------------
__device__ __align__(16) float s_h1[NB*WID*HW];
__device__ __align__(16) float s_h2[NB*WID*HW];
__device__ __align__(16) float s_sm [NB*HW];
__device__ __align__(16) float s_smd[NB*HW];
__device__ __align__(16) float s_px [NB*CIN];
__device__ __align__(16) float s_p1 [NB*WID];
__device__ __align__(16) float s_p2 [NB*WID];
__device__ __align__(16) float s_c1 [NB*WID];
__device__ __align__(16) float s_c2 [NB*WID];
__device__ __align__(16) float s_c3 [NB*OUP];
__device__ __align__(16) float s_xh [NB*OUP*HH];
__device__ __align__(16) float s_xw [NB*OUP*WW];
__device__ __align__(16) float s_ah [NB*OUP*HH];
__device__ __align__(16) float s_aw [NB*OUP*WW];

// ---------------------------------------------------------------------------
// spatial mask: s_sm[b,p] = (sum_c x[b,c,p]*smw[c] + smb > 0)
// ---------------------------------------------------------------------------
__global__ void kA_smask(const float* __restrict__ x,
                         const float* __restrict__ smw,
                         const float* __restrict__ smb)
{
    __shared__ float w[CIN];
    int b = blockIdx.y;
    for (int i = threadIdx.x; i < CIN; i += blockDim.x) w[i] = smw[i];
    __syncthreads();
    int p = blockIdx.x * blockDim.x + threadIdx.x;
    if (p >= HW) return;
    const float* xb = x + ((size_t)b * CIN) * HW + p;
    float a0 = 0.f, a1 = 0.f, a2 = 0.f, a3 = 0.f;
    #pragma unroll 4
    for (int c = 0; c < CIN; c += 4) {
        a0 += xb[(size_t)(c+0)*HW] * w[c+0];
        a1 += xb[(size_t)(c+1)*HW] * w[c+1];
        a2 += xb[(size_t)(c+2)*HW] * w[c+2];
        a3 += xb[(size_t)(c+3)*HW] * w[c+3];
    }
    s_sm[b * HW + p] = ((a0 + a1) + (a2 + a3) + smb[0]) > 0.f ? 1.f : 0.f;
}

// ---------------------------------------------------------------------------
// 3x3 max dilation of s_sm -> s_smd
// ---------------------------------------------------------------------------
__global__ void kB_dilate()
{
    __shared__ float s[HW];
    int b = blockIdx.x;
    for (int i = threadIdx.x; i < HW; i += blockDim.x) s[i] = s_sm[b*HW + i];
    __syncthreads();
    for (int i = threadIdx.x; i < HW; i += blockDim.x) {
        int h = i / WW, w = i % WW;
        float m = 0.f;
        for (int dy = -1; dy <= 1; dy++) {
            int y = h + dy; if (y < 0 || y >= HH) continue;
            for (int dx = -1; dx <= 1; dx++) {
                int xx = w + dx; if (xx < 0 || xx >= WW) continue;
                m = fmaxf(m, s[y*WW + xx]);
            }
        }
        s_smd[b*HW + i] = m;
    }
}

// ---------------------------------------------------------------------------
// mean over HW. MODE 0: x->s_px, 1: s_h1->s_p1, 2: s_h2->s_p2
// ---------------------------------------------------------------------------
template<int MODE>
__global__ void kC_meanhw(const float* __restrict__ xin)
{
    const float* src = (MODE == 0) ? xin : (MODE == 1 ? s_h1 : s_h2);
    float*       dst = (MODE == 0) ? s_px : (MODE == 1 ? s_p1 : s_p2);
    int bc = blockIdx.x;
    const float* p = src + (size_t)bc * HW;
    float s = 0.f;
    for (int i = threadIdx.x; i < HW; i += 256) s += p[i];
    __shared__ float red[256];
    red[threadIdx.x] = s;
    __syncthreads();
    for (int o = 128; o > 0; o >>= 1) {
        if (threadIdx.x < o) red[threadIdx.x] += red[threadIdx.x + o];
        __syncthreads();
    }
    if (threadIdx.x == 0) dst[bc] = red[0] * (1.f / HW);
}

// ---------------------------------------------------------------------------
// channel mask, warp-per-output with coalesced weight loads.
// STAGE 1: s_px(512)->s_c1(128); 2: s_p1->s_c2; 3: s_p2->s_c3(512)
// ---------------------------------------------------------------------------
template<int STAGE>
__global__ void kD_cmask(const float* __restrict__ w,
                         const float* __restrict__ bias)
{
    constexpr int CI = (STAGE == 1) ? CIN : WID;
    constexpr int CO = (STAGE == 3) ? OUP : WID;
    const float* pooled = (STAGE == 1) ? s_px : (STAGE == 2 ? s_p1 : s_p2);
    float*       mask   = (STAGE == 1) ? s_c1 : (STAGE == 2 ? s_c2 : s_c3);
    int b = blockIdx.x;
    __shared__ float pr[CI];
    for (int i = threadIdx.x; i < CI; i += blockDim.x) pr[i] = pooled[b*CI + i];
    __syncthreads();
    int warp = threadIdx.x >> 5, lane = threadIdx.x & 31;
    for (int o = warp; o < CO; o += 8) {
        const float* wr = w + (size_t)o * CI;
        float s = 0.f;
        #pragma unroll 4
        for (int c = lane; c < CI; c += 32) s += pr[c] * wr[c];
        #pragma unroll
        for (int off = 16; off > 0; off >>= 1) s += __shfl_xor_sync(0xffffffffu, s, off);
        if (lane == 0) mask[b*CO + o] = (s + bias[o]) > 0.f ? 1.f : 0.f;
    }
}

// ---------------------------------------------------------------------------
// Conv GEMM: 128x128 tile, BK=8, 8x8 micro-tile, 256 threads, double-buffered.
// MODE 1: conv1 1x1  M=128 K=512  In=x     Out=s_h1  cm=s_c1 pm=s_smd relu
// MODE 2: conv2 3x3  M=128 K=1152 In=s_h1  Out=s_h2  cm=s_c2 pm=s_sm  relu (im2col)
// MODE 3: conv3 1x1  M=512 K=128  In=s_h2  Out=d_out cm=s_c3 pm=s_sm  no relu
// ---------------------------------------------------------------------------
template<int MODE, int M, int K, int CI>
__global__ __launch_bounds__(256)
void conv_gemm(const float* __restrict__ A,     // weights (M x K)
               const float* __restrict__ bias,  // (M)
               const float* __restrict__ xin,   // x (MODE 1)
               float* __restrict__ xout)        // d_out (MODE 3)
{
    constexpr int BK = 8;
    const float* In  = (MODE == 1) ? xin  : (MODE == 2 ? s_h1 : s_h2);
    float*       Out = (MODE == 1) ? s_h1 : (MODE == 2 ? s_h2 : xout);
    const float* cm  = (MODE == 1) ? s_c1 : (MODE == 2 ? s_c2 : s_c3);
    const float* pm  = (MODE == 1) ? s_smd : s_sm;

    __shared__ __align__(16) float As[2][BK][128];
    __shared__ __align__(16) float Bs[2][BK][128];

    const int tid = threadIdx.x;
    const int tx  = tid & 15;
    const int ty  = tid >> 4;
    const int b   = blockIdx.z;
    const int m0  = blockIdx.y * 128;
    const int n0  = blockIdx.x * 128;

    const int la_m = tid >> 1;
    const int la_k = (tid & 1) * 4;
    const int lb_k = tid >> 5;
    const int lb_n = (tid & 31) * 4;

    float4 va;
    float  bv0, bv1, bv2, bv3;

    // ---- fetch of tile at k0 into registers ----
    auto fetch = [&](int k0) {
        va = *(const float4*)&A[(size_t)(m0 + la_m) * K + k0 + la_k];
        if (MODE != 2) {
            int p = n0 + lb_n;
            int c = k0 + lb_k;
            if (p < HW) {
                float4 v = *(const float4*)&In[((size_t)b * CI + c) * HW + p];
                bv0 = v.x; bv1 = v.y; bv2 = v.z; bv3 = v.w;
            } else { bv0 = bv1 = bv2 = bv3 = 0.f; }
        } else {
            int gk = k0 + lb_k;
            int c  = gk / 9;
            int r  = gk - c * 9;
            int ky = r / 3 - 1;
            int kx = r - (r / 3) * 3 - 1;
            const float* base = In + ((size_t)b * CI + c) * HW;
            float t[4];
            #pragma unroll
            for (int j = 0; j < 4; j++) {
                int p = n0 + lb_n + j;
                float v = 0.f;
                if (p < HW) {
                    int py = p / WW, px = p - py * WW;
                    int iy = py + ky, ix = px + kx;
                    if (iy >= 0 && iy < HH && ix >= 0 && ix < WW)
                        v = base[iy * WW + ix];
                }
                t[j] = v;
            }
            bv0 = t[0]; bv1 = t[1]; bv2 = t[2]; bv3 = t[3];
        }
    };
    auto stage = [&](int buf) {
        As[buf][la_k + 0][la_m] = va.x;
        As[buf][la_k + 1][la_m] = va.y;
        As[buf][la_k + 2][la_m] = va.z;
        As[buf][la_k + 3][la_m] = va.w;
        Bs[buf][lb_k][lb_n + 0] = bv0;
        Bs[buf][lb_k][lb_n + 1] = bv1;
        Bs[buf][lb_k][lb_n + 2] = bv2;
        Bs[buf][lb_k][lb_n + 3] = bv3;
    };

    float acc[8][8];
    #pragma unroll
    for (int i = 0; i < 8; i++)
        #pragma unroll
        for (int j = 0; j < 8; j++) acc[i][j] = 0.f;

    fetch(0);
    stage(0);
    __syncthreads();

    int buf = 0;
    for (int k0 = 0; k0 < K; k0 += BK) {
        if (k0 + BK < K) fetch(k0 + BK);

        #pragma unroll
        for (int k = 0; k < BK; k++) {
            float4 a0 = *(const float4*)&As[buf][k][ty * 8];
            float4 a1 = *(const float4*)&As[buf][k][ty * 8 + 4];
            float4 b0 = *(const float4*)&Bs[buf][k][tx * 8];
            float4 b1 = *(const float4*)&Bs[buf][k][tx * 8 + 4];
            float af[8] = {a0.x,a0.y,a0.z,a0.w,a1.x,a1.y,a1.z,a1.w};
            float bf[8] = {b0.x,b0.y,b0.z,b0.w,b1.x,b1.y,b1.z,b1.w};
            #pragma unroll
            for (int i = 0; i < 8; i++)
                #pragma unroll
                for (int j = 0; j < 8; j++)
                    acc[i][j] += af[i] * bf[j];
        }

        if (k0 + BK < K) stage(buf ^ 1);
        __syncthreads();
        buf ^= 1;
    }

    // ---- epilogue: bias, (relu), channel mask, spatial mask ----
    const int pbase = n0 + tx * 8;
    #pragma unroll
    for (int i = 0; i < 8; i++) {
        int o = m0 + ty * 8 + i;
        float cb  = bias[o];
        float cmv = cm[b * M + o];
        float* orow = Out + ((size_t)b * M + o) * HW;
        #pragma unroll
        for (int g = 0; g < 2; g++) {
            int p = pbase + g * 4;
            if (p < HW) {
                float4 r;
                float m0v = pm[b * HW + p + 0];
                float m1v = pm[b * HW + p + 1];
                float m2v = pm[b * HW + p + 2];
                float m3v = pm[b * HW + p + 3];
                float v0 = acc[i][g*4+0] + cb;
                float v1 = acc[i][g*4+1] + cb;
                float v2 = acc[i][g*4+2] + cb;
                float v3 = acc[i][g*4+3] + cb;
                if (MODE != 3) {
                    v0 = fmaxf(v0, 0.f); v1 = fmaxf(v1, 0.f);
                    v2 = fmaxf(v2, 0.f); v3 = fmaxf(v3, 0.f);
                }
                r.x = v0 * cmv * m0v;
                r.y = v1 * cmv * m1v;
                r.z = v2 * cmv * m2v;
                r.w = v3 * cmv * m3v;
                *(float4*)&orow[p] = r;
            }
        }
    }
}

// ---------------------------------------------------------------------------
// row/col means of h3 (in d_out) -> s_xh, s_xw
// ---------------------------------------------------------------------------
__global__ void kH_rowcol(const float* __restrict__ h3)
{
    int bc = blockIdx.x;
    const float* img = h3 + (size_t)bc * HW;
    int t = threadIdx.x;
    if (t < WW) {
        float s = 0.f;
        for (int h = 0; h < HH; h++) s += img[h * WW + t];
        s_xw[bc * WW + t] = s * (1.f / HH);
        float r = 0.f;
        for (int w = 0; w < WW; w++) r += img[t * WW + w];
        s_xh[bc * HH + t] = r * (1.f / WW);
    }
}

// ---------------------------------------------------------------------------
// coordinate attention -> s_ah, s_aw
// ---------------------------------------------------------------------------
__global__ void kI_coord(const float* __restrict__ w1, const float* __restrict__ b1,
                         const float* __restrict__ wh, const float* __restrict__ bh,
                         const float* __restrict__ ww, const float* __restrict__ bw)
{
    int b = blockIdx.x;
    int t = threadIdx.x;                        // 128 threads
    __shared__ float w1s[MIP * OUP];
    __shared__ float ys[2 * HH][MIP];
    for (int i = t; i < MIP * OUP; i += 128) w1s[i] = w1[i];
    __syncthreads();

    if (t < 2 * HH) {
        float acc[MIP];
        #pragma unroll
        for (int m = 0; m < MIP; m++) acc[m] = b1[m];
        const float* src = (t < HH)
            ? (s_xh + (size_t)b * OUP * HH + t)
            : (s_xw + (size_t)b * OUP * WW + (t - HH));
        for (int c = 0; c < OUP; c++) {
            float v = src[(size_t)c * HH];
            #pragma unroll
            for (int m = 0; m < MIP; m++) acc[m] += v * w1s[m * OUP + c];
        }
        #pragma unroll
        for (int m = 0; m < MIP; m++) {
            float u = acc[m];
            float r6 = fminf(fmaxf(u + 3.f, 0.f), 6.f);
            ys[t][m] = u * r6 * (1.f / 6.f);
        }
    }
    __syncthreads();

    for (int c = t; c < OUP; c += 128) {
        float whr[MIP], wwr[MIP];
        #pragma unroll
        for (int m = 0; m < MIP; m++) { whr[m] = wh[c*MIP + m]; wwr[m] = ww[c*MIP + m]; }
        float bhc = bh[c], bwc = bw[c];
        for (int j = 0; j < HH; j++) {
            float sh = bhc, sw = bwc;
            #pragma unroll
            for (int m = 0; m < MIP; m++) {
                sh += ys[j][m]       * whr[m];
                sw += ys[HH + j][m]  * wwr[m];
            }
            s_ah[((size_t)b * OUP + c) * HH + j] = 1.f / (1.f + expf(-sh));
            s_aw[((size_t)b * OUP + c) * WW + j] = 1.f / (1.f + expf(-sw));
        }
    }
}

// ---------------------------------------------------------------------------
// final: out = relu(h3 * ah * aw + x), in place on d_out
// ---------------------------------------------------------------------------
__global__ void kJ_final(const float* __restrict__ x, float* __restrict__ out)
{
    size_t i = (size_t)blockIdx.x * blockDim.x + threadIdx.x;
    const size_t total4 = (size_t)NB * OUP * HW / 4;
    if (i >= total4) return;
    size_t e   = i * 4;
    size_t row = e / WW;
    int    w   = (int)(e - row * WW);
    size_t bc  = row / HH;
    float a_h  = s_ah[row];
    const float* awp = s_aw + bc * WW + w;
    float4 hv = *(float4*)(out + e);
    float4 xv = *(const float4*)(x + e);
    float4 r;
    r.x = fmaxf(hv.x * a_h * awp[0] + xv.x, 0.f);
    r.y = fmaxf(hv.y * a_h * awp[1] + xv.y, 0.f);
    r.z = fmaxf(hv.z * a_h * awp[2] + xv.z, 0.f);
    r.w = fmaxf(hv.w * a_h * awp[3] + xv.w, 0.f);
    *(float4*)(out + e) = r;
}

// ---------------------------------------------------------------------------
// Launch — only harness pointers are ever passed as kernel arguments.
// ---------------------------------------------------------------------------
extern "C" void kernel_launch(void* const* d_in, const int* in_sizes, int n_in,
                              void* d_out, int out_size)
{
    const float* x     = (const float*)d_in[0];
    const float* sm_w  = (const float*)d_in[1];
    const float* sm_b  = (const float*)d_in[2];
    const float* cm1_w = (const float*)d_in[3];
    const float* cm1_b = (const float*)d_in[4];
    const float* cm2_w = (const float*)d_in[5];
    const float* cm2_b = (const float*)d_in[6];
    const float* cm3_w = (const float*)d_in[7];
    const float* cm3_b = (const float*)d_in[8];
    const float* w1    = (const float*)d_in[9];
    const float* b1    = (const float*)d_in[10];
    const float* w2    = (const float*)d_in[11];
    const float* b2    = (const float*)d_in[12];
    const float* w3    = (const float*)d_in[13];
    const float* b3    = (const float*)d_in[14];
    const float* ca_w1 = (const float*)d_in[15];
    const float* ca_b1 = (const float*)d_in[16];
    const float* ca_wh = (const float*)d_in[17];
    const float* ca_bh = (const float*)d_in[18];
    const float* ca_ww = (const float*)d_in[19];
    const float* ca_bw = (const float*)d_in[20];
    float* out = (float*)d_out;

    kA_smask<<<dim3((HW + 255) / 256, NB), 256>>>(x, sm_w, sm_b);
    kB_dilate<<<NB, 256>>>();
    kC_meanhw<0><<<NB * CIN, 256>>>(x);
    kD_cmask<1><<<NB, 256>>>(cm1_w, cm1_b);

    conv_gemm<1, WID, CIN, CIN><<<dim3(25, 1, NB), 256>>>(w1, b1, x, out);

    kC_meanhw<1><<<NB * WID, 256>>>(x);
    kD_cmask<2><<<NB, 256>>>(cm2_w, cm2_b);

    conv_gemm<2, WID, WID*9, WID><<<dim3(25, 1, NB), 256>>>(w2, b2, x, out);

    kC_meanhw<2><<<NB * WID, 256>>>(x);
    kD_cmask<3><<<NB, 256>>>(cm3_w, cm3_b);

    conv_gemm<3, OUP, WID, WID><<<dim3(25, 4, NB), 256>>>(w3, b3, x, out);

    kH_rowcol<<<NB * OUP, 64>>>(out);
    kI_coord<<<NB, 128>>>(ca_w1, ca_b1, ca_wh, ca_bh, ca_ww, ca_bw);

    {
        size_t total4 = (size_t)NB * OUP * HW / 4;
        kJ_final<<<(unsigned)((total4 + 255) / 256), 256>>>(x, out);
    }
}

// round 7
// speedup vs baseline: 4.7342x; 1.6966x over previous
#include <cuda_runtime.h>
#include <cuda_bf16.h>
#include <math.h>
#include <stdint.h>

// ---------------------------------------------------------------------------
// Problem constants
// ---------------------------------------------------------------------------
#define NB   16
#define CIN  512
#define WID  128
#define OUP  512
#define HH   56
#define WW   56
#define HW   (HH*WW)     // 3136
#define MIP  16

union U8 { __nv_bfloat16 h[8]; uint4 u; };

__device__ __forceinline__ uint32_t smem_u32(const void* p) {
    uint32_t a;
    asm("{ .reg .u64 t; cvta.to.shared.u64 t, %1; cvt.u32.u64 %0, t; }" : "=r"(a) : "l"(p));
    return a;
}
__device__ __forceinline__ void ldsm4(uint32_t* r, uint32_t a) {
    asm volatile("ldmatrix.sync.aligned.m8n8.x4.shared.b16 {%0,%1,%2,%3}, [%4];"
                 : "=r"(r[0]), "=r"(r[1]), "=r"(r[2]), "=r"(r[3]) : "r"(a));
}
__device__ __forceinline__ void mma_bf(float* c, const uint32_t* a, uint32_t b0, uint32_t b1) {
    asm volatile("mma.sync.aligned.m16n8k16.row.col.f32.bf16.bf16.f32 "
                 "{%0,%1,%2,%3}, {%4,%5,%6,%7}, {%8,%9}, {%0,%1,%2,%3};"
                 : "+f"(c[0]), "+f"(c[1]), "+f"(c[2]), "+f"(c[3])
                 : "r"(a[0]), "r"(a[1]), "r"(a[2]), "r"(a[3]), "r"(b0), "r"(b1));
}

// ---------------------------------------------------------------------------
// Scratch — __device__ globals, referenced ONLY inside device code.
// ---------------------------------------------------------------------------
__device__ __align__(128) __nv_bfloat16 gx_hi [NB*HW*CIN];
__device__ __align__(128) __nv_bfloat16 gx_lo [NB*HW*CIN];
__device__ __align__(128) __nv_bfloat16 gh1_hi[NB*HW*WID];
__device__ __align__(128) __nv_bfloat16 gh1_lo[NB*HW*WID];
__device__ __align__(128) __nv_bfloat16 gh2_hi[NB*HW*WID];
__device__ __align__(128) __nv_bfloat16 gh2_lo[NB*HW*WID];
__device__ __align__(128) __nv_bfloat16 gw1h[WID*CIN],  gw1l[WID*CIN];
__device__ __align__(128) __nv_bfloat16 gw2h[WID*1152], gw2l[WID*1152];
__device__ __align__(128) __nv_bfloat16 gw3h[OUP*WID],  gw3l[OUP*WID];
__device__ __align__(16) float s_sm [NB*HW];
__device__ __align__(16) float s_smd[NB*HW];
__device__ __align__(16) float s_ppx[NB*8*CIN];
__device__ __align__(16) float s_pp1[NB*8*WID];
__device__ __align__(16) float s_pp2[NB*8*WID];
__device__ __align__(16) float s_c1 [NB*WID];
__device__ __align__(16) float s_c2 [NB*WID];
__device__ __align__(16) float s_c3 [NB*OUP];
__device__ __align__(16) float s_xh [NB*OUP*HH];
__device__ __align__(16) float s_xw [NB*OUP*WW];
__device__ __align__(16) float s_ah [NB*OUP*HH];
__device__ __align__(16) float s_aw [NB*OUP*WW];

// ---------------------------------------------------------------------------
// kT: transpose + bf16-split x [b,c,p] fp32 -> gx_hi/lo [b,p,c]
// ---------------------------------------------------------------------------
__global__ __launch_bounds__(256) void kT_transx(const float* __restrict__ x)
{
    __shared__ float ts[64][65];
    const int b  = blockIdx.z;
    const int c0 = blockIdx.y * 64;
    const int p0 = blockIdx.x * 64;
    const int t  = threadIdx.x;
    {
        int ci = t >> 2, jg = (t & 3) * 16;
        const float* src = x + ((size_t)b * CIN + c0 + ci) * HW + p0 + jg;
        #pragma unroll
        for (int q = 0; q < 4; q++) {
            float4 f = *(const float4*)(src + q * 4);
            ts[ci][jg + q*4 + 0] = f.x; ts[ci][jg + q*4 + 1] = f.y;
            ts[ci][jg + q*4 + 2] = f.z; ts[ci][jg + q*4 + 3] = f.w;
        }
    }
    __syncthreads();
    {
        int pi = t >> 2, cg = (t & 3) * 16;
        __nv_bfloat16* oh = gx_hi + ((size_t)b * HW + p0 + pi) * CIN + c0 + cg;
        __nv_bfloat16* ol = gx_lo + ((size_t)b * HW + p0 + pi) * CIN + c0 + cg;
        #pragma unroll
        for (int g = 0; g < 2; g++) {
            U8 hh, ll;
            #pragma unroll
            for (int j = 0; j < 8; j++) {
                float v = ts[cg + g*8 + j][pi];
                __nv_bfloat16 h = __float2bfloat16(v);
                hh.h[j] = h;
                ll.h[j] = __float2bfloat16(v - __bfloat162float(h));
            }
            *(uint4*)(oh + g*8) = hh.u;
            *(uint4*)(ol + g*8) = ll.u;
        }
    }
}

// ---------------------------------------------------------------------------
// kW: weight fp32 -> split bf16 (+ conv2 reorder k = r*128+c from [o][c*9+r])
// ---------------------------------------------------------------------------
template<int MODE>
__global__ void kW_split(const float* __restrict__ W)
{
    constexpr int M = (MODE == 3) ? OUP : WID;
    constexpr int K = (MODE == 1) ? CIN : ((MODE == 2) ? 1152 : WID);
    __nv_bfloat16* oh = (MODE == 1) ? gw1h : (MODE == 2 ? gw2h : gw3h);
    __nv_bfloat16* ol = (MODE == 1) ? gw1l : (MODE == 2 ? gw2l : gw3l);
    int i = blockIdx.x * 256 + threadIdx.x;
    if (i >= M * K) return;
    int o = i / K, k = i - o * K;
    float v;
    if (MODE == 2) {
        int r = k >> 7, c = k & 127;
        v = W[(size_t)o * 1152 + c * 9 + r];
    } else v = W[i];
    __nv_bfloat16 h = __float2bfloat16(v);
    oh[i] = h;
    ol[i] = __float2bfloat16(v - __bfloat162float(h));
}

// ---------------------------------------------------------------------------
// kS: spatial mask from gx (hi+lo). warp per pixel.
// ---------------------------------------------------------------------------
__global__ __launch_bounds__(256) void kS_smask(const float* __restrict__ smw,
                                                const float* __restrict__ smb)
{
    __shared__ float w[CIN];
    const int b = blockIdx.y;
    for (int i = threadIdx.x; i < CIN; i += 256) w[i] = smw[i];
    __syncthreads();
    const int wrp = threadIdx.x >> 5, lane = threadIdx.x & 31;
    const int p = blockIdx.x * 8 + wrp;
    const __nv_bfloat16* ph = gx_hi + ((size_t)b * HW + p) * CIN + lane * 16;
    const __nv_bfloat16* pl = gx_lo + ((size_t)b * HW + p) * CIN + lane * 16;
    float s = 0.f;
    #pragma unroll
    for (int g = 0; g < 2; g++) {
        U8 hh, ll;
        hh.u = *(const uint4*)(ph + g*8);
        ll.u = *(const uint4*)(pl + g*8);
        #pragma unroll
        for (int j = 0; j < 8; j++)
            s += (__bfloat162float(hh.h[j]) + __bfloat162float(ll.h[j])) * w[lane*16 + g*8 + j];
    }
    #pragma unroll
    for (int o = 16; o > 0; o >>= 1) s += __shfl_xor_sync(0xffffffffu, s, o);
    if (lane == 0) s_sm[b * HW + p] = (s + smb[0]) > 0.f ? 1.f : 0.f;
}

// ---------------------------------------------------------------------------
// kB: 3x3 max dilation of s_sm -> s_smd
// ---------------------------------------------------------------------------
__global__ void kB_dilate()
{
    __shared__ float s[HW];
    int b = blockIdx.x;
    for (int i = threadIdx.x; i < HW; i += blockDim.x) s[i] = s_sm[b*HW + i];
    __syncthreads();
    for (int i = threadIdx.x; i < HW; i += blockDim.x) {
        int h = i / WW, w = i % WW;
        float m = 0.f;
        for (int dy = -1; dy <= 1; dy++) {
            int y = h + dy; if (y < 0 || y >= HH) continue;
            for (int dx = -1; dx <= 1; dx++) {
                int xx = w + dx; if (xx < 0 || xx >= WW) continue;
                m = fmaxf(m, s[y*WW + xx]);
            }
        }
        s_smd[b*HW + i] = m;
    }
}

// ---------------------------------------------------------------------------
// kM: partial channel sums over pixel range. S 0:gx(512) 1:gh1(128) 2:gh2(128)
// ---------------------------------------------------------------------------
template<int S>
__global__ void kM_partial()
{
    constexpr int C = (S == 0) ? CIN : WID;
    const __nv_bfloat16* hh = (S == 0) ? gx_hi : (S == 1 ? gh1_hi : gh2_hi);
    const __nv_bfloat16* ll = (S == 0) ? gx_lo : (S == 1 ? gh1_lo : gh2_lo);
    float* part = (S == 0) ? s_ppx : (S == 1 ? s_pp1 : s_pp2);
    const int b = blockIdx.y, ch = blockIdx.x, c = threadIdx.x;
    const __nv_bfloat16* bh = hh + ((size_t)b * HW + ch * 392) * C + c;
    const __nv_bfloat16* bl = ll + ((size_t)b * HW + ch * 392) * C + c;
    float s = 0.f;
    for (int p = 0; p < 392; p++)
        s += __bfloat162float(bh[(size_t)p * C]) + __bfloat162float(bl[(size_t)p * C]);
    part[((size_t)b * 8 + ch) * C + c] = s;
}

// ---------------------------------------------------------------------------
// kD: channel mask from partial sums.
// ---------------------------------------------------------------------------
template<int STAGE>
__global__ void kD_cmask(const float* __restrict__ w,
                         const float* __restrict__ bias)
{
    constexpr int CI = (STAGE == 1) ? CIN : WID;
    constexpr int CO = (STAGE == 3) ? OUP : WID;
    const float* part = (STAGE == 1) ? s_ppx : (STAGE == 2 ? s_pp1 : s_pp2);
    float*       mask = (STAGE == 1) ? s_c1 : (STAGE == 2 ? s_c2 : s_c3);
    int b = blockIdx.x;
    __shared__ float pr[CI];
    for (int i = threadIdx.x; i < CI; i += blockDim.x) {
        float s = 0.f;
        #pragma unroll
        for (int k = 0; k < 8; k++) s += part[((size_t)b * 8 + k) * CI + i];
        pr[i] = s * (1.f / HW);
    }
    __syncthreads();
    int wrp = threadIdx.x >> 5, lane = threadIdx.x & 31;
    for (int o = wrp; o < CO; o += 8) {
        const float* wr = w + (size_t)o * CI;
        float s = 0.f;
        #pragma unroll 4
        for (int c = lane; c < CI; c += 32) s += pr[c] * wr[c];
        #pragma unroll
        for (int off = 16; off > 0; off >>= 1) s += __shfl_xor_sync(0xffffffffu, s, off);
        if (lane == 0) mask[b*CO + o] = (s + bias[o]) > 0.f ? 1.f : 0.f;
    }
}

// ---------------------------------------------------------------------------
// conv_mma: mma.sync bf16-split GEMM. D[pix][oc] = act[pix][k] . w[oc][k]
// Block: 128 pixels x 128 oc, 8 warps (4m x 2n), warp tile 32x64, K chunk 64.
// MODE 1: conv1 K=512  act=gx  -> gh1 split (relu*cm1*smd)
// MODE 2: conv2 K=1152 act=gh1 -> gh2 split (relu*cm2*sm)   r=chunk>>1
// MODE 3: conv3 K=128  act=gh2 -> d_out fp32 [oc][p] (*cm3*sm)
// ---------------------------------------------------------------------------
#define A_HI 0
#define A_LO 18432
#define B_HI 36864
#define B_LO 55296
#define CONV_DSM 73728

template<int MODE, int NOC, int K, int CI>
__global__ __launch_bounds__(256)
void conv_mma(const float* __restrict__ bias, float* __restrict__ xout)
{
    extern __shared__ char dsm[];
    const uint32_t sb = smem_u32(dsm);
    __shared__ float pmv[128], cmb[128], bb[128];

    const int tid  = threadIdx.x;
    const int wid  = tid >> 5;
    const int lane = tid & 31;
    const int b    = blockIdx.z;
    const int m0   = blockIdx.x * 128;       // pixel base
    const int n0g  = blockIdx.y * 128;       // out-channel base

    const __nv_bfloat16* act_h = (MODE == 1) ? gx_hi : (MODE == 2 ? gh1_hi : gh2_hi);
    const __nv_bfloat16* act_l = (MODE == 1) ? gx_lo : (MODE == 2 ? gh1_lo : gh2_lo);
    const __nv_bfloat16* wt_h  = (MODE == 1) ? gw1h : (MODE == 2 ? gw2h : gw3h);
    const __nv_bfloat16* wt_l  = (MODE == 1) ? gw1l : (MODE == 2 ? gw2l : gw3l);
    const float* cm = (MODE == 1) ? s_c1 : (MODE == 2 ? s_c2 : s_c3);
    const float* pm = (MODE == 1) ? s_smd : s_sm;

    if (tid < 128) {
        int p = m0 + tid;
        pmv[tid] = (p < HW) ? pm[b * HW + p] : 0.f;
        cmb[tid] = cm[b * NOC + n0g + tid];
        bb[tid]  = bias[n0g + tid];
    }

    float cacc[2][8][4];
    #pragma unroll
    for (int i = 0; i < 2; i++)
        #pragma unroll
        for (int j = 0; j < 8; j++)
            #pragma unroll
            for (int q = 0; q < 4; q++) cacc[i][j][q] = 0.f;

    const int wm = wid >> 1, wn = wid & 1;
    const int lr = lane & 7, s23 = lane >> 3;
    const int arow = (s23 & 1) * 8 + lr, acol = (s23 >> 1) * 8;
    const int brow = (s23 >> 1) * 8 + lr, bcol = (s23 & 1) * 8;

    const int prow = tid >> 1, ug = (tid & 1) * 4;

    for (int ch = 0; ch < K / 64; ch++) {
        const int k0 = ch * 64;
        // ---- A (activations) ----
        {
            int p = m0 + prow;
            bool valid; int q, c0;
            if (MODE == 2) {
                int r  = ch >> 1;
                int ky = r / 3 - 1, kx = r % 3 - 1;
                int py = p / WW, px = p - py * WW;
                int iy = py + ky, ix = px + kx;
                valid = (p < HW) && iy >= 0 && iy < HH && ix >= 0 && ix < WW;
                q = iy * WW + ix;
                c0 = (ch & 1) * 64;
            } else { valid = (p < HW); q = p; c0 = k0; }
            const uint4* ahp = (const uint4*)(act_h + ((size_t)b * HW + (valid ? q : 0)) * CI + c0);
            const uint4* alp = (const uint4*)(act_l + ((size_t)b * HW + (valid ? q : 0)) * CI + c0);
            uint4* dh = (uint4*)(dsm + A_HI + prow * 144 + ug * 16);
            uint4* dl = (uint4*)(dsm + A_LO + prow * 144 + ug * 16);
            #pragma unroll
            for (int u = 0; u < 4; u++) {
                dh[u] = valid ? ahp[ug + u] : make_uint4(0, 0, 0, 0);
                dl[u] = valid ? alp[ug + u] : make_uint4(0, 0, 0, 0);
            }
        }
        // ---- B (weights, pre-split) ----
        {
            const uint4* whp = (const uint4*)(wt_h + ((size_t)(n0g + prow)) * K + k0);
            const uint4* wlp = (const uint4*)(wt_l + ((size_t)(n0g + prow)) * K + k0);
            uint4* dh = (uint4*)(dsm + B_HI + prow * 144 + ug * 16);
            uint4* dl = (uint4*)(dsm + B_LO + prow * 144 + ug * 16);
            #pragma unroll
            for (int u = 0; u < 4; u++) { dh[u] = whp[ug + u]; dl[u] = wlp[ug + u]; }
        }
        __syncthreads();

        #pragma unroll
        for (int s = 0; s < 4; s++) {
            const int kb = s * 16;
            uint32_t ah[2][4], al[2][4];
            #pragma unroll
            for (int mi = 0; mi < 2; mi++) {
                uint32_t off = (uint32_t)((wm * 32 + mi * 16 + arow) * 144 + (kb + acol) * 2);
                ldsm4(ah[mi], sb + A_HI + off);
                ldsm4(al[mi], sb + A_LO + off);
            }
            #pragma unroll
            for (int np = 0; np < 4; np++) {
                uint32_t bh[4], bl[4];
                uint32_t off = (uint32_t)((wn * 64 + np * 16 + brow) * 144 + (kb + bcol) * 2);
                ldsm4(bh, sb + B_HI + off);
                ldsm4(bl, sb + B_LO + off);
                #pragma unroll
                for (int mi = 0; mi < 2; mi++) {
                    float* c0p = cacc[mi][np * 2];
                    float* c1p = cacc[mi][np * 2 + 1];
                    mma_bf(c0p, ah[mi], bh[0], bh[1]);
                    mma_bf(c0p, al[mi], bh[0], bh[1]);
                    mma_bf(c0p, ah[mi], bl[0], bl[1]);
                    mma_bf(c1p, ah[mi], bh[2], bh[3]);
                    mma_bf(c1p, al[mi], bh[2], bh[3]);
                    mma_bf(c1p, ah[mi], bl[2], bl[3]);
                }
            }
        }
        __syncthreads();
    }

    // ---- epilogue ----
    const int g = lane >> 2, tg = lane & 3;
    if (MODE != 3) {
        __nv_bfloat16* ohg = (MODE == 1 ? gh1_hi : gh2_hi);
        __nv_bfloat16* olg = (MODE == 1 ? gh1_lo : gh2_lo);
        #pragma unroll
        for (int mi = 0; mi < 2; mi++) {
            #pragma unroll
            for (int h = 0; h < 2; h++) {
                int pl = wm * 32 + mi * 16 + g + h * 8;
                int p  = m0 + pl;
                if (p < HW) {
                    float pmx = pmv[pl];
                    size_t rowoff = ((size_t)b * HW + p) * WID;
                    #pragma unroll
                    for (int nf = 0; nf < 8; nf++) {
                        int ocl = wn * 64 + nf * 8 + tg * 2;
                        float v0 = fmaxf(cacc[mi][nf][h*2+0] + bb[ocl],   0.f) * cmb[ocl]   * pmx;
                        float v1 = fmaxf(cacc[mi][nf][h*2+1] + bb[ocl+1], 0.f) * cmb[ocl+1] * pmx;
                        __nv_bfloat16 h0 = __float2bfloat16(v0);
                        __nv_bfloat16 h1 = __float2bfloat16(v1);
                        __nv_bfloat162 hp; hp.x = h0; hp.y = h1;
                        *(__nv_bfloat162*)(ohg + rowoff + ocl) = hp;
                        __nv_bfloat162 lp;
                        lp.x = __float2bfloat16(v0 - __bfloat162float(h0));
                        lp.y = __float2bfloat16(v1 - __bfloat162float(h1));
                        *(__nv_bfloat162*)(olg + rowoff + ocl) = lp;
                    }
                }
            }
        }
    } else {
        float* tf = (float*)dsm;          // reuse: [128 oc][132 p]
        __syncthreads();
        #pragma unroll
        for (int mi = 0; mi < 2; mi++)
            #pragma unroll
            for (int h = 0; h < 2; h++) {
                int pl = wm * 32 + mi * 16 + g + h * 8;
                float pmx = pmv[pl];
                #pragma unroll
                for (int nf = 0; nf < 8; nf++) {
                    int ocl = wn * 64 + nf * 8 + tg * 2;
                    tf[ocl * 132 + pl]       = (cacc[mi][nf][h*2+0] + bb[ocl])   * cmb[ocl]   * pmx;
                    tf[(ocl + 1) * 132 + pl] = (cacc[mi][nf][h*2+1] + bb[ocl+1]) * cmb[ocl+1] * pmx;
                }
            }
        __syncthreads();
        int ocl = tid >> 1, half = tid & 1;
        if (m0 + half * 64 < HW) {
            float* orow = xout + ((size_t)b * OUP + n0g + ocl) * HW + m0 + half * 64;
            const float* src = tf + ocl * 132 + half * 64;
            #pragma unroll
            for (int gi = 0; gi < 16; gi++)
                *(float4*)(orow + gi * 4) = *(const float4*)(src + gi * 4);
        }
    }
}

// ---------------------------------------------------------------------------
// row/col means of h3 (in d_out) -> s_xh, s_xw
// ---------------------------------------------------------------------------
__global__ void kH_rowcol(const float* __restrict__ h3)
{
    int bc = blockIdx.x;
    const float* img = h3 + (size_t)bc * HW;
    int t = threadIdx.x;
    if (t < WW) {
        float s = 0.f;
        for (int h = 0; h < HH; h++) s += img[h * WW + t];
        s_xw[bc * WW + t] = s * (1.f / HH);
        float r = 0.f;
        for (int w = 0; w < WW; w++) r += img[t * WW + w];
        s_xh[bc * HH + t] = r * (1.f / WW);
    }
}

// ---------------------------------------------------------------------------
// coordinate attention -> s_ah, s_aw
// ---------------------------------------------------------------------------
__global__ void kI_coord(const float* __restrict__ w1, const float* __restrict__ b1,
                         const float* __restrict__ wh, const float* __restrict__ bh,
                         const float* __restrict__ ww, const float* __restrict__ bw)
{
    int b = blockIdx.x;
    int t = threadIdx.x;                        // 128 threads
    __shared__ float w1s[MIP * OUP];
    __shared__ float ys[2 * HH][MIP];
    for (int i = t; i < MIP * OUP; i += 128) w1s[i] = w1[i];
    __syncthreads();

    if (t < 2 * HH) {
        float acc[MIP];
        #pragma unroll
        for (int m = 0; m < MIP; m++) acc[m] = b1[m];
        const float* src = (t < HH)
            ? (s_xh + (size_t)b * OUP * HH + t)
            : (s_xw + (size_t)b * OUP * WW + (t - HH));
        for (int c = 0; c < OUP; c++) {
            float v = src[(size_t)c * HH];
            #pragma unroll
            for (int m = 0; m < MIP; m++) acc[m] += v * w1s[m * OUP + c];
        }
        #pragma unroll
        for (int m = 0; m < MIP; m++) {
            float u = acc[m];
            float r6 = fminf(fmaxf(u + 3.f, 0.f), 6.f);
            ys[t][m] = u * r6 * (1.f / 6.f);
        }
    }
    __syncthreads();

    for (int c = t; c < OUP; c += 128) {
        float whr[MIP], wwr[MIP];
        #pragma unroll
        for (int m = 0; m < MIP; m++) { whr[m] = wh[c*MIP + m]; wwr[m] = ww[c*MIP + m]; }
        float bhc = bh[c], bwc = bw[c];
        for (int j = 0; j < HH; j++) {
            float sh = bhc, sw = bwc;
            #pragma unroll
            for (int m = 0; m < MIP; m++) {
                sh += ys[j][m]      * whr[m];
                sw += ys[HH + j][m] * wwr[m];
            }
            s_ah[((size_t)b * OUP + c) * HH + j] = 1.f / (1.f + expf(-sh));
            s_aw[((size_t)b * OUP + c) * WW + j] = 1.f / (1.f + expf(-sw));
        }
    }
}

// ---------------------------------------------------------------------------
// final: out = relu(h3 * ah * aw + x), in place on d_out
// ---------------------------------------------------------------------------
__global__ void kJ_final(const float* __restrict__ x, float* __restrict__ out)
{
    size_t i = (size_t)blockIdx.x * blockDim.x + threadIdx.x;
    const size_t total4 = (size_t)NB * OUP * HW / 4;
    if (i >= total4) return;
    size_t e   = i * 4;
    size_t row = e / WW;
    int    w   = (int)(e - row * WW);
    size_t bc  = row / HH;
    float a_h  = s_ah[row];
    const float* awp = s_aw + bc * WW + w;
    float4 hv = *(float4*)(out + e);
    float4 xv = *(const float4*)(x + e);
    float4 r;
    r.x = fmaxf(hv.x * a_h * awp[0] + xv.x, 0.f);
    r.y = fmaxf(hv.y * a_h * awp[1] + xv.y, 0.f);
    r.z = fmaxf(hv.z * a_h * awp[2] + xv.z, 0.f);
    r.w = fmaxf(hv.w * a_h * awp[3] + xv.w, 0.f);
    *(float4*)(out + e) = r;
}

// ---------------------------------------------------------------------------
// Launch — only harness pointers cross the host/device boundary.
// ---------------------------------------------------------------------------
extern "C" void kernel_launch(void* const* d_in, const int* in_sizes, int n_in,
                              void* d_out, int out_size)
{
    const float* x     = (const float*)d_in[0];
    const float* sm_w  = (const float*)d_in[1];
    const float* sm_b  = (const float*)d_in[2];
    const float* cm1_w = (const float*)d_in[3];
    const float* cm1_b = (const float*)d_in[4];
    const float* cm2_w = (const float*)d_in[5];
    const float* cm2_b = (const float*)d_in[6];
    const float* cm3_w = (const float*)d_in[7];
    const float* cm3_b = (const float*)d_in[8];
    const float* w1    = (const float*)d_in[9];
    const float* b1    = (const float*)d_in[10];
    const float* w2    = (const float*)d_in[11];
    const float* b2    = (const float*)d_in[12];
    const float* w3    = (const float*)d_in[13];
    const float* b3    = (const float*)d_in[14];
    const float* ca_w1 = (const float*)d_in[15];
    const float* ca_b1 = (const float*)d_in[16];
    const float* ca_wh = (const float*)d_in[17];
    const float* ca_bh = (const float*)d_in[18];
    const float* ca_ww = (const float*)d_in[19];
    const float* ca_bw = (const float*)d_in[20];
    float* out = (float*)d_out;

    cudaFuncSetAttribute(conv_mma<1, WID, CIN,   CIN>, cudaFuncAttributeMaxDynamicSharedMemorySize, CONV_DSM);
    cudaFuncSetAttribute(conv_mma<2, WID, 1152,  WID>, cudaFuncAttributeMaxDynamicSharedMemorySize, CONV_DSM);
    cudaFuncSetAttribute(conv_mma<3, OUP, WID,   WID>, cudaFuncAttributeMaxDynamicSharedMemorySize, CONV_DSM);

    kT_transx<<<dim3(HW/64, CIN/64, NB), 256>>>(x);
    kW_split<1><<<(WID*CIN  + 255)/256, 256>>>(w1);
    kW_split<2><<<(WID*1152 + 255)/256, 256>>>(w2);
    kW_split<3><<<(OUP*WID  + 255)/256, 256>>>(w3);

    kS_smask<<<dim3(HW/8, NB), 256>>>(sm_w, sm_b);
    kB_dilate<<<NB, 256>>>();
    kM_partial<0><<<dim3(8, NB), CIN>>>();
    kD_cmask<1><<<NB, 256>>>(cm1_w, cm1_b);

    conv_mma<1, WID, CIN, CIN><<<dim3(25, 1, NB), 256, CONV_DSM>>>(b1, out);

    kM_partial<1><<<dim3(8, NB), WID>>>();
    kD_cmask<2><<<NB, 256>>>(cm2_w, cm2_b);

    conv_mma<2, WID, 1152, WID><<<dim3(25, 1, NB), 256, CONV_DSM>>>(b2, out);

    kM_partial<2><<<dim3(8, NB), WID>>>();
    kD_cmask<3><<<NB, 256>>>(cm3_w, cm3_b);

    conv_mma<3, OUP, WID, WID><<<dim3(25, 4, NB), 256, CONV_DSM>>>(b3, out);

    kH_rowcol<<<NB * OUP, 64>>>(out);
    kI_coord<<<NB, 128>>>(ca_w1, ca_b1, ca_wh, ca_bh, ca_ww, ca_bw);

    {
        size_t total4 = (size_t)NB * OUP * HW / 4;
        kJ_final<<<(unsigned)((total4 + 255) / 256), 256>>>(x, out);
    }
}

// round 8
// speedup vs baseline: 4.8505x; 1.0246x over previous
#include <cuda_runtime.h>
#include <cuda_bf16.h>
#include <math.h>
#include <stdint.h>

// ---------------------------------------------------------------------------
// Problem constants
// ---------------------------------------------------------------------------
#define NB   16
#define CIN  512
#define WID  128
#define OUP  512
#define HH   56
#define WW   56
#define HW   (HH*WW)     // 3136
#define MIP  16

union U8 { __nv_bfloat16 h[8]; uint4 u; };

__device__ __forceinline__ uint32_t smem_u32(const void* p) {
    uint32_t a;
    asm("{ .reg .u64 t; cvta.to.shared.u64 t, %1; cvt.u32.u64 %0, t; }" : "=r"(a) : "l"(p));
    return a;
}
__device__ __forceinline__ void ldsm4(uint32_t* r, uint32_t a) {
    asm volatile("ldmatrix.sync.aligned.m8n8.x4.shared.b16 {%0,%1,%2,%3}, [%4];"
                 : "=r"(r[0]), "=r"(r[1]), "=r"(r[2]), "=r"(r[3]) : "r"(a));
}
__device__ __forceinline__ void mma_bf(float* c, const uint32_t* a, uint32_t b0, uint32_t b1) {
    asm volatile("mma.sync.aligned.m16n8k16.row.col.f32.bf16.bf16.f32 "
                 "{%0,%1,%2,%3}, {%4,%5,%6,%7}, {%8,%9}, {%0,%1,%2,%3};"
                 : "+f"(c[0]), "+f"(c[1]), "+f"(c[2]), "+f"(c[3])
                 : "r"(a[0]), "r"(a[1]), "r"(a[2]), "r"(a[3]), "r"(b0), "r"(b1));
}
__device__ __forceinline__ void cpa16(uint32_t d, const void* s, uint32_t srcsz) {
    asm volatile("cp.async.cg.shared.global [%0], [%1], 16, %2;"
                 :: "r"(d), "l"(s), "r"(srcsz) : "memory");
}
__device__ __forceinline__ void cpa_commit() { asm volatile("cp.async.commit_group;" ::: "memory"); }
template<int N> __device__ __forceinline__ void cpa_wait() {
    asm volatile("cp.async.wait_group %0;" :: "n"(N) : "memory");
}

// ---------------------------------------------------------------------------
// Scratch — __device__ globals, referenced ONLY inside device code.
// ---------------------------------------------------------------------------
__device__ __align__(128) __nv_bfloat16 gx_hi [NB*HW*CIN];
__device__ __align__(128) __nv_bfloat16 gx_lo [NB*HW*CIN];
__device__ __align__(128) __nv_bfloat16 gh1_hi[NB*HW*WID];
__device__ __align__(128) __nv_bfloat16 gh1_lo[NB*HW*WID];
__device__ __align__(128) __nv_bfloat16 gh2_hi[NB*HW*WID];
__device__ __align__(128) __nv_bfloat16 gh2_lo[NB*HW*WID];
__device__ __align__(128) __nv_bfloat16 gw1h[WID*CIN],  gw1l[WID*CIN];
__device__ __align__(128) __nv_bfloat16 gw2h[WID*1152], gw2l[WID*1152];
__device__ __align__(128) __nv_bfloat16 gw3h[OUP*WID],  gw3l[OUP*WID];
__device__ __align__(16) float g_smlog[NB*HW];   // spatial-mask logit accumulators
__device__ __align__(16) float g_poolx[NB*CIN];  // channel-sum accumulators (x)
__device__ __align__(16) float g_pool1[NB*WID];  // (h1)
__device__ __align__(16) float g_pool2[NB*WID];  // (h2)
__device__ __align__(16) float s_sm [NB*HW];
__device__ __align__(16) float s_smd[NB*HW];
__device__ __align__(16) float s_c1 [NB*WID];
__device__ __align__(16) float s_c2 [NB*WID];
__device__ __align__(16) float s_c3 [NB*OUP];
__device__ __align__(16) float s_xh [NB*OUP*HH];
__device__ __align__(16) float s_xw [NB*OUP*WW];
__device__ __align__(16) float s_ah [NB*OUP*HH];
__device__ __align__(16) float s_aw [NB*OUP*WW];

// ---------------------------------------------------------------------------
// kZ: zero the atomic accumulators
// ---------------------------------------------------------------------------
__global__ void kZ_zero()
{
    int i = blockIdx.x * 256 + threadIdx.x;
    if (i < NB*HW)  g_smlog[i] = 0.f;
    if (i < NB*CIN) g_poolx[i] = 0.f;
    if (i < NB*WID) { g_pool1[i] = 0.f; g_pool2[i] = 0.f; }
}

// ---------------------------------------------------------------------------
// kT: transpose + bf16-split x [b,c,p] -> gx_hi/lo [b,p,c]
//     + fused partials: spatial-mask logit (per pixel), channel sums (per c)
// ---------------------------------------------------------------------------
__global__ __launch_bounds__(256) void kT_transx(const float* __restrict__ x,
                                                 const float* __restrict__ smw)
{
    __shared__ float ts[64][65];
    __shared__ float wsh[64];
    __shared__ float red[4][64];
    const int b  = blockIdx.z;
    const int c0 = blockIdx.y * 64;
    const int p0 = blockIdx.x * 64;
    const int t  = threadIdx.x;

    if (t < 64) wsh[t] = smw[c0 + t];
    {
        int ci = t >> 2, jg = (t & 3) * 16;
        const float* src = x + ((size_t)b * CIN + c0 + ci) * HW + p0 + jg;
        #pragma unroll
        for (int q = 0; q < 4; q++) {
            float4 f = *(const float4*)(src + q * 4);
            ts[ci][jg + q*4 + 0] = f.x; ts[ci][jg + q*4 + 1] = f.y;
            ts[ci][jg + q*4 + 2] = f.z; ts[ci][jg + q*4 + 3] = f.w;
        }
    }
    __syncthreads();

    // fused: spatial-mask logit partial (this block's 64 channels)
    {
        int g = t >> 6, pi = t & 63;
        float s = 0.f;
        #pragma unroll
        for (int cc = 0; cc < 16; cc++) s += ts[g*16 + cc][pi] * wsh[g*16 + cc];
        red[g][pi] = s;
    }
    __syncthreads();
    if (t < 64)
        atomicAdd(&g_smlog[b * HW + p0 + t], red[0][t] + red[1][t] + red[2][t] + red[3][t]);
    __syncthreads();

    // fused: channel-sum partial (this block's 64 pixels)
    {
        int c = t & 63, pg = t >> 6;
        float s = 0.f;
        #pragma unroll
        for (int i = 0; i < 16; i++) s += ts[c][pg*16 + i];
        red[pg][c] = s;
    }
    __syncthreads();
    if (t < 64)
        atomicAdd(&g_poolx[b * CIN + c0 + t], red[0][t] + red[1][t] + red[2][t] + red[3][t]);

    // split-transposed store
    {
        int pi = t >> 2, cg = (t & 3) * 16;
        __nv_bfloat16* oh = gx_hi + ((size_t)b * HW + p0 + pi) * CIN + c0 + cg;
        __nv_bfloat16* ol = gx_lo + ((size_t)b * HW + p0 + pi) * CIN + c0 + cg;
        #pragma unroll
        for (int g = 0; g < 2; g++) {
            U8 hh, ll;
            #pragma unroll
            for (int j = 0; j < 8; j++) {
                float v = ts[cg + g*8 + j][pi];
                __nv_bfloat16 h = __float2bfloat16(v);
                hh.h[j] = h;
                ll.h[j] = __float2bfloat16(v - __bfloat162float(h));
            }
            *(uint4*)(oh + g*8) = hh.u;
            *(uint4*)(ol + g*8) = ll.u;
        }
    }
}

// ---------------------------------------------------------------------------
// kW: weight fp32 -> split bf16 (+ conv2 reorder k = r*128+c from [o][c*9+r])
// ---------------------------------------------------------------------------
template<int MODE>
__global__ void kW_split(const float* __restrict__ W)
{
    constexpr int M = (MODE == 3) ? OUP : WID;
    constexpr int K = (MODE == 1) ? CIN : ((MODE == 2) ? 1152 : WID);
    __nv_bfloat16* oh = (MODE == 1) ? gw1h : (MODE == 2 ? gw2h : gw3h);
    __nv_bfloat16* ol = (MODE == 1) ? gw1l : (MODE == 2 ? gw2l : gw3l);
    int i = blockIdx.x * 256 + threadIdx.x;
    if (i >= M * K) return;
    int o = i / K, k = i - o * K;
    float v;
    if (MODE == 2) {
        int r = k >> 7, c = k & 127;
        v = W[(size_t)o * 1152 + c * 9 + r];
    } else v = W[i];
    __nv_bfloat16 h = __float2bfloat16(v);
    oh[i] = h;
    ol[i] = __float2bfloat16(v - __bfloat162float(h));
}

// ---------------------------------------------------------------------------
// kB: threshold smask logits + 3x3 max dilation
// ---------------------------------------------------------------------------
__global__ void kB_dilate(const float* __restrict__ smb)
{
    __shared__ float s[HW];
    int b = blockIdx.x;
    float sb0 = smb[0];
    for (int i = threadIdx.x; i < HW; i += blockDim.x) {
        float m = (g_smlog[b*HW + i] + sb0) > 0.f ? 1.f : 0.f;
        s[i] = m;
        s_sm[b*HW + i] = m;
    }
    __syncthreads();
    for (int i = threadIdx.x; i < HW; i += blockDim.x) {
        int h = i / WW, w = i % WW;
        float m = 0.f;
        for (int dy = -1; dy <= 1; dy++) {
            int y = h + dy; if (y < 0 || y >= HH) continue;
            for (int dx = -1; dx <= 1; dx++) {
                int xx = w + dx; if (xx < 0 || xx >= WW) continue;
                m = fmaxf(m, s[y*WW + xx]);
            }
        }
        s_smd[b*HW + i] = m;
    }
}

// ---------------------------------------------------------------------------
// kD: channel mask from accumulated channel sums (scale 1/HW -> mean).
// ---------------------------------------------------------------------------
template<int STAGE>
__global__ void kD_cmask(const float* __restrict__ w,
                         const float* __restrict__ bias)
{
    constexpr int CI = (STAGE == 1) ? CIN : WID;
    constexpr int CO = (STAGE == 3) ? OUP : WID;
    const float* psum = (STAGE == 1) ? g_poolx : (STAGE == 2 ? g_pool1 : g_pool2);
    float*       mask = (STAGE == 1) ? s_c1 : (STAGE == 2 ? s_c2 : s_c3);
    int b = blockIdx.x;
    __shared__ float pr[CI];
    for (int i = threadIdx.x; i < CI; i += blockDim.x)
        pr[i] = psum[b*CI + i] * (1.f / HW);
    __syncthreads();
    int wrp = threadIdx.x >> 5, lane = threadIdx.x & 31;
    for (int o = wrp; o < CO; o += 8) {
        const float* wr = w + (size_t)o * CI;
        float s = 0.f;
        #pragma unroll 4
        for (int c = lane; c < CI; c += 32) s += pr[c] * wr[c];
        #pragma unroll
        for (int off = 16; off > 0; off >>= 1) s += __shfl_xor_sync(0xffffffffu, s, off);
        if (lane == 0) mask[b*CO + o] = (s + bias[o]) > 0.f ? 1.f : 0.f;
    }
}

// ---------------------------------------------------------------------------
// conv_mma: mma.sync bf16-split GEMM, cp.async double-buffered.
// Block: 128 pixels x 128 oc, 8 warps (4m x 2n), K chunk 64, 2 smem stages.
// MODE 1: conv1 K=512  act=gx  -> gh1 split (relu*cm1*smd) + pool1 partials
// MODE 2: conv2 K=1152 act=gh1 -> gh2 split (relu*cm2*sm)  + pool2 partials
// MODE 3: conv3 K=128  act=gh2 -> d_out fp32 [oc][p] (*cm3*sm)
// ---------------------------------------------------------------------------
#define A_HI 0
#define A_LO 18432
#define B_HI 36864
#define B_LO 55296
#define STG  73728
#define CONV_DSM (2*STG)

template<int MODE, int NOC, int K, int CI>
__global__ __launch_bounds__(256)
void conv_mma(const float* __restrict__ bias, float* __restrict__ xout)
{
    extern __shared__ char dsm[];
    const uint32_t sb = smem_u32(dsm);
    __shared__ float pmv[128], cmb[128], bb[128];
    __shared__ float pool[128];

    const int tid  = threadIdx.x;
    const int wid  = tid >> 5;
    const int lane = tid & 31;
    const int b    = blockIdx.z;
    const int m0   = blockIdx.x * 128;       // pixel base
    const int n0g  = blockIdx.y * 128;       // out-channel base

    const __nv_bfloat16* act_h = (MODE == 1) ? gx_hi : (MODE == 2 ? gh1_hi : gh2_hi);
    const __nv_bfloat16* act_l = (MODE == 1) ? gx_lo : (MODE == 2 ? gh1_lo : gh2_lo);
    const __nv_bfloat16* wt_h  = (MODE == 1) ? gw1h : (MODE == 2 ? gw2h : gw3h);
    const __nv_bfloat16* wt_l  = (MODE == 1) ? gw1l : (MODE == 2 ? gw2l : gw3l);
    const float* cm = (MODE == 1) ? s_c1 : (MODE == 2 ? s_c2 : s_c3);
    const float* pm = (MODE == 1) ? s_smd : s_sm;

    if (tid < 128) {
        int p = m0 + tid;
        pmv[tid] = (p < HW) ? pm[b * HW + p] : 0.f;
        cmb[tid] = cm[b * NOC + n0g + tid];
        bb[tid]  = bias[n0g + tid];
        pool[tid] = 0.f;
    }

    const int prow = tid >> 1, ug = (tid & 1) * 4;

    auto prefetch = [&](int ch, int st) {
        const uint32_t sbase = sb + st * STG;
        const int k0 = ch * 64;
        // A (activations)
        {
            int p = m0 + prow;
            bool valid; int q, c0;
            if (MODE == 2) {
                int r  = ch >> 1;
                int ky = r / 3 - 1, kx = r % 3 - 1;
                int py = p / WW, px = p - py * WW;
                int iy = py + ky, ix = px + kx;
                valid = (p < HW) && iy >= 0 && iy < HH && ix >= 0 && ix < WW;
                q = iy * WW + ix;
                c0 = (ch & 1) * 64;
            } else { valid = (p < HW); q = p; c0 = k0; }
            uint32_t sz = valid ? 16u : 0u;
            const __nv_bfloat16* ah = act_h + ((size_t)b * HW + (valid ? q : 0)) * CI + c0 + ug * 8;
            const __nv_bfloat16* al = act_l + ((size_t)b * HW + (valid ? q : 0)) * CI + c0 + ug * 8;
            uint32_t dh = sbase + A_HI + prow * 144 + ug * 16;
            uint32_t dl = sbase + A_LO + prow * 144 + ug * 16;
            #pragma unroll
            for (int u = 0; u < 4; u++) {
                cpa16(dh + u * 16, ah + u * 8, sz);
                cpa16(dl + u * 16, al + u * 8, sz);
            }
        }
        // B (weights)
        {
            const __nv_bfloat16* wh = wt_h + (size_t)(n0g + prow) * K + k0 + ug * 8;
            const __nv_bfloat16* wl = wt_l + (size_t)(n0g + prow) * K + k0 + ug * 8;
            uint32_t dh = sbase + B_HI + prow * 144 + ug * 16;
            uint32_t dl = sbase + B_LO + prow * 144 + ug * 16;
            #pragma unroll
            for (int u = 0; u < 4; u++) {
                cpa16(dh + u * 16, wh + u * 8, 16u);
                cpa16(dl + u * 16, wl + u * 8, 16u);
            }
        }
        cpa_commit();
    };

    float cacc[2][8][4];
    #pragma unroll
    for (int i = 0; i < 2; i++)
        #pragma unroll
        for (int j = 0; j < 8; j++)
            #pragma unroll
            for (int q = 0; q < 4; q++) cacc[i][j][q] = 0.f;

    const int wm = wid >> 1, wn = wid & 1;
    const int lr = lane & 7, s23 = lane >> 3;
    const int arow = (s23 & 1) * 8 + lr, acol = (s23 >> 1) * 8;
    const int brow = (s23 >> 1) * 8 + lr, bcol = (s23 & 1) * 8;

    constexpr int NC = K / 64;
    prefetch(0, 0);
    int buf = 0;
    for (int ch = 0; ch < NC; ch++) {
        if (ch + 1 < NC) { prefetch(ch + 1, buf ^ 1); cpa_wait<1>(); }
        else             { cpa_wait<0>(); }
        __syncthreads();

        const uint32_t sbb = sb + buf * STG;
        #pragma unroll
        for (int s = 0; s < 4; s++) {
            const int kb = s * 16;
            uint32_t ah[2][4], al[2][4];
            #pragma unroll
            for (int mi = 0; mi < 2; mi++) {
                uint32_t off = (uint32_t)((wm * 32 + mi * 16 + arow) * 144 + (kb + acol) * 2);
                ldsm4(ah[mi], sbb + A_HI + off);
                ldsm4(al[mi], sbb + A_LO + off);
            }
            #pragma unroll
            for (int np = 0; np < 4; np++) {
                uint32_t bh[4], bl[4];
                uint32_t off = (uint32_t)((wn * 64 + np * 16 + brow) * 144 + (kb + bcol) * 2);
                ldsm4(bh, sbb + B_HI + off);
                ldsm4(bl, sbb + B_LO + off);
                #pragma unroll
                for (int mi = 0; mi < 2; mi++) {
                    float* c0p = cacc[mi][np * 2];
                    float* c1p = cacc[mi][np * 2 + 1];
                    mma_bf(c0p, ah[mi], bh[0], bh[1]);
                    mma_bf(c0p, al[mi], bh[0], bh[1]);
                    mma_bf(c0p, ah[mi], bl[0], bl[1]);
                    mma_bf(c1p, ah[mi], bh[2], bh[3]);
                    mma_bf(c1p, al[mi], bh[2], bh[3]);
                    mma_bf(c1p, ah[mi], bl[2], bl[3]);
                }
            }
        }
        __syncthreads();
        buf ^= 1;
    }

    // ---- epilogue ----
    const int g = lane >> 2, tg = lane & 3;
    if (MODE != 3) {
        __nv_bfloat16* ohg = (MODE == 1 ? gh1_hi : gh2_hi);
        __nv_bfloat16* olg = (MODE == 1 ? gh1_lo : gh2_lo);
        float lsum[16];
        #pragma unroll
        for (int i = 0; i < 16; i++) lsum[i] = 0.f;
        #pragma unroll
        for (int mi = 0; mi < 2; mi++) {
            #pragma unroll
            for (int h = 0; h < 2; h++) {
                int pl = wm * 32 + mi * 16 + g + h * 8;
                int p  = m0 + pl;
                if (p < HW) {
                    float pmx = pmv[pl];
                    size_t rowoff = ((size_t)b * HW + p) * WID;
                    #pragma unroll
                    for (int nf = 0; nf < 8; nf++) {
                        int ocl = wn * 64 + nf * 8 + tg * 2;
                        float v0 = fmaxf(cacc[mi][nf][h*2+0] + bb[ocl],   0.f) * cmb[ocl]   * pmx;
                        float v1 = fmaxf(cacc[mi][nf][h*2+1] + bb[ocl+1], 0.f) * cmb[ocl+1] * pmx;
                        lsum[nf*2 + 0] += v0;
                        lsum[nf*2 + 1] += v1;
                        __nv_bfloat16 h0 = __float2bfloat16(v0);
                        __nv_bfloat16 h1 = __float2bfloat16(v1);
                        __nv_bfloat162 hp; hp.x = h0; hp.y = h1;
                        *(__nv_bfloat162*)(ohg + rowoff + ocl) = hp;
                        __nv_bfloat162 lp;
                        lp.x = __float2bfloat16(v0 - __bfloat162float(h0));
                        lp.y = __float2bfloat16(v1 - __bfloat162float(h1));
                        *(__nv_bfloat162*)(olg + rowoff + ocl) = lp;
                    }
                }
            }
        }
        // pooled-sum partials for the next channel mask
        #pragma unroll
        for (int nf = 0; nf < 8; nf++) {
            int ocl = wn * 64 + nf * 8 + tg * 2;
            atomicAdd(&pool[ocl],     lsum[nf*2 + 0]);
            atomicAdd(&pool[ocl + 1], lsum[nf*2 + 1]);
        }
        __syncthreads();
        float* gpool = (MODE == 1) ? g_pool1 : g_pool2;
        if (tid < 128) atomicAdd(&gpool[b * WID + tid], pool[tid]);
    } else {
        float* tf = (float*)dsm;          // reuse: [128 oc][132 p]
        __syncthreads();
        #pragma unroll
        for (int mi = 0; mi < 2; mi++)
            #pragma unroll
            for (int h = 0; h < 2; h++) {
                int pl = wm * 32 + mi * 16 + g + h * 8;
                float pmx = pmv[pl];
                #pragma unroll
                for (int nf = 0; nf < 8; nf++) {
                    int ocl = wn * 64 + nf * 8 + tg * 2;
                    tf[ocl * 132 + pl]       = (cacc[mi][nf][h*2+0] + bb[ocl])   * cmb[ocl]   * pmx;
                    tf[(ocl + 1) * 132 + pl] = (cacc[mi][nf][h*2+1] + bb[ocl+1]) * cmb[ocl+1] * pmx;
                }
            }
        __syncthreads();
        int ocl = tid >> 1, half = tid & 1;
        if (m0 + half * 64 < HW) {
            float* orow = xout + ((size_t)b * OUP + n0g + ocl) * HW + m0 + half * 64;
            const float* src = tf + ocl * 132 + half * 64;
            #pragma unroll
            for (int gi = 0; gi < 16; gi++)
                *(float4*)(orow + gi * 4) = *(const float4*)(src + gi * 4);
        }
    }
}

// ---------------------------------------------------------------------------
// row/col means of h3 (in d_out) -> s_xh, s_xw
// ---------------------------------------------------------------------------
__global__ void kH_rowcol(const float* __restrict__ h3)
{
    int bc = blockIdx.x;
    const float* img = h3 + (size_t)bc * HW;
    int t = threadIdx.x;
    if (t < WW) {
        float s = 0.f;
        for (int h = 0; h < HH; h++) s += img[h * WW + t];
        s_xw[bc * WW + t] = s * (1.f / HH);
        float r = 0.f;
        for (int w = 0; w < WW; w++) r += img[t * WW + w];
        s_xh[bc * HH + t] = r * (1.f / WW);
    }
}

// ---------------------------------------------------------------------------
// coordinate attention -> s_ah, s_aw
// ---------------------------------------------------------------------------
__global__ void kI_coord(const float* __restrict__ w1, const float* __restrict__ b1,
                         const float* __restrict__ wh, const float* __restrict__ bh,
                         const float* __restrict__ ww, const float* __restrict__ bw)
{
    int b = blockIdx.x;
    int t = threadIdx.x;                        // 128 threads
    __shared__ float w1s[MIP * OUP];
    __shared__ float ys[2 * HH][MIP];
    for (int i = t; i < MIP * OUP; i += 128) w1s[i] = w1[i];
    __syncthreads();

    if (t < 2 * HH) {
        float acc[MIP];
        #pragma unroll
        for (int m = 0; m < MIP; m++) acc[m] = b1[m];
        const float* src = (t < HH)
            ? (s_xh + (size_t)b * OUP * HH + t)
            : (s_xw + (size_t)b * OUP * WW + (t - HH));
        for (int c = 0; c < OUP; c++) {
            float v = src[(size_t)c * HH];
            #pragma unroll
            for (int m = 0; m < MIP; m++) acc[m] += v * w1s[m * OUP + c];
        }
        #pragma unroll
        for (int m = 0; m < MIP; m++) {
            float u = acc[m];
            float r6 = fminf(fmaxf(u + 3.f, 0.f), 6.f);
            ys[t][m] = u * r6 * (1.f / 6.f);
        }
    }
    __syncthreads();

    for (int c = t; c < OUP; c += 128) {
        float whr[MIP], wwr[MIP];
        #pragma unroll
        for (int m = 0; m < MIP; m++) { whr[m] = wh[c*MIP + m]; wwr[m] = ww[c*MIP + m]; }
        float bhc = bh[c], bwc = bw[c];
        for (int j = 0; j < HH; j++) {
            float sh = bhc, sw = bwc;
            #pragma unroll
            for (int m = 0; m < MIP; m++) {
                sh += ys[j][m]      * whr[m];
                sw += ys[HH + j][m] * wwr[m];
            }
            s_ah[((size_t)b * OUP + c) * HH + j] = 1.f / (1.f + expf(-sh));
            s_aw[((size_t)b * OUP + c) * WW + j] = 1.f / (1.f + expf(-sw));
        }
    }
}

// ---------------------------------------------------------------------------
// final: out = relu(h3 * ah * aw + x), in place on d_out
// ---------------------------------------------------------------------------
__global__ void kJ_final(const float* __restrict__ x, float* __restrict__ out)
{
    size_t i = (size_t)blockIdx.x * blockDim.x + threadIdx.x;
    const size_t total4 = (size_t)NB * OUP * HW / 4;
    if (i >= total4) return;
    size_t e   = i * 4;
    size_t row = e / WW;
    int    w   = (int)(e - row * WW);
    size_t bc  = row / HH;
    float a_h  = s_ah[row];
    const float* awp = s_aw + bc * WW + w;
    float4 hv = *(float4*)(out + e);
    float4 xv = *(const float4*)(x + e);
    float4 r;
    r.x = fmaxf(hv.x * a_h * awp[0] + xv.x, 0.f);
    r.y = fmaxf(hv.y * a_h * awp[1] + xv.y, 0.f);
    r.z = fmaxf(hv.z * a_h * awp[2] + xv.z, 0.f);
    r.w = fmaxf(hv.w * a_h * awp[3] + xv.w, 0.f);
    *(float4*)(out + e) = r;
}

// ---------------------------------------------------------------------------
// Launch — only harness pointers cross the host/device boundary.
// ---------------------------------------------------------------------------
extern "C" void kernel_launch(void* const* d_in, const int* in_sizes, int n_in,
                              void* d_out, int out_size)
{
    const float* x     = (const float*)d_in[0];
    const float* sm_w  = (const float*)d_in[1];
    const float* sm_b  = (const float*)d_in[2];
    const float* cm1_w = (const float*)d_in[3];
    const float* cm1_b = (const float*)d_in[4];
    const float* cm2_w = (const float*)d_in[5];
    const float* cm2_b = (const float*)d_in[6];
    const float* cm3_w = (const float*)d_in[7];
    const float* cm3_b = (const float*)d_in[8];
    const float* w1    = (const float*)d_in[9];
    const float* b1    = (const float*)d_in[10];
    const float* w2    = (const float*)d_in[11];
    const float* b2    = (const float*)d_in[12];
    const float* w3    = (const float*)d_in[13];
    const float* b3    = (const float*)d_in[14];
    const float* ca_w1 = (const float*)d_in[15];
    const float* ca_b1 = (const float*)d_in[16];
    const float* ca_wh = (const float*)d_in[17];
    const float* ca_bh = (const float*)d_in[18];
    const float* ca_ww = (const float*)d_in[19];
    const float* ca_bw = (const float*)d_in[20];
    float* out = (float*)d_out;

    cudaFuncSetAttribute(conv_mma<1, WID, CIN,  CIN>, cudaFuncAttributeMaxDynamicSharedMemorySize, CONV_DSM);
    cudaFuncSetAttribute(conv_mma<2, WID, 1152, WID>, cudaFuncAttributeMaxDynamicSharedMemorySize, CONV_DSM);
    cudaFuncSetAttribute(conv_mma<3, OUP, WID,  WID>, cudaFuncAttributeMaxDynamicSharedMemorySize, CONV_DSM);

    kZ_zero<<<(NB*HW + 255)/256, 256>>>();
    kT_transx<<<dim3(HW/64, CIN/64, NB), 256>>>(x, sm_w);
    kW_split<1><<<(WID*CIN  + 255)/256, 256>>>(w1);
    kW_split<2><<<(WID*1152 + 255)/256, 256>>>(w2);
    kW_split<3><<<(OUP*WID  + 255)/256, 256>>>(w3);

    kB_dilate<<<NB, 256>>>(sm_b);
    kD_cmask<1><<<NB, 256>>>(cm1_w, cm1_b);

    conv_mma<1, WID, CIN, CIN><<<dim3(25, 1, NB), 256, CONV_DSM>>>(b1, out);

    kD_cmask<2><<<NB, 256>>>(cm2_w, cm2_b);

    conv_mma<2, WID, 1152, WID><<<dim3(25, 1, NB), 256, CONV_DSM>>>(b2, out);

    kD_cmask<3><<<NB, 256>>>(cm3_w, cm3_b);

    conv_mma<3, OUP, WID, WID><<<dim3(25, 4, NB), 256, CONV_DSM>>>(b3, out);

    kH_rowcol<<<NB * OUP, 64>>>(out);
    kI_coord<<<NB, 128>>>(ca_w1, ca_b1, ca_wh, ca_bh, ca_ww, ca_bw);

    {
        size_t total4 = (size_t)NB * OUP * HW / 4;
        kJ_final<<<(unsigned)((total4 + 255) / 256), 256>>>(x, out);
    }
}

// round 9
// speedup vs baseline: 5.3017x; 1.0930x over previous
#include <cuda_runtime.h>
#include <cuda_bf16.h>
#include <math.h>
#include <stdint.h>

// ---------------------------------------------------------------------------
// Problem constants
// ---------------------------------------------------------------------------
#define NB   16
#define CIN  512
#define WID  128
#define OUP  512
#define HH   56
#define WW   56
#define HW   (HH*WW)     // 3136
#define MIP  16

union U8 { __nv_bfloat16 h[8]; uint4 u; };

__device__ __forceinline__ uint32_t smem_u32(const void* p) {
    uint32_t a;
    asm("{ .reg .u64 t; cvta.to.shared.u64 t, %1; cvt.u32.u64 %0, t; }" : "=r"(a) : "l"(p));
    return a;
}
__device__ __forceinline__ void ldsm4(uint32_t* r, uint32_t a) {
    asm volatile("ldmatrix.sync.aligned.m8n8.x4.shared.b16 {%0,%1,%2,%3}, [%4];"
                 : "=r"(r[0]), "=r"(r[1]), "=r"(r[2]), "=r"(r[3]) : "r"(a));
}
__device__ __forceinline__ void mma_bf(float* c, const uint32_t* a, uint32_t b0, uint32_t b1) {
    asm volatile("mma.sync.aligned.m16n8k16.row.col.f32.bf16.bf16.f32 "
                 "{%0,%1,%2,%3}, {%4,%5,%6,%7}, {%8,%9}, {%0,%1,%2,%3};"
                 : "+f"(c[0]), "+f"(c[1]), "+f"(c[2]), "+f"(c[3])
                 : "r"(a[0]), "r"(a[1]), "r"(a[2]), "r"(a[3]), "r"(b0), "r"(b1));
}
__device__ __forceinline__ void cpa16(uint32_t d, const void* s, uint32_t srcsz) {
    asm volatile("cp.async.cg.shared.global [%0], [%1], 16, %2;"
                 :: "r"(d), "l"(s), "r"(srcsz) : "memory");
}
__device__ __forceinline__ void cpa_commit() { asm volatile("cp.async.commit_group;" ::: "memory"); }
template<int N> __device__ __forceinline__ void cpa_wait() {
    asm volatile("cp.async.wait_group %0;" :: "n"(N) : "memory");
}

// ---------------------------------------------------------------------------
// Scratch — __device__ globals, referenced ONLY inside device code.
// ---------------------------------------------------------------------------
__device__ __align__(128) __nv_bfloat16 gx_hi [NB*HW*CIN];
__device__ __align__(128) __nv_bfloat16 gx_lo [NB*HW*CIN];
__device__ __align__(128) __nv_bfloat16 gh1_hi[NB*HW*WID];
__device__ __align__(128) __nv_bfloat16 gh1_lo[NB*HW*WID];
__device__ __align__(128) __nv_bfloat16 gh2_hi[NB*HW*WID];
__device__ __align__(128) __nv_bfloat16 gh2_lo[NB*HW*WID];
__device__ __align__(128) __nv_bfloat16 gw1h[WID*CIN],  gw1l[WID*CIN];
__device__ __align__(128) __nv_bfloat16 gw2h[WID*1152], gw2l[WID*1152];
__device__ __align__(128) __nv_bfloat16 gw3h[OUP*WID],  gw3l[OUP*WID];
__device__ __align__(16) float g_smlog[NB*HW];
__device__ __align__(16) float g_poolx[NB*CIN];
__device__ __align__(16) float g_pool1[NB*WID];
__device__ __align__(16) float g_pool2[NB*WID];
__device__ __align__(16) float s_sm [NB*HW];
__device__ __align__(16) float s_smd[NB*HW];
__device__ __align__(16) float s_c1 [NB*WID];
__device__ __align__(16) float s_c2 [NB*WID];
__device__ __align__(16) float s_c3 [NB*OUP];
__device__ __align__(16) float s_xh [NB*OUP*HH];
__device__ __align__(16) float s_xw [NB*OUP*WW];
__device__ __align__(16) float s_ah [NB*OUP*HH];
__device__ __align__(16) float s_aw [NB*OUP*WW];

// ---------------------------------------------------------------------------
// kZ: zero the atomic accumulators
// ---------------------------------------------------------------------------
__global__ void kZ_zero()
{
    int i = blockIdx.x * 256 + threadIdx.x;
    if (i < NB*HW)  g_smlog[i] = 0.f;
    if (i < NB*CIN) g_poolx[i] = 0.f;
    if (i < NB*WID) { g_pool1[i] = 0.f; g_pool2[i] = 0.f; }
}

// ---------------------------------------------------------------------------
// kT: transpose + bf16-split x [b,c,p] -> gx_hi/lo [b,p,c]
//     + fused partials: spatial-mask logit (per pixel), channel sums (per c)
// ---------------------------------------------------------------------------
__global__ __launch_bounds__(256) void kT_transx(const float* __restrict__ x,
                                                 const float* __restrict__ smw)
{
    __shared__ float ts[64][65];
    __shared__ float wsh[64];
    __shared__ float red[4][64];
    const int b  = blockIdx.z;
    const int c0 = blockIdx.y * 64;
    const int p0 = blockIdx.x * 64;
    const int t  = threadIdx.x;

    if (t < 64) wsh[t] = smw[c0 + t];
    {
        int ci = t >> 2, jg = (t & 3) * 16;
        const float* src = x + ((size_t)b * CIN + c0 + ci) * HW + p0 + jg;
        #pragma unroll
        for (int q = 0; q < 4; q++) {
            float4 f = *(const float4*)(src + q * 4);
            ts[ci][jg + q*4 + 0] = f.x; ts[ci][jg + q*4 + 1] = f.y;
            ts[ci][jg + q*4 + 2] = f.z; ts[ci][jg + q*4 + 3] = f.w;
        }
    }
    __syncthreads();

    {
        int g = t >> 6, pi = t & 63;
        float s = 0.f;
        #pragma unroll
        for (int cc = 0; cc < 16; cc++) s += ts[g*16 + cc][pi] * wsh[g*16 + cc];
        red[g][pi] = s;
    }
    __syncthreads();
    if (t < 64)
        atomicAdd(&g_smlog[b * HW + p0 + t], red[0][t] + red[1][t] + red[2][t] + red[3][t]);
    __syncthreads();

    {
        int c = t & 63, pg = t >> 6;
        float s = 0.f;
        #pragma unroll
        for (int i = 0; i < 16; i++) s += ts[c][pg*16 + i];
        red[pg][c] = s;
    }
    __syncthreads();
    if (t < 64)
        atomicAdd(&g_poolx[b * CIN + c0 + t], red[0][t] + red[1][t] + red[2][t] + red[3][t]);

    {
        int pi = t >> 2, cg = (t & 3) * 16;
        __nv_bfloat16* oh = gx_hi + ((size_t)b * HW + p0 + pi) * CIN + c0 + cg;
        __nv_bfloat16* ol = gx_lo + ((size_t)b * HW + p0 + pi) * CIN + c0 + cg;
        #pragma unroll
        for (int g = 0; g < 2; g++) {
            U8 hh, ll;
            #pragma unroll
            for (int j = 0; j < 8; j++) {
                float v = ts[cg + g*8 + j][pi];
                __nv_bfloat16 h = __float2bfloat16(v);
                hh.h[j] = h;
                ll.h[j] = __float2bfloat16(v - __bfloat162float(h));
            }
            *(uint4*)(oh + g*8) = hh.u;
            *(uint4*)(ol + g*8) = ll.u;
        }
    }
}

// ---------------------------------------------------------------------------
// kW: weight fp32 -> split bf16 (+ conv2 reorder k = r*128+c from [o][c*9+r])
// ---------------------------------------------------------------------------
template<int MODE>
__global__ void kW_split(const float* __restrict__ W)
{
    constexpr int M = (MODE == 3) ? OUP : WID;
    constexpr int K = (MODE == 1) ? CIN : ((MODE == 2) ? 1152 : WID);
    __nv_bfloat16* oh = (MODE == 1) ? gw1h : (MODE == 2 ? gw2h : gw3h);
    __nv_bfloat16* ol = (MODE == 1) ? gw1l : (MODE == 2 ? gw2l : gw3l);
    int i = blockIdx.x * 256 + threadIdx.x;
    if (i >= M * K) return;
    int o = i / K, k = i - o * K;
    float v;
    if (MODE == 2) {
        int r = k >> 7, c = k & 127;
        v = W[(size_t)o * 1152 + c * 9 + r];
    } else v = W[i];
    __nv_bfloat16 h = __float2bfloat16(v);
    oh[i] = h;
    ol[i] = __float2bfloat16(v - __bfloat162float(h));
}

// ---------------------------------------------------------------------------
// kB: threshold smask logits + 3x3 max dilation
// ---------------------------------------------------------------------------
__global__ void kB_dilate(const float* __restrict__ smb)
{
    __shared__ float s[HW];
    int b = blockIdx.x;
    float sb0 = smb[0];
    for (int i = threadIdx.x; i < HW; i += blockDim.x) {
        float m = (g_smlog[b*HW + i] + sb0) > 0.f ? 1.f : 0.f;
        s[i] = m;
        s_sm[b*HW + i] = m;
    }
    __syncthreads();
    for (int i = threadIdx.x; i < HW; i += blockDim.x) {
        int h = i / WW, w = i % WW;
        float m = 0.f;
        for (int dy = -1; dy <= 1; dy++) {
            int y = h + dy; if (y < 0 || y >= HH) continue;
            for (int dx = -1; dx <= 1; dx++) {
                int xx = w + dx; if (xx < 0 || xx >= WW) continue;
                m = fmaxf(m, s[y*WW + xx]);
            }
        }
        s_smd[b*HW + i] = m;
    }
}

// ---------------------------------------------------------------------------
// kD: channel mask from accumulated channel sums (scale 1/HW -> mean).
// ---------------------------------------------------------------------------
template<int STAGE>
__global__ void kD_cmask(const float* __restrict__ w,
                         const float* __restrict__ bias)
{
    constexpr int CI = (STAGE == 1) ? CIN : WID;
    constexpr int CO = (STAGE == 3) ? OUP : WID;
    const float* psum = (STAGE == 1) ? g_poolx : (STAGE == 2 ? g_pool1 : g_pool2);
    float*       mask = (STAGE == 1) ? s_c1 : (STAGE == 2 ? s_c2 : s_c3);
    int b = blockIdx.x;
    __shared__ float pr[CI];
    for (int i = threadIdx.x; i < CI; i += blockDim.x)
        pr[i] = psum[b*CI + i] * (1.f / HW);
    __syncthreads();
    int wrp = threadIdx.x >> 5, lane = threadIdx.x & 31;
    for (int o = wrp; o < CO; o += 8) {
        const float* wr = w + (size_t)o * CI;
        float s = 0.f;
        #pragma unroll 4
        for (int c = lane; c < CI; c += 32) s += pr[c] * wr[c];
        #pragma unroll
        for (int off = 16; off > 0; off >>= 1) s += __shfl_xor_sync(0xffffffffu, s, off);
        if (lane == 0) mask[b*CO + o] = (s + bias[o]) > 0.f ? 1.f : 0.f;
    }
}

// ---------------------------------------------------------------------------
// conv_mma: mma.sync bf16-split GEMM, cp.async double-buffered, K chunk 32,
// 2 stages x 40KB smem -> 2 CTAs/SM. Block: 128 pixels x 128 oc, 8 warps.
// MODE 1: conv1 K=512  act=gx  -> gh1 split (relu*cm1*smd) + pool1 partials
// MODE 2: conv2 K=1152 act=gh1 -> gh2 split (relu*cm2*sm)  + pool2 partials
// MODE 3: conv3 K=128  act=gh2 -> d_out fp32 [oc][p] (*cm3*sm)
// ---------------------------------------------------------------------------
#define A_HI 0
#define A_LO 10240
#define B_HI 20480
#define B_LO 30720
#define STG  40960
#define CONV_DSM (2*STG)

template<int MODE, int NOC, int K, int CI>
__global__ __launch_bounds__(256, 2)
void conv_mma(const float* __restrict__ bias, float* __restrict__ xout)
{
    extern __shared__ char dsm[];
    const uint32_t sb = smem_u32(dsm);
    __shared__ float pmv[128], cmb[128], bb[128];
    __shared__ float pool[128];

    const int tid  = threadIdx.x;
    const int wid  = tid >> 5;
    const int lane = tid & 31;
    const int b    = blockIdx.z;
    const int m0   = blockIdx.x * 128;       // pixel base
    const int n0g  = blockIdx.y * 128;       // out-channel base

    const __nv_bfloat16* act_h = (MODE == 1) ? gx_hi : (MODE == 2 ? gh1_hi : gh2_hi);
    const __nv_bfloat16* act_l = (MODE == 1) ? gx_lo : (MODE == 2 ? gh1_lo : gh2_lo);
    const __nv_bfloat16* wt_h  = (MODE == 1) ? gw1h : (MODE == 2 ? gw2h : gw3h);
    const __nv_bfloat16* wt_l  = (MODE == 1) ? gw1l : (MODE == 2 ? gw2l : gw3l);
    const float* cm = (MODE == 1) ? s_c1 : (MODE == 2 ? s_c2 : s_c3);
    const float* pm = (MODE == 1) ? s_smd : s_sm;

    if (tid < 128) {
        int p = m0 + tid;
        pmv[tid] = (p < HW) ? pm[b * HW + p] : 0.f;
        cmb[tid] = cm[b * NOC + n0g + tid];
        bb[tid]  = bias[n0g + tid];
        pool[tid] = 0.f;
    }

    const int prow = tid >> 1;               // 0..127 smem row
    const int u0   = (tid & 1) * 2;          // 16B units {0,1} or {2,3}

    auto prefetch = [&](int ch, int st) {
        const uint32_t sbase = sb + st * STG;
        const int k0 = ch * 32;
        // A (activations)
        {
            int p = m0 + prow;
            bool valid; int q, c0;
            if (MODE == 2) {
                int r  = ch >> 2;
                int ky = r / 3 - 1, kx = r % 3 - 1;
                int py = p / WW, px = p - py * WW;
                int iy = py + ky, ix = px + kx;
                valid = (p < HW) && iy >= 0 && iy < HH && ix >= 0 && ix < WW;
                q = iy * WW + ix;
                c0 = (ch & 3) * 32;
            } else { valid = (p < HW); q = p; c0 = k0; }
            uint32_t sz = valid ? 16u : 0u;
            const __nv_bfloat16* ah = act_h + ((size_t)b * HW + (valid ? q : 0)) * CI + c0 + u0 * 8;
            const __nv_bfloat16* al = act_l + ((size_t)b * HW + (valid ? q : 0)) * CI + c0 + u0 * 8;
            uint32_t dh = sbase + A_HI + prow * 80 + u0 * 16;
            uint32_t dl = sbase + A_LO + prow * 80 + u0 * 16;
            #pragma unroll
            for (int u = 0; u < 2; u++) {
                cpa16(dh + u * 16, ah + u * 8, sz);
                cpa16(dl + u * 16, al + u * 8, sz);
            }
        }
        // B (weights)
        {
            const __nv_bfloat16* wh = wt_h + (size_t)(n0g + prow) * K + k0 + u0 * 8;
            const __nv_bfloat16* wl = wt_l + (size_t)(n0g + prow) * K + k0 + u0 * 8;
            uint32_t dh = sbase + B_HI + prow * 80 + u0 * 16;
            uint32_t dl = sbase + B_LO + prow * 80 + u0 * 16;
            #pragma unroll
            for (int u = 0; u < 2; u++) {
                cpa16(dh + u * 16, wh + u * 8, 16u);
                cpa16(dl + u * 16, wl + u * 8, 16u);
            }
        }
        cpa_commit();
    };

    float cacc[2][8][4];
    #pragma unroll
    for (int i = 0; i < 2; i++)
        #pragma unroll
        for (int j = 0; j < 8; j++)
            #pragma unroll
            for (int q = 0; q < 4; q++) cacc[i][j][q] = 0.f;

    const int wm = wid >> 1, wn = wid & 1;
    const int lr = lane & 7, s23 = lane >> 3;
    const int arow = (s23 & 1) * 8 + lr, acol = (s23 >> 1) * 8;
    const int brow = (s23 >> 1) * 8 + lr, bcol = (s23 & 1) * 8;

    constexpr int NC = K / 32;
    prefetch(0, 0);
    int buf = 0;
    for (int ch = 0; ch < NC; ch++) {
        if (ch + 1 < NC) { prefetch(ch + 1, buf ^ 1); cpa_wait<1>(); }
        else             { cpa_wait<0>(); }
        __syncthreads();

        const uint32_t sbb = sb + buf * STG;
        #pragma unroll
        for (int s = 0; s < 2; s++) {
            const int kb = s * 16;
            uint32_t ah[2][4], al[2][4];
            #pragma unroll
            for (int mi = 0; mi < 2; mi++) {
                uint32_t off = (uint32_t)((wm * 32 + mi * 16 + arow) * 80 + (kb + acol) * 2);
                ldsm4(ah[mi], sbb + A_HI + off);
                ldsm4(al[mi], sbb + A_LO + off);
            }
            #pragma unroll
            for (int np = 0; np < 4; np++) {
                uint32_t bh[4], bl[4];
                uint32_t off = (uint32_t)((wn * 64 + np * 16 + brow) * 80 + (kb + bcol) * 2);
                ldsm4(bh, sbb + B_HI + off);
                ldsm4(bl, sbb + B_LO + off);
                #pragma unroll
                for (int mi = 0; mi < 2; mi++) {
                    float* c0p = cacc[mi][np * 2];
                    float* c1p = cacc[mi][np * 2 + 1];
                    mma_bf(c0p, ah[mi], bh[0], bh[1]);
                    mma_bf(c0p, al[mi], bh[0], bh[1]);
                    mma_bf(c0p, ah[mi], bl[0], bl[1]);
                    mma_bf(c1p, ah[mi], bh[2], bh[3]);
                    mma_bf(c1p, al[mi], bh[2], bh[3]);
                    mma_bf(c1p, ah[mi], bl[2], bl[3]);
                }
            }
        }
        __syncthreads();
        buf ^= 1;
    }

    // ---- epilogue ----
    const int g = lane >> 2, tg = lane & 3;
    if (MODE != 3) {
        __nv_bfloat16* ohg = (MODE == 1 ? gh1_hi : gh2_hi);
        __nv_bfloat16* olg = (MODE == 1 ? gh1_lo : gh2_lo);
        float lsum[16];
        #pragma unroll
        for (int i = 0; i < 16; i++) lsum[i] = 0.f;
        #pragma unroll
        for (int mi = 0; mi < 2; mi++) {
            #pragma unroll
            for (int h = 0; h < 2; h++) {
                int pl = wm * 32 + mi * 16 + g + h * 8;
                int p  = m0 + pl;
                if (p < HW) {
                    float pmx = pmv[pl];
                    size_t rowoff = ((size_t)b * HW + p) * WID;
                    #pragma unroll
                    for (int nf = 0; nf < 8; nf++) {
                        int ocl = wn * 64 + nf * 8 + tg * 2;
                        float v0 = fmaxf(cacc[mi][nf][h*2+0] + bb[ocl],   0.f) * cmb[ocl]   * pmx;
                        float v1 = fmaxf(cacc[mi][nf][h*2+1] + bb[ocl+1], 0.f) * cmb[ocl+1] * pmx;
                        lsum[nf*2 + 0] += v0;
                        lsum[nf*2 + 1] += v1;
                        __nv_bfloat16 h0 = __float2bfloat16(v0);
                        __nv_bfloat16 h1 = __float2bfloat16(v1);
                        __nv_bfloat162 hp; hp.x = h0; hp.y = h1;
                        *(__nv_bfloat162*)(ohg + rowoff + ocl) = hp;
                        __nv_bfloat162 lp;
                        lp.x = __float2bfloat16(v0 - __bfloat162float(h0));
                        lp.y = __float2bfloat16(v1 - __bfloat162float(h1));
                        *(__nv_bfloat162*)(olg + rowoff + ocl) = lp;
                    }
                }
            }
        }
        #pragma unroll
        for (int nf = 0; nf < 8; nf++) {
            int ocl = wn * 64 + nf * 8 + tg * 2;
            atomicAdd(&pool[ocl],     lsum[nf*2 + 0]);
            atomicAdd(&pool[ocl + 1], lsum[nf*2 + 1]);
        }
        __syncthreads();
        float* gpool = (MODE == 1) ? g_pool1 : g_pool2;
        if (tid < 128) atomicAdd(&gpool[b * WID + tid], pool[tid]);
    } else {
        float* tf = (float*)dsm;          // reuse: [128 oc][132 p] = 67.6KB
        __syncthreads();
        #pragma unroll
        for (int mi = 0; mi < 2; mi++)
            #pragma unroll
            for (int h = 0; h < 2; h++) {
                int pl = wm * 32 + mi * 16 + g + h * 8;
                float pmx = pmv[pl];
                #pragma unroll
                for (int nf = 0; nf < 8; nf++) {
                    int ocl = wn * 64 + nf * 8 + tg * 2;
                    tf[ocl * 132 + pl]       = (cacc[mi][nf][h*2+0] + bb[ocl])   * cmb[ocl]   * pmx;
                    tf[(ocl + 1) * 132 + pl] = (cacc[mi][nf][h*2+1] + bb[ocl+1]) * cmb[ocl+1] * pmx;
                }
            }
        __syncthreads();
        int ocl = tid >> 1, half = tid & 1;
        if (m0 + half * 64 < HW) {
            float* orow = xout + ((size_t)b * OUP + n0g + ocl) * HW + m0 + half * 64;
            const float* src = tf + ocl * 132 + half * 64;
            #pragma unroll
            for (int gi = 0; gi < 16; gi++)
                *(float4*)(orow + gi * 4) = *(const float4*)(src + gi * 4);
        }
    }
}

// ---------------------------------------------------------------------------
// kH: row/col means of h3 (in d_out) -> s_xh, s_xw (smem-staged)
// ---------------------------------------------------------------------------
__global__ __launch_bounds__(256) void kH_rowcol(const float* __restrict__ h3)
{
    __shared__ float img[HW];
    int bc = blockIdx.x;
    const float* src = h3 + (size_t)bc * HW;
    for (int i = threadIdx.x; i < HW; i += 256) img[i] = src[i];
    __syncthreads();
    int t = threadIdx.x;
    if (t < WW) {
        float s = 0.f;
        #pragma unroll 8
        for (int h = 0; h < HH; h++) s += img[h * WW + t];
        s_xw[bc * WW + t] = s * (1.f / HH);
    } else if (t >= 64 && t < 64 + HH) {
        int r = t - 64;
        float s = 0.f;
        #pragma unroll 8
        for (int w = 0; w < WW; w++) s += img[r * WW + w];
        s_xh[bc * HH + r] = s * (1.f / WW);
    }
}

// ---------------------------------------------------------------------------
// coordinate attention -> s_ah, s_aw
// ---------------------------------------------------------------------------
__global__ void kI_coord(const float* __restrict__ w1, const float* __restrict__ b1,
                         const float* __restrict__ wh, const float* __restrict__ bh,
                         const float* __restrict__ ww, const float* __restrict__ bw)
{
    int b = blockIdx.x;
    int t = threadIdx.x;                        // 128 threads
    __shared__ float w1s[MIP * OUP];
    __shared__ float ys[2 * HH][MIP];
    for (int i = t; i < MIP * OUP; i += 128) w1s[i] = w1[i];
    __syncthreads();

    if (t < 2 * HH) {
        float acc[MIP];
        #pragma unroll
        for (int m = 0; m < MIP; m++) acc[m] = b1[m];
        const float* src = (t < HH)
            ? (s_xh + (size_t)b * OUP * HH + t)
            : (s_xw + (size_t)b * OUP * WW + (t - HH));
        for (int c = 0; c < OUP; c++) {
            float v = src[(size_t)c * HH];
            #pragma unroll
            for (int m = 0; m < MIP; m++) acc[m] += v * w1s[m * OUP + c];
        }
        #pragma unroll
        for (int m = 0; m < MIP; m++) {
            float u = acc[m];
            float r6 = fminf(fmaxf(u + 3.f, 0.f), 6.f);
            ys[t][m] = u * r6 * (1.f / 6.f);
        }
    }
    __syncthreads();

    for (int c = t; c < OUP; c += 128) {
        float whr[MIP], wwr[MIP];
        #pragma unroll
        for (int m = 0; m < MIP; m++) { whr[m] = wh[c*MIP + m]; wwr[m] = ww[c*MIP + m]; }
        float bhc = bh[c], bwc = bw[c];
        for (int j = 0; j < HH; j++) {
            float sh = bhc, sw = bwc;
            #pragma unroll
            for (int m = 0; m < MIP; m++) {
                sh += ys[j][m]      * whr[m];
                sw += ys[HH + j][m] * wwr[m];
            }
            s_ah[((size_t)b * OUP + c) * HH + j] = 1.f / (1.f + expf(-sh));
            s_aw[((size_t)b * OUP + c) * WW + j] = 1.f / (1.f + expf(-sw));
        }
    }
}

// ---------------------------------------------------------------------------
// final: out = relu(h3 * ah * aw + x), in place on d_out
// ---------------------------------------------------------------------------
__global__ void kJ_final(const float* __restrict__ x, float* __restrict__ out)
{
    size_t i = (size_t)blockIdx.x * blockDim.x + threadIdx.x;
    const size_t total4 = (size_t)NB * OUP * HW / 4;
    if (i >= total4) return;
    size_t e   = i * 4;
    size_t row = e / WW;
    int    w   = (int)(e - row * WW);
    size_t bc  = row / HH;
    float a_h  = s_ah[row];
    const float* awp = s_aw + bc * WW + w;
    float4 hv = *(float4*)(out + e);
    float4 xv = *(const float4*)(x + e);
    float4 r;
    r.x = fmaxf(hv.x * a_h * awp[0] + xv.x, 0.f);
    r.y = fmaxf(hv.y * a_h * awp[1] + xv.y, 0.f);
    r.z = fmaxf(hv.z * a_h * awp[2] + xv.z, 0.f);
    r.w = fmaxf(hv.w * a_h * awp[3] + xv.w, 0.f);
    *(float4*)(out + e) = r;
}

// ---------------------------------------------------------------------------
// Launch — only harness pointers cross the host/device boundary.
// ---------------------------------------------------------------------------
extern "C" void kernel_launch(void* const* d_in, const int* in_sizes, int n_in,
                              void* d_out, int out_size)
{
    const float* x     = (const float*)d_in[0];
    const float* sm_w  = (const float*)d_in[1];
    const float* sm_b  = (const float*)d_in[2];
    const float* cm1_w = (const float*)d_in[3];
    const float* cm1_b = (const float*)d_in[4];
    const float* cm2_w = (const float*)d_in[5];
    const float* cm2_b = (const float*)d_in[6];
    const float* cm3_w = (const float*)d_in[7];
    const float* cm3_b = (const float*)d_in[8];
    const float* w1    = (const float*)d_in[9];
    const float* b1    = (const float*)d_in[10];
    const float* w2    = (const float*)d_in[11];
    const float* b2    = (const float*)d_in[12];
    const float* w3    = (const float*)d_in[13];
    const float* b3    = (const float*)d_in[14];
    const float* ca_w1 = (const float*)d_in[15];
    const float* ca_b1 = (const float*)d_in[16];
    const float* ca_wh = (const float*)d_in[17];
    const float* ca_bh = (const float*)d_in[18];
    const float* ca_ww = (const float*)d_in[19];
    const float* ca_bw = (const float*)d_in[20];
    float* out = (float*)d_out;

    cudaFuncSetAttribute(conv_mma<1, WID, CIN,  CIN>, cudaFuncAttributeMaxDynamicSharedMemorySize, CONV_DSM);
    cudaFuncSetAttribute(conv_mma<2, WID, 1152, WID>, cudaFuncAttributeMaxDynamicSharedMemorySize, CONV_DSM);
    cudaFuncSetAttribute(conv_mma<3, OUP, WID,  WID>, cudaFuncAttributeMaxDynamicSharedMemorySize, CONV_DSM);

    kZ_zero<<<(NB*HW + 255)/256, 256>>>();
    kT_transx<<<dim3(HW/64, CIN/64, NB), 256>>>(x, sm_w);
    kW_split<1><<<(WID*CIN  + 255)/256, 256>>>(w1);
    kB_dilate<<<NB, 256>>>(sm_b);
    kD_cmask<1><<<NB, 256>>>(cm1_w, cm1_b);

    conv_mma<1, WID, CIN, CIN><<<dim3(25, 1, NB), 256, CONV_DSM>>>(b1, out);

    kW_split<2><<<(WID*1152 + 255)/256, 256>>>(w2);
    kD_cmask<2><<<NB, 256>>>(cm2_w, cm2_b);

    conv_mma<2, WID, 1152, WID><<<dim3(25, 1, NB), 256, CONV_DSM>>>(b2, out);

    kW_split<3><<<(OUP*WID  + 255)/256, 256>>>(w3);
    kD_cmask<3><<<NB, 256>>>(cm3_w, cm3_b);

    conv_mma<3, OUP, WID, WID><<<dim3(25, 4, NB), 256, CONV_DSM>>>(b3, out);

    kH_rowcol<<<NB * OUP, 256>>>(out);
    kI_coord<<<NB, 128>>>(ca_w1, ca_b1, ca_wh, ca_bh, ca_ww, ca_bw);

    {
        size_t total4 = (size_t)NB * OUP * HW / 4;
        kJ_final<<<(unsigned)((total4 + 255) / 256), 256>>>(x, out);
    }
}

// round 10
// speedup vs baseline: 7.1522x; 1.3490x over previous
#include <cuda_runtime.h>
#include <cuda_bf16.h>
#include <math.h>
#include <stdint.h>

// ---------------------------------------------------------------------------
// Problem constants
// ---------------------------------------------------------------------------
#define NB   16
#define CIN  512
#define WID  128
#define OUP  512
#define HH   56
#define WW   56
#define HW   (HH*WW)     // 3136
#define MIP  16

union U8 { __nv_bfloat16 h[8]; uint4 u; };

__device__ __forceinline__ uint32_t smem_u32(const void* p) {
    uint32_t a;
    asm("{ .reg .u64 t; cvta.to.shared.u64 t, %1; cvt.u32.u64 %0, t; }" : "=r"(a) : "l"(p));
    return a;
}
__device__ __forceinline__ void ldsm4(uint32_t* r, uint32_t a) {
    asm volatile("ldmatrix.sync.aligned.m8n8.x4.shared.b16 {%0,%1,%2,%3}, [%4];"
                 : "=r"(r[0]), "=r"(r[1]), "=r"(r[2]), "=r"(r[3]) : "r"(a));
}
__device__ __forceinline__ void mma_bf(float* c, const uint32_t* a, uint32_t b0, uint32_t b1) {
    asm volatile("mma.sync.aligned.m16n8k16.row.col.f32.bf16.bf16.f32 "
                 "{%0,%1,%2,%3}, {%4,%5,%6,%7}, {%8,%9}, {%0,%1,%2,%3};"
                 : "+f"(c[0]), "+f"(c[1]), "+f"(c[2]), "+f"(c[3])
                 : "r"(a[0]), "r"(a[1]), "r"(a[2]), "r"(a[3]), "r"(b0), "r"(b1));
}
__device__ __forceinline__ void cpa16(uint32_t d, const void* s, uint32_t srcsz) {
    asm volatile("cp.async.cg.shared.global [%0], [%1], 16, %2;"
                 :: "r"(d), "l"(s), "r"(srcsz) : "memory");
}
__device__ __forceinline__ void cpa_commit() { asm volatile("cp.async.commit_group;" ::: "memory"); }
template<int N> __device__ __forceinline__ void cpa_wait() {
    asm volatile("cp.async.wait_group %0;" :: "n"(N) : "memory");
}

// ---------------------------------------------------------------------------
// Scratch — __device__ globals, referenced ONLY inside device code.
// ---------------------------------------------------------------------------
__device__ __align__(128) __nv_bfloat16 gx_hi [NB*HW*CIN];
__device__ __align__(128) __nv_bfloat16 gx_lo [NB*HW*CIN];
__device__ __align__(128) __nv_bfloat16 gh1_hi[NB*HW*WID];
__device__ __align__(128) __nv_bfloat16 gh1_lo[NB*HW*WID];
__device__ __align__(128) __nv_bfloat16 gh2_hi[NB*HW*WID];
__device__ __align__(128) __nv_bfloat16 gh2_lo[NB*HW*WID];
__device__ __align__(128) __nv_bfloat16 gw1h[WID*CIN],  gw1l[WID*CIN];
__device__ __align__(128) __nv_bfloat16 gw2h[WID*1152], gw2l[WID*1152];
__device__ __align__(128) __nv_bfloat16 gw3h[OUP*WID],  gw3l[OUP*WID];
__device__ __align__(16) float g_smlog[NB*HW];
__device__ __align__(16) float g_poolx[NB*CIN];
__device__ __align__(16) float g_pool1[NB*WID];
__device__ __align__(16) float g_pool2[NB*WID];
__device__ __align__(16) float g_ys   [NB*2*HH*MIP];
__device__ __align__(16) float s_sm [NB*HW];
__device__ __align__(16) float s_smd[NB*HW];
__device__ __align__(16) float s_c1 [NB*WID];
__device__ __align__(16) float s_c2 [NB*WID];
__device__ __align__(16) float s_c3 [NB*OUP];
__device__ __align__(16) float s_xh [NB*OUP*HH];
__device__ __align__(16) float s_xw [NB*OUP*WW];
__device__ __align__(16) float s_ah [NB*OUP*HH];
__device__ __align__(16) float s_aw [NB*OUP*WW];

// ---------------------------------------------------------------------------
// kZ: zero the atomic accumulators
// ---------------------------------------------------------------------------
__global__ void kZ_zero()
{
    int i = blockIdx.x * 256 + threadIdx.x;
    if (i < NB*HW)  g_smlog[i] = 0.f;
    if (i < NB*CIN) g_poolx[i] = 0.f;
    if (i < NB*WID) { g_pool1[i] = 0.f; g_pool2[i] = 0.f; }
}

// ---------------------------------------------------------------------------
// kT: transpose + bf16-split x [b,c,p] -> gx_hi/lo [b,p,c]
//     + fused partials: spatial-mask logit (per pixel), channel sums (per c)
// ---------------------------------------------------------------------------
__global__ __launch_bounds__(256) void kT_transx(const float* __restrict__ x,
                                                 const float* __restrict__ smw)
{
    __shared__ float ts[64][65];
    __shared__ float wsh[64];
    __shared__ float red[4][64];
    const int b  = blockIdx.z;
    const int c0 = blockIdx.y * 64;
    const int p0 = blockIdx.x * 64;
    const int t  = threadIdx.x;

    if (t < 64) wsh[t] = smw[c0 + t];
    {
        int ci = t >> 2, jg = (t & 3) * 16;
        const float* src = x + ((size_t)b * CIN + c0 + ci) * HW + p0 + jg;
        #pragma unroll
        for (int q = 0; q < 4; q++) {
            float4 f = *(const float4*)(src + q * 4);
            ts[ci][jg + q*4 + 0] = f.x; ts[ci][jg + q*4 + 1] = f.y;
            ts[ci][jg + q*4 + 2] = f.z; ts[ci][jg + q*4 + 3] = f.w;
        }
    }
    __syncthreads();

    {
        int g = t >> 6, pi = t & 63;
        float s = 0.f;
        #pragma unroll
        for (int cc = 0; cc < 16; cc++) s += ts[g*16 + cc][pi] * wsh[g*16 + cc];
        red[g][pi] = s;
    }
    __syncthreads();
    if (t < 64)
        atomicAdd(&g_smlog[b * HW + p0 + t], red[0][t] + red[1][t] + red[2][t] + red[3][t]);
    __syncthreads();

    {
        int c = t & 63, pg = t >> 6;
        float s = 0.f;
        #pragma unroll
        for (int i = 0; i < 16; i++) s += ts[c][pg*16 + i];
        red[pg][c] = s;
    }
    __syncthreads();
    if (t < 64)
        atomicAdd(&g_poolx[b * CIN + c0 + t], red[0][t] + red[1][t] + red[2][t] + red[3][t]);

    {
        int pi = t >> 2, cg = (t & 3) * 16;
        __nv_bfloat16* oh = gx_hi + ((size_t)b * HW + p0 + pi) * CIN + c0 + cg;
        __nv_bfloat16* ol = gx_lo + ((size_t)b * HW + p0 + pi) * CIN + c0 + cg;
        #pragma unroll
        for (int g = 0; g < 2; g++) {
            U8 hh, ll;
            #pragma unroll
            for (int j = 0; j < 8; j++) {
                float v = ts[cg + g*8 + j][pi];
                __nv_bfloat16 h = __float2bfloat16(v);
                hh.h[j] = h;
                ll.h[j] = __float2bfloat16(v - __bfloat162float(h));
            }
            *(uint4*)(oh + g*8) = hh.u;
            *(uint4*)(ol + g*8) = ll.u;
        }
    }
}

// ---------------------------------------------------------------------------
// kW: weight fp32 -> split bf16 (+ conv2 reorder k = r*128+c from [o][c*9+r])
// ---------------------------------------------------------------------------
template<int MODE>
__global__ void kW_split(const float* __restrict__ W)
{
    constexpr int M = (MODE == 3) ? OUP : WID;
    constexpr int K = (MODE == 1) ? CIN : ((MODE == 2) ? 1152 : WID);
    __nv_bfloat16* oh = (MODE == 1) ? gw1h : (MODE == 2 ? gw2h : gw3h);
    __nv_bfloat16* ol = (MODE == 1) ? gw1l : (MODE == 2 ? gw2l : gw3l);
    int i = blockIdx.x * 256 + threadIdx.x;
    if (i >= M * K) return;
    int o = i / K, k = i - o * K;
    float v;
    if (MODE == 2) {
        int r = k >> 7, c = k & 127;
        v = W[(size_t)o * 1152 + c * 9 + r];
    } else v = W[i];
    __nv_bfloat16 h = __float2bfloat16(v);
    oh[i] = h;
    ol[i] = __float2bfloat16(v - __bfloat162float(h));
}

// ---------------------------------------------------------------------------
// kB: threshold smask logits + 3x3 max dilation.  grid (NB, 7) row-strips.
// ---------------------------------------------------------------------------
__global__ __launch_bounds__(256) void kB_dilate(const float* __restrict__ smb)
{
    __shared__ float s[10][WW];
    int b  = blockIdx.x;
    int r0 = blockIdx.y * 8;
    float sb0 = smb[0];
    for (int i = threadIdx.x; i < 10 * WW; i += 256) {
        int rr = i / WW, cc = i - rr * WW;
        int gr = r0 + rr - 1;
        float m = 0.f;
        if (gr >= 0 && gr < HH)
            m = (g_smlog[b*HW + gr*WW + cc] + sb0) > 0.f ? 1.f : 0.f;
        s[rr][cc] = m;
    }
    __syncthreads();
    for (int i = threadIdx.x; i < 8 * WW; i += 256) {
        int rr = i / WW, cc = i - rr * WW;
        s_sm[b*HW + (r0+rr)*WW + cc] = s[rr+1][cc];
        float m = 0.f;
        #pragma unroll
        for (int dy = 0; dy < 3; dy++) {
            #pragma unroll
            for (int dx = -1; dx <= 1; dx++) {
                int xx = cc + dx; if (xx < 0 || xx >= WW) continue;
                m = fmaxf(m, s[rr+dy][xx]);
            }
        }
        s_smd[b*HW + (r0+rr)*WW + cc] = m;
    }
}

// ---------------------------------------------------------------------------
// kD: channel mask from accumulated sums.  grid (NB, CO/64).
// ---------------------------------------------------------------------------
template<int STAGE>
__global__ __launch_bounds__(256) void kD_cmask(const float* __restrict__ w,
                                                const float* __restrict__ bias)
{
    constexpr int CI = (STAGE == 1) ? CIN : WID;
    constexpr int CO = (STAGE == 3) ? OUP : WID;
    const float* psum = (STAGE == 1) ? g_poolx : (STAGE == 2 ? g_pool1 : g_pool2);
    float*       mask = (STAGE == 1) ? s_c1 : (STAGE == 2 ? s_c2 : s_c3);
    int b  = blockIdx.x;
    int o0 = blockIdx.y * 64;
    __shared__ float pr[CI];
    for (int i = threadIdx.x; i < CI; i += 256)
        pr[i] = psum[b*CI + i] * (1.f / HW);
    __syncthreads();
    int wrp = threadIdx.x >> 5, lane = threadIdx.x & 31;
    #pragma unroll
    for (int i = 0; i < 8; i++) {
        int o = o0 + wrp * 8 + i;
        const float* wr = w + (size_t)o * CI;
        float s = 0.f;
        #pragma unroll 4
        for (int c = lane; c < CI; c += 32) s += pr[c] * wr[c];
        #pragma unroll
        for (int off = 16; off > 0; off >>= 1) s += __shfl_xor_sync(0xffffffffu, s, off);
        if (lane == 0) mask[b*CO + o] = (s + bias[o]) > 0.f ? 1.f : 0.f;
    }
}

// ---------------------------------------------------------------------------
// conv_mma: mma.sync bf16-split GEMM, cp.async double-buffered.
// Tile: 128 px x 64 oc. K chunk 32. 2 stages x 30KB -> 3 CTAs/SM.
// grid (25, NOC/64, NB). 8 warps: wm=wid>>1 (32px), wn=wid&1 (32oc).
// MODE 1: conv1 K=512  act=gx  -> gh1 split (relu*cm1*smd) + pool1 partials
// MODE 2: conv2 K=1152 act=gh1 -> gh2 split (relu*cm2*sm)  + pool2 partials
// MODE 3: conv3 K=128  act=gh2 -> d_out fp32 [oc][p] (*cm3*sm)
// ---------------------------------------------------------------------------
#define A_HI 0
#define A_LO 10240
#define B_HI 20480
#define B_LO 25600
#define STG  30720
#define CONV_DSM (2*STG)

template<int MODE, int NOC, int K, int CI>
__global__ __launch_bounds__(256, 3)
void conv_mma(const float* __restrict__ bias, float* __restrict__ xout)
{
    extern __shared__ char dsm[];
    const uint32_t sb = smem_u32(dsm);
    __shared__ float pmv[128], cmb[64], bb[64];
    __shared__ float pool[64];

    const int tid  = threadIdx.x;
    const int wid  = tid >> 5;
    const int lane = tid & 31;
    const int b    = blockIdx.z;
    const int m0   = blockIdx.x * 128;       // pixel base
    const int n0g  = blockIdx.y * 64;        // out-channel base

    const __nv_bfloat16* act_h = (MODE == 1) ? gx_hi : (MODE == 2 ? gh1_hi : gh2_hi);
    const __nv_bfloat16* act_l = (MODE == 1) ? gx_lo : (MODE == 2 ? gh1_lo : gh2_lo);
    const __nv_bfloat16* wt_h  = (MODE == 1) ? gw1h : (MODE == 2 ? gw2h : gw3h);
    const __nv_bfloat16* wt_l  = (MODE == 1) ? gw1l : (MODE == 2 ? gw2l : gw3l);
    const float* cm = (MODE == 1) ? s_c1 : (MODE == 2 ? s_c2 : s_c3);
    const float* pm = (MODE == 1) ? s_smd : s_sm;

    if (tid < 128) {
        int p = m0 + tid;
        pmv[tid] = (p < HW) ? pm[b * HW + p] : 0.f;
    }
    if (tid < 64) {
        cmb[tid] = cm[b * NOC + n0g + tid];
        bb[tid]  = bias[n0g + tid];
        pool[tid] = 0.f;
    }

    const int prow = tid >> 1;               // A smem row 0..127
    const int u0   = (tid & 1) * 2;          // A 16B units {0,1} or {2,3}
    const int brow2 = tid >> 2;              // B smem row 0..63
    const int bu    = tid & 3;               // B 16B unit

    auto prefetch = [&](int ch, int st) {
        const uint32_t sbase = sb + st * STG;
        const int k0 = ch * 32;
        // A (activations, 128 px rows)
        {
            int p = m0 + prow;
            bool valid; int q, c0;
            if (MODE == 2) {
                int r  = ch >> 2;
                int ky = r / 3 - 1, kx = r % 3 - 1;
                int py = p / WW, px = p - py * WW;
                int iy = py + ky, ix = px + kx;
                valid = (p < HW) && iy >= 0 && iy < HH && ix >= 0 && ix < WW;
                q = iy * WW + ix;
                c0 = (ch & 3) * 32;
            } else { valid = (p < HW); q = p; c0 = k0; }
            uint32_t sz = valid ? 16u : 0u;
            const __nv_bfloat16* ah = act_h + ((size_t)b * HW + (valid ? q : 0)) * CI + c0 + u0 * 8;
            const __nv_bfloat16* al = act_l + ((size_t)b * HW + (valid ? q : 0)) * CI + c0 + u0 * 8;
            uint32_t dh = sbase + A_HI + prow * 80 + u0 * 16;
            uint32_t dl = sbase + A_LO + prow * 80 + u0 * 16;
            #pragma unroll
            for (int u = 0; u < 2; u++) {
                cpa16(dh + u * 16, ah + u * 8, sz);
                cpa16(dl + u * 16, al + u * 8, sz);
            }
        }
        // B (weights, 64 oc rows)
        {
            const __nv_bfloat16* wh = wt_h + (size_t)(n0g + brow2) * K + k0 + bu * 8;
            const __nv_bfloat16* wl = wt_l + (size_t)(n0g + brow2) * K + k0 + bu * 8;
            cpa16(sbase + B_HI + brow2 * 80 + bu * 16, wh, 16u);
            cpa16(sbase + B_LO + brow2 * 80 + bu * 16, wl, 16u);
        }
        cpa_commit();
    };

    float cacc[2][4][4];
    #pragma unroll
    for (int i = 0; i < 2; i++)
        #pragma unroll
        for (int j = 0; j < 4; j++)
            #pragma unroll
            for (int q = 0; q < 4; q++) cacc[i][j][q] = 0.f;

    const int wm = wid >> 1, wn = wid & 1;
    const int lr = lane & 7, s23 = lane >> 3;
    const int arow = (s23 & 1) * 8 + lr, acol = (s23 >> 1) * 8;
    const int brow = (s23 >> 1) * 8 + lr, bcol = (s23 & 1) * 8;

    constexpr int NC = K / 32;
    prefetch(0, 0);
    int buf = 0;
    for (int ch = 0; ch < NC; ch++) {
        if (ch + 1 < NC) { prefetch(ch + 1, buf ^ 1); cpa_wait<1>(); }
        else             { cpa_wait<0>(); }
        __syncthreads();

        const uint32_t sbb = sb + buf * STG;
        #pragma unroll
        for (int s = 0; s < 2; s++) {
            const int kb = s * 16;
            uint32_t ah[2][4], al[2][4];
            #pragma unroll
            for (int mi = 0; mi < 2; mi++) {
                uint32_t off = (uint32_t)((wm * 32 + mi * 16 + arow) * 80 + (kb + acol) * 2);
                ldsm4(ah[mi], sbb + A_HI + off);
                ldsm4(al[mi], sbb + A_LO + off);
            }
            #pragma unroll
            for (int np = 0; np < 2; np++) {
                uint32_t bh[4], bl[4];
                uint32_t off = (uint32_t)((wn * 32 + np * 16 + brow) * 80 + (kb + bcol) * 2);
                ldsm4(bh, sbb + B_HI + off);
                ldsm4(bl, sbb + B_LO + off);
                #pragma unroll
                for (int mi = 0; mi < 2; mi++) {
                    float* c0p = cacc[mi][np * 2];
                    float* c1p = cacc[mi][np * 2 + 1];
                    mma_bf(c0p, ah[mi], bh[0], bh[1]);
                    mma_bf(c0p, al[mi], bh[0], bh[1]);
                    mma_bf(c0p, ah[mi], bl[0], bl[1]);
                    mma_bf(c1p, ah[mi], bh[2], bh[3]);
                    mma_bf(c1p, al[mi], bh[2], bh[3]);
                    mma_bf(c1p, ah[mi], bl[2], bl[3]);
                }
            }
        }
        __syncthreads();
        buf ^= 1;
    }

    // ---- epilogue ----
    const int g = lane >> 2, tg = lane & 3;
    if (MODE != 3) {
        __nv_bfloat16* ohg = (MODE == 1 ? gh1_hi : gh2_hi);
        __nv_bfloat16* olg = (MODE == 1 ? gh1_lo : gh2_lo);
        float lsum[8];
        #pragma unroll
        for (int i = 0; i < 8; i++) lsum[i] = 0.f;
        #pragma unroll
        for (int mi = 0; mi < 2; mi++) {
            #pragma unroll
            for (int h = 0; h < 2; h++) {
                int pl = wm * 32 + mi * 16 + g + h * 8;
                int p  = m0 + pl;
                if (p < HW) {
                    float pmx = pmv[pl];
                    size_t rowoff = ((size_t)b * HW + p) * WID;
                    #pragma unroll
                    for (int nf = 0; nf < 4; nf++) {
                        int ocl = wn * 32 + nf * 8 + tg * 2;
                        float v0 = fmaxf(cacc[mi][nf][h*2+0] + bb[ocl],   0.f) * cmb[ocl]   * pmx;
                        float v1 = fmaxf(cacc[mi][nf][h*2+1] + bb[ocl+1], 0.f) * cmb[ocl+1] * pmx;
                        lsum[nf*2 + 0] += v0;
                        lsum[nf*2 + 1] += v1;
                        __nv_bfloat16 h0 = __float2bfloat16(v0);
                        __nv_bfloat16 h1 = __float2bfloat16(v1);
                        __nv_bfloat162 hp; hp.x = h0; hp.y = h1;
                        *(__nv_bfloat162*)(ohg + rowoff + n0g + ocl) = hp;
                        __nv_bfloat162 lp;
                        lp.x = __float2bfloat16(v0 - __bfloat162float(h0));
                        lp.y = __float2bfloat16(v1 - __bfloat162float(h1));
                        *(__nv_bfloat162*)(olg + rowoff + n0g + ocl) = lp;
                    }
                }
            }
        }
        #pragma unroll
        for (int nf = 0; nf < 4; nf++) {
            int ocl = wn * 32 + nf * 8 + tg * 2;
            atomicAdd(&pool[ocl],     lsum[nf*2 + 0]);
            atomicAdd(&pool[ocl + 1], lsum[nf*2 + 1]);
        }
        __syncthreads();
        float* gpool = (MODE == 1) ? g_pool1 : g_pool2;
        if (tid < 64) atomicAdd(&gpool[b * WID + n0g + tid], pool[tid]);
    } else {
        float* tf = (float*)dsm;          // reuse: [64 oc][132 p] = 33.8KB
        __syncthreads();
        #pragma unroll
        for (int mi = 0; mi < 2; mi++)
            #pragma unroll
            for (int h = 0; h < 2; h++) {
                int pl = wm * 32 + mi * 16 + g + h * 8;
                float pmx = pmv[pl];
                #pragma unroll
                for (int nf = 0; nf < 4; nf++) {
                    int ocl = wn * 32 + nf * 8 + tg * 2;
                    tf[ocl * 132 + pl]       = (cacc[mi][nf][h*2+0] + bb[ocl])   * cmb[ocl]   * pmx;
                    tf[(ocl + 1) * 132 + pl] = (cacc[mi][nf][h*2+1] + bb[ocl+1]) * cmb[ocl+1] * pmx;
                }
            }
        __syncthreads();
        int ocl = tid >> 2, q = tid & 3;
        if (m0 + q * 32 < HW) {
            float* orow = xout + ((size_t)b * OUP + n0g + ocl) * HW + m0 + q * 32;
            const float* src = tf + ocl * 132 + q * 32;
            #pragma unroll
            for (int gi = 0; gi < 8; gi++)
                *(float4*)(orow + gi * 4) = *(const float4*)(src + gi * 4);
        }
    }
}

// ---------------------------------------------------------------------------
// kH: row/col means of h3 (in d_out) -> s_xh, s_xw (smem-staged)
// ---------------------------------------------------------------------------
__global__ __launch_bounds__(256) void kH_rowcol(const float* __restrict__ h3)
{
    __shared__ float img[HW];
    int bc = blockIdx.x;
    const float* src = h3 + (size_t)bc * HW;
    for (int i = threadIdx.x; i < HW; i += 256) img[i] = src[i];
    __syncthreads();
    int t = threadIdx.x;
    if (t < WW) {
        float s = 0.f;
        #pragma unroll 8
        for (int h = 0; h < HH; h++) s += img[h * WW + t];
        s_xw[bc * WW + t] = s * (1.f / HH);
    } else if (t >= 64 && t < 64 + HH) {
        int r = t - 64;
        float s = 0.f;
        #pragma unroll 8
        for (int w = 0; w < WW; w++) s += img[r * WW + w];
        s_xh[bc * HH + r] = s * (1.f / WW);
    }
}

// ---------------------------------------------------------------------------
// kI1: coord-att squeeze conv (512->16) + hswish -> g_ys.  grid (NB, 14).
// warp per output position t (112 per b).
// ---------------------------------------------------------------------------
__global__ __launch_bounds__(256) void kI1(const float* __restrict__ w1,
                                           const float* __restrict__ b1)
{
    __shared__ float w1s[MIP * OUP];            // 32KB
    const int b = blockIdx.x;
    const int t = threadIdx.x;
    for (int i = t; i < MIP * OUP; i += 256) w1s[i] = w1[i];
    __syncthreads();
    const int wid = t >> 5, lane = t & 31;
    const int ti = blockIdx.y * 8 + wid;        // 0..111
    const float* src = (ti < HH)
        ? (s_xh + (size_t)b * OUP * HH + ti)
        : (s_xw + (size_t)b * OUP * WW + (ti - HH));
    float acc[MIP];
    #pragma unroll
    for (int m = 0; m < MIP; m++) acc[m] = 0.f;
    #pragma unroll 4
    for (int cc = 0; cc < 16; cc++) {
        int c = cc * 32 + lane;
        float v = src[(size_t)c * HH];
        #pragma unroll
        for (int m = 0; m < MIP; m++) acc[m] += v * w1s[m * OUP + c];
    }
    #pragma unroll
    for (int off = 16; off > 0; off >>= 1)
        #pragma unroll
        for (int m = 0; m < MIP; m++) acc[m] += __shfl_xor_sync(0xffffffffu, acc[m], off);
    if (lane == 0) {
        #pragma unroll
        for (int m = 0; m < MIP; m++) {
            float u = acc[m] + b1[m];
            float r6 = fminf(fmaxf(u + 3.f, 0.f), 6.f);
            g_ys[((size_t)b * 2 * HH + ti) * MIP + m] = u * r6 * (1.f / 6.f);
        }
    }
}

// ---------------------------------------------------------------------------
// kI2: coord-att excite convs (16->512) + sigmoid -> s_ah, s_aw. grid (NB, 8).
// ---------------------------------------------------------------------------
__global__ __launch_bounds__(256) void kI2(const float* __restrict__ wh,
                                           const float* __restrict__ bh,
                                           const float* __restrict__ ww,
                                           const float* __restrict__ bw)
{
    __shared__ float ys[2 * HH * MIP];          // 7KB
    const int b  = blockIdx.x;
    const int c0 = blockIdx.y * 64;
    const int t  = threadIdx.x;
    for (int i = t; i < 2 * HH * MIP; i += 256) ys[i] = g_ys[(size_t)b * 2 * HH * MIP + i];
    __syncthreads();
    const int cl = t >> 2, jq = t & 3;
    const int c  = c0 + cl;
    float whr[MIP], wwr[MIP];
    #pragma unroll
    for (int m = 0; m < MIP; m++) { whr[m] = wh[c*MIP + m]; wwr[m] = ww[c*MIP + m]; }
    const float bhc = bh[c], bwc = bw[c];
    #pragma unroll 2
    for (int jj = 0; jj < 14; jj++) {
        int j = jq * 14 + jj;
        float sh = bhc, sw = bwc;
        #pragma unroll
        for (int m = 0; m < MIP; m++) {
            sh += ys[j * MIP + m]        * whr[m];
            sw += ys[(HH + j) * MIP + m] * wwr[m];
        }
        s_ah[((size_t)b * OUP + c) * HH + j] = 1.f / (1.f + expf(-sh));
        s_aw[((size_t)b * OUP + c) * WW + j] = 1.f / (1.f + expf(-sw));
    }
}

// ---------------------------------------------------------------------------
// final: out = relu(h3 * ah * aw + x), in place on d_out
// ---------------------------------------------------------------------------
__global__ void kJ_final(const float* __restrict__ x, float* __restrict__ out)
{
    size_t i = (size_t)blockIdx.x * blockDim.x + threadIdx.x;
    const size_t total4 = (size_t)NB * OUP * HW / 4;
    if (i >= total4) return;
    size_t e   = i * 4;
    size_t row = e / WW;
    int    w   = (int)(e - row * WW);
    size_t bc  = row / HH;
    float a_h  = s_ah[row];
    const float* awp = s_aw + bc * WW + w;
    float4 hv = *(float4*)(out + e);
    float4 xv = *(const float4*)(x + e);
    float4 r;
    r.x = fmaxf(hv.x * a_h * awp[0] + xv.x, 0.f);
    r.y = fmaxf(hv.y * a_h * awp[1] + xv.y, 0.f);
    r.z = fmaxf(hv.z * a_h * awp[2] + xv.z, 0.f);
    r.w = fmaxf(hv.w * a_h * awp[3] + xv.w, 0.f);
    *(float4*)(out + e) = r;
}

// ---------------------------------------------------------------------------
// Launch — only harness pointers cross the host/device boundary.
// ---------------------------------------------------------------------------
extern "C" void kernel_launch(void* const* d_in, const int* in_sizes, int n_in,
                              void* d_out, int out_size)
{
    const float* x     = (const float*)d_in[0];
    const float* sm_w  = (const float*)d_in[1];
    const float* sm_b  = (const float*)d_in[2];
    const float* cm1_w = (const float*)d_in[3];
    const float* cm1_b = (const float*)d_in[4];
    const float* cm2_w = (const float*)d_in[5];
    const float* cm2_b = (const float*)d_in[6];
    const float* cm3_w = (const float*)d_in[7];
    const float* cm3_b = (const float*)d_in[8];
    const float* w1    = (const float*)d_in[9];
    const float* b1    = (const float*)d_in[10];
    const float* w2    = (const float*)d_in[11];
    const float* b2    = (const float*)d_in[12];
    const float* w3    = (const float*)d_in[13];
    const float* b3    = (const float*)d_in[14];
    const float* ca_w1 = (const float*)d_in[15];
    const float* ca_b1 = (const float*)d_in[16];
    const float* ca_wh = (const float*)d_in[17];
    const float* ca_bh = (const float*)d_in[18];
    const float* ca_ww = (const float*)d_in[19];
    const float* ca_bw = (const float*)d_in[20];
    float* out = (float*)d_out;

    cudaFuncSetAttribute(conv_mma<1, WID, CIN,  CIN>, cudaFuncAttributeMaxDynamicSharedMemorySize, CONV_DSM);
    cudaFuncSetAttribute(conv_mma<2, WID, 1152, WID>, cudaFuncAttributeMaxDynamicSharedMemorySize, CONV_DSM);
    cudaFuncSetAttribute(conv_mma<3, OUP, WID,  WID>, cudaFuncAttributeMaxDynamicSharedMemorySize, CONV_DSM);

    kZ_zero<<<(NB*HW + 255)/256, 256>>>();
    kT_transx<<<dim3(HW/64, CIN/64, NB), 256>>>(x, sm_w);
    kW_split<1><<<(WID*CIN  + 255)/256, 256>>>(w1);
    kB_dilate<<<dim3(NB, 7), 256>>>(sm_b);
    kD_cmask<1><<<dim3(NB, WID/64), 256>>>(cm1_w, cm1_b);

    conv_mma<1, WID, CIN, CIN><<<dim3(25, 2, NB), 256, CONV_DSM>>>(b1, out);

    kW_split<2><<<(WID*1152 + 255)/256, 256>>>(w2);
    kD_cmask<2><<<dim3(NB, WID/64), 256>>>(cm2_w, cm2_b);

    conv_mma<2, WID, 1152, WID><<<dim3(25, 2, NB), 256, CONV_DSM>>>(b2, out);

    kW_split<3><<<(OUP*WID  + 255)/256, 256>>>(w3);
    kD_cmask<3><<<dim3(NB, OUP/64), 256>>>(cm3_w, cm3_b);

    conv_mma<3, OUP, WID, WID><<<dim3(25, 8, NB), 256, CONV_DSM>>>(b3, out);

    kH_rowcol<<<NB * OUP, 256>>>(out);
    kI1<<<dim3(NB, 14), 256>>>(ca_w1, ca_b1);
    kI2<<<dim3(NB, 8),  256>>>(ca_wh, ca_bh, ca_ww, ca_bw);

    {
        size_t total4 = (size_t)NB * OUP * HW / 4;
        kJ_final<<<(unsigned)((total4 + 255) / 256), 256>>>(x, out);
    }
}

// round 11
// speedup vs baseline: 7.2892x; 1.0192x over previous
#include <cuda_runtime.h>
#include <cuda_bf16.h>
#include <math.h>
#include <stdint.h>

// ---------------------------------------------------------------------------
// Problem constants
// ---------------------------------------------------------------------------
#define NB   16
#define CIN  512
#define WID  128
#define OUP  512
#define HH   56
#define WW   56
#define HW   (HH*WW)     // 3136
#define MIP  16

union U8 { __nv_bfloat16 h[8]; uint4 u; };

__device__ __forceinline__ uint32_t smem_u32(const void* p) {
    uint32_t a;
    asm("{ .reg .u64 t; cvta.to.shared.u64 t, %1; cvt.u32.u64 %0, t; }" : "=r"(a) : "l"(p));
    return a;
}
__device__ __forceinline__ void ldsm4(uint32_t* r, uint32_t a) {
    asm volatile("ldmatrix.sync.aligned.m8n8.x4.shared.b16 {%0,%1,%2,%3}, [%4];"
                 : "=r"(r[0]), "=r"(r[1]), "=r"(r[2]), "=r"(r[3]) : "r"(a));
}
__device__ __forceinline__ void mma_bf(float* c, const uint32_t* a, uint32_t b0, uint32_t b1) {
    asm volatile("mma.sync.aligned.m16n8k16.row.col.f32.bf16.bf16.f32 "
                 "{%0,%1,%2,%3}, {%4,%5,%6,%7}, {%8,%9}, {%0,%1,%2,%3};"
                 : "+f"(c[0]), "+f"(c[1]), "+f"(c[2]), "+f"(c[3])
                 : "r"(a[0]), "r"(a[1]), "r"(a[2]), "r"(a[3]), "r"(b0), "r"(b1));
}
__device__ __forceinline__ void cpa16(uint32_t d, const void* s, uint32_t srcsz) {
    asm volatile("cp.async.cg.shared.global [%0], [%1], 16, %2;"
                 :: "r"(d), "l"(s), "r"(srcsz) : "memory");
}
__device__ __forceinline__ void cpa_commit() { asm volatile("cp.async.commit_group;" ::: "memory"); }
template<int N> __device__ __forceinline__ void cpa_wait() {
    asm volatile("cp.async.wait_group %0;" :: "n"(N) : "memory");
}

// ---------------------------------------------------------------------------
// Scratch — __device__ globals, referenced ONLY inside device code.
// ---------------------------------------------------------------------------
__device__ __align__(128) __nv_bfloat16 gx_hi [NB*HW*CIN];
__device__ __align__(128) __nv_bfloat16 gx_lo [NB*HW*CIN];
__device__ __align__(128) __nv_bfloat16 gh1_hi[NB*HW*WID];
__device__ __align__(128) __nv_bfloat16 gh1_lo[NB*HW*WID];
__device__ __align__(128) __nv_bfloat16 gh2_hi[NB*HW*WID];
__device__ __align__(128) __nv_bfloat16 gh2_lo[NB*HW*WID];
__device__ __align__(128) __nv_bfloat16 gw1h[WID*CIN],  gw1l[WID*CIN];
__device__ __align__(128) __nv_bfloat16 gw2h[WID*1152], gw2l[WID*1152];
__device__ __align__(128) __nv_bfloat16 gw3h[OUP*WID],  gw3l[OUP*WID];
__device__ __align__(16) float g_smlog[NB*HW];
__device__ __align__(16) float g_poolx[NB*CIN];
__device__ __align__(16) float g_pool1[NB*WID];
__device__ __align__(16) float g_pool2[NB*WID];
__device__ __align__(16) float g_ys   [NB*2*HH*MIP];
__device__ __align__(16) float s_sm [NB*HW];
__device__ __align__(16) float s_smd[NB*HW];
__device__ __align__(16) float s_c1 [NB*WID];
__device__ __align__(16) float s_c2 [NB*WID];
__device__ __align__(16) float s_c3 [NB*OUP];
__device__ __align__(16) float s_xh [NB*OUP*HH];
__device__ __align__(16) float s_xw [NB*OUP*WW];
__device__ __align__(16) float s_ah [NB*OUP*HH];
__device__ __align__(16) float s_aw [NB*OUP*WW];

// ---------------------------------------------------------------------------
// kZ: zero the atomic accumulators
// ---------------------------------------------------------------------------
__global__ void kZ_zero()
{
    int i = blockIdx.x * 256 + threadIdx.x;
    if (i < NB*HW)  g_smlog[i] = 0.f;
    if (i < NB*CIN) g_poolx[i] = 0.f;
    if (i < NB*WID) { g_pool1[i] = 0.f; g_pool2[i] = 0.f; }
}

// ---------------------------------------------------------------------------
// kT: transpose + bf16-split x [b,c,p] -> gx_hi/lo [b,p,c]
//     + fused partials: spatial-mask logit (per pixel), channel sums (per c)
// ---------------------------------------------------------------------------
__global__ __launch_bounds__(256) void kT_transx(const float* __restrict__ x,
                                                 const float* __restrict__ smw)
{
    __shared__ float ts[64][65];
    __shared__ float wsh[64];
    __shared__ float red[4][64];
    const int b  = blockIdx.z;
    const int c0 = blockIdx.y * 64;
    const int p0 = blockIdx.x * 64;
    const int t  = threadIdx.x;

    if (t < 64) wsh[t] = smw[c0 + t];
    {
        int ci = t >> 2, jg = (t & 3) * 16;
        const float* src = x + ((size_t)b * CIN + c0 + ci) * HW + p0 + jg;
        #pragma unroll
        for (int q = 0; q < 4; q++) {
            float4 f = *(const float4*)(src + q * 4);
            ts[ci][jg + q*4 + 0] = f.x; ts[ci][jg + q*4 + 1] = f.y;
            ts[ci][jg + q*4 + 2] = f.z; ts[ci][jg + q*4 + 3] = f.w;
        }
    }
    __syncthreads();

    {
        int g = t >> 6, pi = t & 63;
        float s = 0.f;
        #pragma unroll
        for (int cc = 0; cc < 16; cc++) s += ts[g*16 + cc][pi] * wsh[g*16 + cc];
        red[g][pi] = s;
    }
    __syncthreads();
    if (t < 64)
        atomicAdd(&g_smlog[b * HW + p0 + t], red[0][t] + red[1][t] + red[2][t] + red[3][t]);
    __syncthreads();

    {
        int c = t & 63, pg = t >> 6;
        float s = 0.f;
        #pragma unroll
        for (int i = 0; i < 16; i++) s += ts[c][pg*16 + i];
        red[pg][c] = s;
    }
    __syncthreads();
    if (t < 64)
        atomicAdd(&g_poolx[b * CIN + c0 + t], red[0][t] + red[1][t] + red[2][t] + red[3][t]);

    {
        int pi = t >> 2, cg = (t & 3) * 16;
        __nv_bfloat16* oh = gx_hi + ((size_t)b * HW + p0 + pi) * CIN + c0 + cg;
        __nv_bfloat16* ol = gx_lo + ((size_t)b * HW + p0 + pi) * CIN + c0 + cg;
        #pragma unroll
        for (int g = 0; g < 2; g++) {
            U8 hh, ll;
            #pragma unroll
            for (int j = 0; j < 8; j++) {
                float v = ts[cg + g*8 + j][pi];
                __nv_bfloat16 h = __float2bfloat16(v);
                hh.h[j] = h;
                ll.h[j] = __float2bfloat16(v - __bfloat162float(h));
            }
            *(uint4*)(oh + g*8) = hh.u;
            *(uint4*)(ol + g*8) = ll.u;
        }
    }
}

// ---------------------------------------------------------------------------
// kW: weight fp32 -> split bf16 (+ conv2 reorder k = r*128+c from [o][c*9+r])
// ---------------------------------------------------------------------------
template<int MODE>
__global__ void kW_split(const float* __restrict__ W)
{
    constexpr int M = (MODE == 3) ? OUP : WID;
    constexpr int K = (MODE == 1) ? CIN : ((MODE == 2) ? 1152 : WID);
    __nv_bfloat16* oh = (MODE == 1) ? gw1h : (MODE == 2 ? gw2h : gw3h);
    __nv_bfloat16* ol = (MODE == 1) ? gw1l : (MODE == 2 ? gw2l : gw3l);
    int i = blockIdx.x * 256 + threadIdx.x;
    if (i >= M * K) return;
    int o = i / K, k = i - o * K;
    float v;
    if (MODE == 2) {
        int r = k >> 7, c = k & 127;
        v = W[(size_t)o * 1152 + c * 9 + r];
    } else v = W[i];
    __nv_bfloat16 h = __float2bfloat16(v);
    oh[i] = h;
    ol[i] = __float2bfloat16(v - __bfloat162float(h));
}

// ---------------------------------------------------------------------------
// kB: threshold smask logits + 3x3 max dilation.  grid (NB, 7) row-strips.
// ---------------------------------------------------------------------------
__global__ __launch_bounds__(256) void kB_dilate(const float* __restrict__ smb)
{
    __shared__ float s[10][WW];
    int b  = blockIdx.x;
    int r0 = blockIdx.y * 8;
    float sb0 = smb[0];
    for (int i = threadIdx.x; i < 10 * WW; i += 256) {
        int rr = i / WW, cc = i - rr * WW;
        int gr = r0 + rr - 1;
        float m = 0.f;
        if (gr >= 0 && gr < HH)
            m = (g_smlog[b*HW + gr*WW + cc] + sb0) > 0.f ? 1.f : 0.f;
        s[rr][cc] = m;
    }
    __syncthreads();
    for (int i = threadIdx.x; i < 8 * WW; i += 256) {
        int rr = i / WW, cc = i - rr * WW;
        s_sm[b*HW + (r0+rr)*WW + cc] = s[rr+1][cc];
        float m = 0.f;
        #pragma unroll
        for (int dy = 0; dy < 3; dy++) {
            #pragma unroll
            for (int dx = -1; dx <= 1; dx++) {
                int xx = cc + dx; if (xx < 0 || xx >= WW) continue;
                m = fmaxf(m, s[rr+dy][xx]);
            }
        }
        s_smd[b*HW + (r0+rr)*WW + cc] = m;
    }
}

// ---------------------------------------------------------------------------
// kD: channel mask from accumulated sums.  grid (NB, CO/64).
// ---------------------------------------------------------------------------
template<int STAGE>
__global__ __launch_bounds__(256) void kD_cmask(const float* __restrict__ w,
                                                const float* __restrict__ bias)
{
    constexpr int CI = (STAGE == 1) ? CIN : WID;
    constexpr int CO = (STAGE == 3) ? OUP : WID;
    const float* psum = (STAGE == 1) ? g_poolx : (STAGE == 2 ? g_pool1 : g_pool2);
    float*       mask = (STAGE == 1) ? s_c1 : (STAGE == 2 ? s_c2 : s_c3);
    int b  = blockIdx.x;
    int o0 = blockIdx.y * 64;
    __shared__ float pr[CI];
    for (int i = threadIdx.x; i < CI; i += 256)
        pr[i] = psum[b*CI + i] * (1.f / HW);
    __syncthreads();
    int wrp = threadIdx.x >> 5, lane = threadIdx.x & 31;
    #pragma unroll
    for (int i = 0; i < 8; i++) {
        int o = o0 + wrp * 8 + i;
        const float* wr = w + (size_t)o * CI;
        float s = 0.f;
        #pragma unroll 4
        for (int c = lane; c < CI; c += 32) s += pr[c] * wr[c];
        #pragma unroll
        for (int off = 16; off > 0; off >>= 1) s += __shfl_xor_sync(0xffffffffu, s, off);
        if (lane == 0) mask[b*CO + o] = (s + bias[o]) > 0.f ? 1.f : 0.f;
    }
}

// ---------------------------------------------------------------------------
// conv_mma: mma.sync bf16-split GEMM, cp.async double-buffered, ONE barrier
// per K-chunk: wait -> sync -> prefetch(buf^1) -> compute(buf).  The sync both
// publishes the waited stage and proves all warps finished reading buf^1.
// Tile: 128 px x 64 oc. K chunk 32. 2 stages x 30KB -> 3 CTAs/SM.
// MODE 1: conv1 K=512  act=gx  -> gh1 split (relu*cm1*smd) + pool1 partials
// MODE 2: conv2 K=1152 act=gh1 -> gh2 split (relu*cm2*sm)  + pool2 partials
// MODE 3: conv3 K=128  act=gh2 -> d_out fp32 [oc][p] (*cm3*sm)
// ---------------------------------------------------------------------------
#define A_HI 0
#define A_LO 10240
#define B_HI 20480
#define B_LO 25600
#define STG  30720
#define CONV_DSM (2*STG)

template<int MODE, int NOC, int K, int CI>
__global__ __launch_bounds__(256, 3)
void conv_mma(const float* __restrict__ bias, float* __restrict__ xout)
{
    extern __shared__ char dsm[];
    const uint32_t sb = smem_u32(dsm);
    __shared__ float pmv[128], cmb[64], bb[64];
    __shared__ float pool[64];

    const int tid  = threadIdx.x;
    const int wid  = tid >> 5;
    const int lane = tid & 31;
    const int b    = blockIdx.z;
    const int m0   = blockIdx.x * 128;       // pixel base
    const int n0g  = blockIdx.y * 64;        // out-channel base

    const __nv_bfloat16* act_h = (MODE == 1) ? gx_hi : (MODE == 2 ? gh1_hi : gh2_hi);
    const __nv_bfloat16* act_l = (MODE == 1) ? gx_lo : (MODE == 2 ? gh1_lo : gh2_lo);
    const __nv_bfloat16* wt_h  = (MODE == 1) ? gw1h : (MODE == 2 ? gw2h : gw3h);
    const __nv_bfloat16* wt_l  = (MODE == 1) ? gw1l : (MODE == 2 ? gw2l : gw3l);
    const float* cm = (MODE == 1) ? s_c1 : (MODE == 2 ? s_c2 : s_c3);
    const float* pm = (MODE == 1) ? s_smd : s_sm;

    if (tid < 128) {
        int p = m0 + tid;
        pmv[tid] = (p < HW) ? pm[b * HW + p] : 0.f;
    }
    if (tid < 64) {
        cmb[tid] = cm[b * NOC + n0g + tid];
        bb[tid]  = bias[n0g + tid];
        pool[tid] = 0.f;
    }

    const int prow = tid >> 1;               // A smem row 0..127
    const int u0   = (tid & 1) * 2;          // A 16B units {0,1} or {2,3}
    const int brow2 = tid >> 2;              // B smem row 0..63
    const int bu    = tid & 3;               // B 16B unit

    auto prefetch = [&](int ch, int st) {
        const uint32_t sbase = sb + st * STG;
        const int k0 = ch * 32;
        // A (activations, 128 px rows)
        {
            int p = m0 + prow;
            bool valid; int q, c0;
            if (MODE == 2) {
                int r  = ch >> 2;
                int ky = r / 3 - 1, kx = r % 3 - 1;
                int py = p / WW, px = p - py * WW;
                int iy = py + ky, ix = px + kx;
                valid = (p < HW) && iy >= 0 && iy < HH && ix >= 0 && ix < WW;
                q = iy * WW + ix;
                c0 = (ch & 3) * 32;
            } else { valid = (p < HW); q = p; c0 = k0; }
            uint32_t sz = valid ? 16u : 0u;
            const __nv_bfloat16* ah = act_h + ((size_t)b * HW + (valid ? q : 0)) * CI + c0 + u0 * 8;
            const __nv_bfloat16* al = act_l + ((size_t)b * HW + (valid ? q : 0)) * CI + c0 + u0 * 8;
            uint32_t dh = sbase + A_HI + prow * 80 + u0 * 16;
            uint32_t dl = sbase + A_LO + prow * 80 + u0 * 16;
            #pragma unroll
            for (int u = 0; u < 2; u++) {
                cpa16(dh + u * 16, ah + u * 8, sz);
                cpa16(dl + u * 16, al + u * 8, sz);
            }
        }
        // B (weights, 64 oc rows)
        {
            const __nv_bfloat16* wh = wt_h + (size_t)(n0g + brow2) * K + k0 + bu * 8;
            const __nv_bfloat16* wl = wt_l + (size_t)(n0g + brow2) * K + k0 + bu * 8;
            cpa16(sbase + B_HI + brow2 * 80 + bu * 16, wh, 16u);
            cpa16(sbase + B_LO + brow2 * 80 + bu * 16, wl, 16u);
        }
        cpa_commit();
    };

    float cacc[2][4][4];
    #pragma unroll
    for (int i = 0; i < 2; i++)
        #pragma unroll
        for (int j = 0; j < 4; j++)
            #pragma unroll
            for (int q = 0; q < 4; q++) cacc[i][j][q] = 0.f;

    const int wm = wid >> 1, wn = wid & 1;
    const int lr = lane & 7, s23 = lane >> 3;
    const int arow = (s23 & 1) * 8 + lr, acol = (s23 >> 1) * 8;
    const int brow = (s23 >> 1) * 8 + lr, bcol = (s23 & 1) * 8;

    constexpr int NC = K / 32;
    prefetch(0, 0);
    int buf = 0;
    for (int ch = 0; ch < NC; ch++) {
        cpa_wait<0>();
        __syncthreads();                 // publishes stage buf; all warps done reading buf^1
        if (ch + 1 < NC) prefetch(ch + 1, buf ^ 1);

        const uint32_t sbb = sb + buf * STG;
        #pragma unroll
        for (int s = 0; s < 2; s++) {
            const int kb = s * 16;
            uint32_t ah[2][4], al[2][4];
            #pragma unroll
            for (int mi = 0; mi < 2; mi++) {
                uint32_t off = (uint32_t)((wm * 32 + mi * 16 + arow) * 80 + (kb + acol) * 2);
                ldsm4(ah[mi], sbb + A_HI + off);
                ldsm4(al[mi], sbb + A_LO + off);
            }
            #pragma unroll
            for (int np = 0; np < 2; np++) {
                uint32_t bh[4], bl[4];
                uint32_t off = (uint32_t)((wn * 32 + np * 16 + brow) * 80 + (kb + bcol) * 2);
                ldsm4(bh, sbb + B_HI + off);
                ldsm4(bl, sbb + B_LO + off);
                #pragma unroll
                for (int mi = 0; mi < 2; mi++) {
                    float* c0p = cacc[mi][np * 2];
                    float* c1p = cacc[mi][np * 2 + 1];
                    mma_bf(c0p, ah[mi], bh[0], bh[1]);
                    mma_bf(c0p, al[mi], bh[0], bh[1]);
                    mma_bf(c0p, ah[mi], bl[0], bl[1]);
                    mma_bf(c1p, ah[mi], bh[2], bh[3]);
                    mma_bf(c1p, al[mi], bh[2], bh[3]);
                    mma_bf(c1p, ah[mi], bl[2], bl[3]);
                }
            }
        }
        buf ^= 1;
    }

    // ---- epilogue ----
    const int g = lane >> 2, tg = lane & 3;
    if (MODE != 3) {
        __nv_bfloat16* ohg = (MODE == 1 ? gh1_hi : gh2_hi);
        __nv_bfloat16* olg = (MODE == 1 ? gh1_lo : gh2_lo);
        float lsum[8];
        #pragma unroll
        for (int i = 0; i < 8; i++) lsum[i] = 0.f;
        #pragma unroll
        for (int mi = 0; mi < 2; mi++) {
            #pragma unroll
            for (int h = 0; h < 2; h++) {
                int pl = wm * 32 + mi * 16 + g + h * 8;
                int p  = m0 + pl;
                if (p < HW) {
                    float pmx = pmv[pl];
                    size_t rowoff = ((size_t)b * HW + p) * WID;
                    #pragma unroll
                    for (int nf = 0; nf < 4; nf++) {
                        int ocl = wn * 32 + nf * 8 + tg * 2;
                        float v0 = fmaxf(cacc[mi][nf][h*2+0] + bb[ocl],   0.f) * cmb[ocl]   * pmx;
                        float v1 = fmaxf(cacc[mi][nf][h*2+1] + bb[ocl+1], 0.f) * cmb[ocl+1] * pmx;
                        lsum[nf*2 + 0] += v0;
                        lsum[nf*2 + 1] += v1;
                        __nv_bfloat16 h0 = __float2bfloat16(v0);
                        __nv_bfloat16 h1 = __float2bfloat16(v1);
                        __nv_bfloat162 hp; hp.x = h0; hp.y = h1;
                        *(__nv_bfloat162*)(ohg + rowoff + n0g + ocl) = hp;
                        __nv_bfloat162 lp;
                        lp.x = __float2bfloat16(v0 - __bfloat162float(h0));
                        lp.y = __float2bfloat16(v1 - __bfloat162float(h1));
                        *(__nv_bfloat162*)(olg + rowoff + n0g + ocl) = lp;
                    }
                }
            }
        }
        #pragma unroll
        for (int nf = 0; nf < 4; nf++) {
            int ocl = wn * 32 + nf * 8 + tg * 2;
            atomicAdd(&pool[ocl],     lsum[nf*2 + 0]);
            atomicAdd(&pool[ocl + 1], lsum[nf*2 + 1]);
        }
        __syncthreads();
        float* gpool = (MODE == 1) ? g_pool1 : g_pool2;
        if (tid < 64) atomicAdd(&gpool[b * WID + n0g + tid], pool[tid]);
    } else {
        float* tf = (float*)dsm;          // reuse: [64 oc][132 p] = 33.8KB
        __syncthreads();
        #pragma unroll
        for (int mi = 0; mi < 2; mi++)
            #pragma unroll
            for (int h = 0; h < 2; h++) {
                int pl = wm * 32 + mi * 16 + g + h * 8;
                float pmx = pmv[pl];
                #pragma unroll
                for (int nf = 0; nf < 4; nf++) {
                    int ocl = wn * 32 + nf * 8 + tg * 2;
                    tf[ocl * 132 + pl]       = (cacc[mi][nf][h*2+0] + bb[ocl])   * cmb[ocl]   * pmx;
                    tf[(ocl + 1) * 132 + pl] = (cacc[mi][nf][h*2+1] + bb[ocl+1]) * cmb[ocl+1] * pmx;
                }
            }
        __syncthreads();
        int ocl = tid >> 2, q = tid & 3;
        if (m0 + q * 32 < HW) {
            float* orow = xout + ((size_t)b * OUP + n0g + ocl) * HW + m0 + q * 32;
            const float* src = tf + ocl * 132 + q * 32;
            #pragma unroll
            for (int gi = 0; gi < 8; gi++)
                *(float4*)(orow + gi * 4) = *(const float4*)(src + gi * 4);
        }
    }
}

// ---------------------------------------------------------------------------
// kH: row/col means of h3 (in d_out) -> s_xh, s_xw (smem-staged)
// ---------------------------------------------------------------------------
__global__ __launch_bounds__(256) void kH_rowcol(const float* __restrict__ h3)
{
    __shared__ float img[HW];
    int bc = blockIdx.x;
    const float* src = h3 + (size_t)bc * HW;
    for (int i = threadIdx.x; i < HW; i += 256) img[i] = src[i];
    __syncthreads();
    int t = threadIdx.x;
    if (t < WW) {
        float s = 0.f;
        #pragma unroll 8
        for (int h = 0; h < HH; h++) s += img[h * WW + t];
        s_xw[bc * WW + t] = s * (1.f / HH);
    } else if (t >= 64 && t < 64 + HH) {
        int r = t - 64;
        float s = 0.f;
        #pragma unroll 8
        for (int w = 0; w < WW; w++) s += img[r * WW + w];
        s_xh[bc * HH + r] = s * (1.f / WW);
    }
}

// ---------------------------------------------------------------------------
// kI1: coord-att squeeze conv (512->16) + hswish -> g_ys.  grid (NB, 14).
// ---------------------------------------------------------------------------
__global__ __launch_bounds__(256) void kI1(const float* __restrict__ w1,
                                           const float* __restrict__ b1)
{
    __shared__ float w1s[MIP * OUP];            // 32KB
    const int b = blockIdx.x;
    const int t = threadIdx.x;
    for (int i = t; i < MIP * OUP; i += 256) w1s[i] = w1[i];
    __syncthreads();
    const int wid = t >> 5, lane = t & 31;
    const int ti = blockIdx.y * 8 + wid;        // 0..111
    const float* src = (ti < HH)
        ? (s_xh + (size_t)b * OUP * HH + ti)
        : (s_xw + (size_t)b * OUP * WW + (ti - HH));
    float acc[MIP];
    #pragma unroll
    for (int m = 0; m < MIP; m++) acc[m] = 0.f;
    #pragma unroll 4
    for (int cc = 0; cc < 16; cc++) {
        int c = cc * 32 + lane;
        float v = src[(size_t)c * HH];
        #pragma unroll
        for (int m = 0; m < MIP; m++) acc[m] += v * w1s[m * OUP + c];
    }
    #pragma unroll
    for (int off = 16; off > 0; off >>= 1)
        #pragma unroll
        for (int m = 0; m < MIP; m++) acc[m] += __shfl_xor_sync(0xffffffffu, acc[m], off);
    if (lane == 0) {
        #pragma unroll
        for (int m = 0; m < MIP; m++) {
            float u = acc[m] + b1[m];
            float r6 = fminf(fmaxf(u + 3.f, 0.f), 6.f);
            g_ys[((size_t)b * 2 * HH + ti) * MIP + m] = u * r6 * (1.f / 6.f);
        }
    }
}

// ---------------------------------------------------------------------------
// kI2: coord-att excite convs (16->512) + sigmoid -> s_ah, s_aw. grid (NB, 8).
// ---------------------------------------------------------------------------
__global__ __launch_bounds__(256) void kI2(const float* __restrict__ wh,
                                           const float* __restrict__ bh,
                                           const float* __restrict__ ww,
                                           const float* __restrict__ bw)
{
    __shared__ float ys[2 * HH * MIP];          // 7KB
    const int b  = blockIdx.x;
    const int c0 = blockIdx.y * 64;
    const int t  = threadIdx.x;
    for (int i = t; i < 2 * HH * MIP; i += 256) ys[i] = g_ys[(size_t)b * 2 * HH * MIP + i];
    __syncthreads();
    const int cl = t >> 2, jq = t & 3;
    const int c  = c0 + cl;
    float whr[MIP], wwr[MIP];
    #pragma unroll
    for (int m = 0; m < MIP; m++) { whr[m] = wh[c*MIP + m]; wwr[m] = ww[c*MIP + m]; }
    const float bhc = bh[c], bwc = bw[c];
    #pragma unroll 2
    for (int jj = 0; jj < 14; jj++) {
        int j = jq * 14 + jj;
        float sh = bhc, sw = bwc;
        #pragma unroll
        for (int m = 0; m < MIP; m++) {
            sh += ys[j * MIP + m]        * whr[m];
            sw += ys[(HH + j) * MIP + m] * wwr[m];
        }
        s_ah[((size_t)b * OUP + c) * HH + j] = 1.f / (1.f + expf(-sh));
        s_aw[((size_t)b * OUP + c) * WW + j] = 1.f / (1.f + expf(-sw));
    }
}

// ---------------------------------------------------------------------------
// final: out = relu(h3 * ah * aw + x), in place on d_out
// ---------------------------------------------------------------------------
__global__ void kJ_final(const float* __restrict__ x, float* __restrict__ out)
{
    size_t i = (size_t)blockIdx.x * blockDim.x + threadIdx.x;
    const size_t total4 = (size_t)NB * OUP * HW / 4;
    if (i >= total4) return;
    size_t e   = i * 4;
    size_t row = e / WW;
    int    w   = (int)(e - row * WW);
    size_t bc  = row / HH;
    float a_h  = s_ah[row];
    const float* awp = s_aw + bc * WW + w;
    float4 hv = *(float4*)(out + e);
    float4 xv = *(const float4*)(x + e);
    float4 r;
    r.x = fmaxf(hv.x * a_h * awp[0] + xv.x, 0.f);
    r.y = fmaxf(hv.y * a_h * awp[1] + xv.y, 0.f);
    r.z = fmaxf(hv.z * a_h * awp[2] + xv.z, 0.f);
    r.w = fmaxf(hv.w * a_h * awp[3] + xv.w, 0.f);
    *(float4*)(out + e) = r;
}

// ---------------------------------------------------------------------------
// Launch — only harness pointers cross the host/device boundary.
// ---------------------------------------------------------------------------
extern "C" void kernel_launch(void* const* d_in, const int* in_sizes, int n_in,
                              void* d_out, int out_size)
{
    const float* x     = (const float*)d_in[0];
    const float* sm_w  = (const float*)d_in[1];
    const float* sm_b  = (const float*)d_in[2];
    const float* cm1_w = (const float*)d_in[3];
    const float* cm1_b = (const float*)d_in[4];
    const float* cm2_w = (const float*)d_in[5];
    const float* cm2_b = (const float*)d_in[6];
    const float* cm3_w = (const float*)d_in[7];
    const float* cm3_b = (const float*)d_in[8];
    const float* w1    = (const float*)d_in[9];
    const float* b1    = (const float*)d_in[10];
    const float* w2    = (const float*)d_in[11];
    const float* b2    = (const float*)d_in[12];
    const float* w3    = (const float*)d_in[13];
    const float* b3    = (const float*)d_in[14];
    const float* ca_w1 = (const float*)d_in[15];
    const float* ca_b1 = (const float*)d_in[16];
    const float* ca_wh = (const float*)d_in[17];
    const float* ca_bh = (const float*)d_in[18];
    const float* ca_ww = (const float*)d_in[19];
    const float* ca_bw = (const float*)d_in[20];
    float* out = (float*)d_out;

    cudaFuncSetAttribute(conv_mma<1, WID, CIN,  CIN>, cudaFuncAttributeMaxDynamicSharedMemorySize, CONV_DSM);
    cudaFuncSetAttribute(conv_mma<2, WID, 1152, WID>, cudaFuncAttributeMaxDynamicSharedMemorySize, CONV_DSM);
    cudaFuncSetAttribute(conv_mma<3, OUP, WID,  WID>, cudaFuncAttributeMaxDynamicSharedMemorySize, CONV_DSM);

    kZ_zero<<<(NB*HW + 255)/256, 256>>>();
    kT_transx<<<dim3(HW/64, CIN/64, NB), 256>>>(x, sm_w);
    kW_split<1><<<(WID*CIN  + 255)/256, 256>>>(w1);
    kB_dilate<<<dim3(NB, 7), 256>>>(sm_b);
    kD_cmask<1><<<dim3(NB, WID/64), 256>>>(cm1_w, cm1_b);

    conv_mma<1, WID, CIN, CIN><<<dim3(25, 2, NB), 256, CONV_DSM>>>(b1, out);

    kW_split<2><<<(WID*1152 + 255)/256, 256>>>(w2);
    kD_cmask<2><<<dim3(NB, WID/64), 256>>>(cm2_w, cm2_b);

    conv_mma<2, WID, 1152, WID><<<dim3(25, 2, NB), 256, CONV_DSM>>>(b2, out);

    kW_split<3><<<(OUP*WID  + 255)/256, 256>>>(w3);
    kD_cmask<3><<<dim3(NB, OUP/64), 256>>>(cm3_w, cm3_b);

    conv_mma<3, OUP, WID, WID><<<dim3(25, 8, NB), 256, CONV_DSM>>>(b3, out);

    kH_rowcol<<<NB * OUP, 256>>>(out);
    kI1<<<dim3(NB, 14), 256>>>(ca_w1, ca_b1);
    kI2<<<dim3(NB, 8),  256>>>(ca_wh, ca_bh, ca_ww, ca_bw);

    {
        size_t total4 = (size_t)NB * OUP * HW / 4;
        kJ_final<<<(unsigned)((total4 + 255) / 256), 256>>>(x, out);
    }
}

// round 12
// speedup vs baseline: 8.2870x; 1.1369x over previous
#include <cuda_runtime.h>
#include <cuda_bf16.h>
#include <math.h>
#include <stdint.h>

// ---------------------------------------------------------------------------
// Problem constants
// ---------------------------------------------------------------------------
#define NB   16
#define CIN  512
#define WID  128
#define OUP  512
#define HH   56
#define WW   56
#define HW   (HH*WW)     // 3136
#define MIP  16

union U8 { __nv_bfloat16 h[8]; uint4 u; };

__device__ __forceinline__ uint32_t smem_u32(const void* p) {
    uint32_t a;
    asm("{ .reg .u64 t; cvta.to.shared.u64 t, %1; cvt.u32.u64 %0, t; }" : "=r"(a) : "l"(p));
    return a;
}
__device__ __forceinline__ void ldsm4(uint32_t* r, uint32_t a) {
    asm volatile("ldmatrix.sync.aligned.m8n8.x4.shared.b16 {%0,%1,%2,%3}, [%4];"
                 : "=r"(r[0]), "=r"(r[1]), "=r"(r[2]), "=r"(r[3]) : "r"(a));
}
__device__ __forceinline__ void mma_bf(float* c, const uint32_t* a, uint32_t b0, uint32_t b1) {
    asm volatile("mma.sync.aligned.m16n8k16.row.col.f32.bf16.bf16.f32 "
                 "{%0,%1,%2,%3}, {%4,%5,%6,%7}, {%8,%9}, {%0,%1,%2,%3};"
                 : "+f"(c[0]), "+f"(c[1]), "+f"(c[2]), "+f"(c[3])
                 : "r"(a[0]), "r"(a[1]), "r"(a[2]), "r"(a[3]), "r"(b0), "r"(b1));
}
__device__ __forceinline__ void cpa16(uint32_t d, const void* s, uint32_t srcsz) {
    asm volatile("cp.async.cg.shared.global [%0], [%1], 16, %2;"
                 :: "r"(d), "l"(s), "r"(srcsz) : "memory");
}
__device__ __forceinline__ void cpa_commit() { asm volatile("cp.async.commit_group;" ::: "memory"); }
template<int N> __device__ __forceinline__ void cpa_wait() {
    asm volatile("cp.async.wait_group %0;" :: "n"(N) : "memory");
}

// ---------------------------------------------------------------------------
// Scratch — __device__ globals, referenced ONLY inside device code.
// ---------------------------------------------------------------------------
__device__ __align__(128) __nv_bfloat16 gx_hi [NB*HW*CIN];
__device__ __align__(128) __nv_bfloat16 gx_lo [NB*HW*CIN];
__device__ __align__(128) __nv_bfloat16 gh1_hi[NB*HW*WID];
__device__ __align__(128) __nv_bfloat16 gh1_lo[NB*HW*WID];
__device__ __align__(128) __nv_bfloat16 gh2_hi[NB*HW*WID];   // static zero-init: unlisted pixels stay 0
__device__ __align__(128) __nv_bfloat16 gh2_lo[NB*HW*WID];
__device__ __align__(128) __nv_bfloat16 gw1h[WID*CIN],  gw1l[WID*CIN];
__device__ __align__(128) __nv_bfloat16 gw2h[WID*1152], gw2l[WID*1152];
__device__ __align__(128) __nv_bfloat16 gw3h[OUP*WID],  gw3l[OUP*WID];
__device__ __align__(16) float g_smlog[NB*HW];
__device__ __align__(16) float g_poolx[NB*CIN];
__device__ __align__(16) float g_pool1[NB*WID];
__device__ __align__(16) float g_pool2[NB*WID];
__device__ __align__(16) float g_ys   [NB*2*HH*MIP];
__device__ __align__(16) int   g_idx  [NB*HW];   // compacted s_sm=1 pixel list
__device__ __align__(16) int   g_cnt  [NB];
__device__ __align__(16) float s_sm [NB*HW];
__device__ __align__(16) float s_smd[NB*HW];
__device__ __align__(16) float s_c1 [NB*WID];
__device__ __align__(16) float s_c2 [NB*WID];
__device__ __align__(16) float s_c3 [NB*OUP];
__device__ __align__(16) float s_xh [NB*OUP*HH];
__device__ __align__(16) float s_xw [NB*OUP*WW];
__device__ __align__(16) float s_ah [NB*OUP*HH];
__device__ __align__(16) float s_aw [NB*OUP*WW];

// ---------------------------------------------------------------------------
// kZ: zero the atomic accumulators
// ---------------------------------------------------------------------------
__global__ void kZ_zero()
{
    int i = blockIdx.x * 256 + threadIdx.x;
    if (i < NB*HW)  g_smlog[i] = 0.f;
    if (i < NB*CIN) g_poolx[i] = 0.f;
    if (i < NB*WID) { g_pool1[i] = 0.f; g_pool2[i] = 0.f; }
}

// ---------------------------------------------------------------------------
// kT: transpose + bf16-split x [b,c,p] -> gx_hi/lo [b,p,c]
//     + fused partials: spatial-mask logit (per pixel), channel sums (per c)
// ---------------------------------------------------------------------------
__global__ __launch_bounds__(256) void kT_transx(const float* __restrict__ x,
                                                 const float* __restrict__ smw)
{
    __shared__ float ts[64][65];
    __shared__ float wsh[64];
    __shared__ float red[4][64];
    const int b  = blockIdx.z;
    const int c0 = blockIdx.y * 64;
    const int p0 = blockIdx.x * 64;
    const int t  = threadIdx.x;

    if (t < 64) wsh[t] = smw[c0 + t];
    {
        int ci = t >> 2, jg = (t & 3) * 16;
        const float* src = x + ((size_t)b * CIN + c0 + ci) * HW + p0 + jg;
        #pragma unroll
        for (int q = 0; q < 4; q++) {
            float4 f = *(const float4*)(src + q * 4);
            ts[ci][jg + q*4 + 0] = f.x; ts[ci][jg + q*4 + 1] = f.y;
            ts[ci][jg + q*4 + 2] = f.z; ts[ci][jg + q*4 + 3] = f.w;
        }
    }
    __syncthreads();

    {
        int g = t >> 6, pi = t & 63;
        float s = 0.f;
        #pragma unroll
        for (int cc = 0; cc < 16; cc++) s += ts[g*16 + cc][pi] * wsh[g*16 + cc];
        red[g][pi] = s;
    }
    __syncthreads();
    if (t < 64)
        atomicAdd(&g_smlog[b * HW + p0 + t], red[0][t] + red[1][t] + red[2][t] + red[3][t]);
    __syncthreads();

    {
        int c = t & 63, pg = t >> 6;
        float s = 0.f;
        #pragma unroll
        for (int i = 0; i < 16; i++) s += ts[c][pg*16 + i];
        red[pg][c] = s;
    }
    __syncthreads();
    if (t < 64)
        atomicAdd(&g_poolx[b * CIN + c0 + t], red[0][t] + red[1][t] + red[2][t] + red[3][t]);

    {
        int pi = t >> 2, cg = (t & 3) * 16;
        __nv_bfloat16* oh = gx_hi + ((size_t)b * HW + p0 + pi) * CIN + c0 + cg;
        __nv_bfloat16* ol = gx_lo + ((size_t)b * HW + p0 + pi) * CIN + c0 + cg;
        #pragma unroll
        for (int g = 0; g < 2; g++) {
            U8 hh, ll;
            #pragma unroll
            for (int j = 0; j < 8; j++) {
                float v = ts[cg + g*8 + j][pi];
                __nv_bfloat16 h = __float2bfloat16(v);
                hh.h[j] = h;
                ll.h[j] = __float2bfloat16(v - __bfloat162float(h));
            }
            *(uint4*)(oh + g*8) = hh.u;
            *(uint4*)(ol + g*8) = ll.u;
        }
    }
}

// ---------------------------------------------------------------------------
// kW: weight fp32 -> split bf16 (+ conv2 reorder k = r*128+c from [o][c*9+r])
// ---------------------------------------------------------------------------
template<int MODE>
__global__ void kW_split(const float* __restrict__ W)
{
    constexpr int M = (MODE == 3) ? OUP : WID;
    constexpr int K = (MODE == 1) ? CIN : ((MODE == 2) ? 1152 : WID);
    __nv_bfloat16* oh = (MODE == 1) ? gw1h : (MODE == 2 ? gw2h : gw3h);
    __nv_bfloat16* ol = (MODE == 1) ? gw1l : (MODE == 2 ? gw2l : gw3l);
    int i = blockIdx.x * 256 + threadIdx.x;
    if (i >= M * K) return;
    int o = i / K, k = i - o * K;
    float v;
    if (MODE == 2) {
        int r = k >> 7, c = k & 127;
        v = W[(size_t)o * 1152 + c * 9 + r];
    } else v = W[i];
    __nv_bfloat16 h = __float2bfloat16(v);
    oh[i] = h;
    ol[i] = __float2bfloat16(v - __bfloat162float(h));
}

// ---------------------------------------------------------------------------
// kB: threshold smask logits + 3x3 max dilation.  grid (NB, 7) row-strips.
// ---------------------------------------------------------------------------
__global__ __launch_bounds__(256) void kB_dilate(const float* __restrict__ smb)
{
    __shared__ float s[10][WW];
    int b  = blockIdx.x;
    int r0 = blockIdx.y * 8;
    float sb0 = smb[0];
    for (int i = threadIdx.x; i < 10 * WW; i += 256) {
        int rr = i / WW, cc = i - rr * WW;
        int gr = r0 + rr - 1;
        float m = 0.f;
        if (gr >= 0 && gr < HH)
            m = (g_smlog[b*HW + gr*WW + cc] + sb0) > 0.f ? 1.f : 0.f;
        s[rr][cc] = m;
    }
    __syncthreads();
    for (int i = threadIdx.x; i < 8 * WW; i += 256) {
        int rr = i / WW, cc = i - rr * WW;
        s_sm[b*HW + (r0+rr)*WW + cc] = s[rr+1][cc];
        float m = 0.f;
        #pragma unroll
        for (int dy = 0; dy < 3; dy++) {
            #pragma unroll
            for (int dx = -1; dx <= 1; dx++) {
                int xx = cc + dx; if (xx < 0 || xx >= WW) continue;
                m = fmaxf(m, s[rr+dy][xx]);
            }
        }
        s_smd[b*HW + (r0+rr)*WW + cc] = m;
    }
}

// ---------------------------------------------------------------------------
// kL: deterministic ordered compaction of s_sm=1 pixels. grid NB, 256 thr.
// ---------------------------------------------------------------------------
__global__ __launch_bounds__(256) void kL_list()
{
    __shared__ int wsum[8], wbase[8], total;
    const int b = blockIdx.x, t = threadIdx.x;
    const int wrp = t >> 5, lane = t & 31;
    if (t == 0) total = 0;
    __syncthreads();
    for (int i0 = 0; i0 < HW; i0 += 256) {
        int i = i0 + t;
        int f = (i < HW) ? (s_sm[b*HW + i] > 0.5f ? 1 : 0) : 0;
        unsigned bal = __ballot_sync(0xffffffffu, f);
        int wp = __popc(bal & ((1u << lane) - 1u));
        if (lane == 0) wsum[wrp] = __popc(bal);
        __syncthreads();
        if (t == 0) {
            int acc = total;
            #pragma unroll
            for (int w = 0; w < 8; w++) { wbase[w] = acc; acc += wsum[w]; }
            total = acc;
        }
        __syncthreads();
        if (f) g_idx[b*HW + wbase[wrp] + wp] = i;
        __syncthreads();
    }
    if (t == 0) g_cnt[b] = total;
}

// ---------------------------------------------------------------------------
// kD: channel mask from accumulated sums.  grid (NB, CO/64).
// ---------------------------------------------------------------------------
template<int STAGE>
__global__ __launch_bounds__(256) void kD_cmask(const float* __restrict__ w,
                                                const float* __restrict__ bias)
{
    constexpr int CI = (STAGE == 1) ? CIN : WID;
    constexpr int CO = (STAGE == 3) ? OUP : WID;
    const float* psum = (STAGE == 1) ? g_poolx : (STAGE == 2 ? g_pool1 : g_pool2);
    float*       mask = (STAGE == 1) ? s_c1 : (STAGE == 2 ? s_c2 : s_c3);
    int b  = blockIdx.x;
    int o0 = blockIdx.y * 64;
    __shared__ float pr[CI];
    for (int i = threadIdx.x; i < CI; i += 256)
        pr[i] = psum[b*CI + i] * (1.f / HW);
    __syncthreads();
    int wrp = threadIdx.x >> 5, lane = threadIdx.x & 31;
    #pragma unroll
    for (int i = 0; i < 8; i++) {
        int o = o0 + wrp * 8 + i;
        const float* wr = w + (size_t)o * CI;
        float s = 0.f;
        #pragma unroll 4
        for (int c = lane; c < CI; c += 32) s += pr[c] * wr[c];
        #pragma unroll
        for (int off = 16; off > 0; off >>= 1) s += __shfl_xor_sync(0xffffffffu, s, off);
        if (lane == 0) mask[b*CO + o] = (s + bias[o]) > 0.f ? 1.f : 0.f;
    }
}

// ---------------------------------------------------------------------------
// conv_mma: mma.sync bf16-split GEMM, cp.async double-buffered, one barrier
// per K-chunk.  Tile: 128 px x 64 oc, K chunk 32, 2 stages -> 3 CTAs/SM.
// MODE 1: conv1 K=512  act=gx  -> gh1 split (relu*cm1*smd) + pool1, full grid
// MODE 2: conv2 K=1152 act=gh1 -> gh2 split (relu*cm2), COMPACTED over s_sm=1
// MODE 3: conv3 K=128  act=gh2 -> d_out fp32 [oc][p] (*cm3*sm), full grid
// ---------------------------------------------------------------------------
#define A_HI 0
#define A_LO 10240
#define B_HI 20480
#define B_LO 25600
#define STG  30720
#define CONV_DSM (2*STG)

template<int MODE, int NOC, int K, int CI>
__global__ __launch_bounds__(256, 3)
void conv_mma(const float* __restrict__ bias, float* __restrict__ xout)
{
    extern __shared__ char dsm[];
    const uint32_t sb = smem_u32(dsm);
    __shared__ float pmv[128], cmb[64], bb[64];
    __shared__ float pool[64];
    __shared__ int   pidx[128];

    const int tid  = threadIdx.x;
    const int wid  = tid >> 5;
    const int lane = tid & 31;
    const int b    = blockIdx.z;
    const int m0   = blockIdx.x * 128;       // pixel base (compacted domain for MODE 2)
    const int n0g  = blockIdx.y * 64;        // out-channel base

    const int cnt = (MODE == 2) ? g_cnt[b] : HW;
    if (MODE == 2 && m0 >= cnt) return;

    const __nv_bfloat16* act_h = (MODE == 1) ? gx_hi : (MODE == 2 ? gh1_hi : gh2_hi);
    const __nv_bfloat16* act_l = (MODE == 1) ? gx_lo : (MODE == 2 ? gh1_lo : gh2_lo);
    const __nv_bfloat16* wt_h  = (MODE == 1) ? gw1h : (MODE == 2 ? gw2h : gw3h);
    const __nv_bfloat16* wt_l  = (MODE == 1) ? gw1l : (MODE == 2 ? gw2l : gw3l);
    const float* cm = (MODE == 1) ? s_c1 : (MODE == 2 ? s_c2 : s_c3);
    const float* pm = (MODE == 1) ? s_smd : s_sm;

    if (tid < 128) {
        int n = m0 + tid;
        if (MODE == 2) {
            pidx[tid] = (n < cnt) ? g_idx[b * HW + n] : 0;
            pmv[tid]  = 1.f;                 // s_sm == 1 on the list
        } else {
            pmv[tid] = (n < HW) ? pm[b * HW + n] : 0.f;
        }
    }
    if (tid < 64) {
        cmb[tid] = cm[b * NOC + n0g + tid];
        bb[tid]  = bias[n0g + tid];
        pool[tid] = 0.f;
    }
    __syncthreads();

    const int prow = tid >> 1;               // A smem row 0..127
    const int u0   = (tid & 1) * 2;          // A 16B units {0,1} or {2,3}
    const int brow2 = tid >> 2;              // B smem row 0..63
    const int bu    = tid & 3;               // B 16B unit

    auto prefetch = [&](int ch, int st) {
        const uint32_t sbase = sb + st * STG;
        const int k0 = ch * 32;
        // A (activations, 128 px rows)
        {
            int n = m0 + prow;
            bool valid; int q, c0;
            if (MODE == 2) {
                bool vrow = (n < cnt);
                int p = vrow ? pidx[prow] : 0;
                int r  = ch >> 2;
                int ky = r / 3 - 1, kx = r % 3 - 1;
                int py = p / WW, px = p - py * WW;
                int iy = py + ky, ix = px + kx;
                valid = vrow && iy >= 0 && iy < HH && ix >= 0 && ix < WW;
                q = iy * WW + ix;
                c0 = (ch & 3) * 32;
            } else { valid = (n < HW); q = n; c0 = k0; }
            uint32_t sz = valid ? 16u : 0u;
            const __nv_bfloat16* ah = act_h + ((size_t)b * HW + (valid ? q : 0)) * CI + c0 + u0 * 8;
            const __nv_bfloat16* al = act_l + ((size_t)b * HW + (valid ? q : 0)) * CI + c0 + u0 * 8;
            uint32_t dh = sbase + A_HI + prow * 80 + u0 * 16;
            uint32_t dl = sbase + A_LO + prow * 80 + u0 * 16;
            #pragma unroll
            for (int u = 0; u < 2; u++) {
                cpa16(dh + u * 16, ah + u * 8, sz);
                cpa16(dl + u * 16, al + u * 8, sz);
            }
        }
        // B (weights, 64 oc rows)
        {
            const __nv_bfloat16* wh = wt_h + (size_t)(n0g + brow2) * K + k0 + bu * 8;
            const __nv_bfloat16* wl = wt_l + (size_t)(n0g + brow2) * K + k0 + bu * 8;
            cpa16(sbase + B_HI + brow2 * 80 + bu * 16, wh, 16u);
            cpa16(sbase + B_LO + brow2 * 80 + bu * 16, wl, 16u);
        }
        cpa_commit();
    };

    float cacc[2][4][4];
    #pragma unroll
    for (int i = 0; i < 2; i++)
        #pragma unroll
        for (int j = 0; j < 4; j++)
            #pragma unroll
            for (int q = 0; q < 4; q++) cacc[i][j][q] = 0.f;

    const int wm = wid >> 1, wn = wid & 1;
    const int lr = lane & 7, s23 = lane >> 3;
    const int arow = (s23 & 1) * 8 + lr, acol = (s23 >> 1) * 8;
    const int brow = (s23 >> 1) * 8 + lr, bcol = (s23 & 1) * 8;

    constexpr int NC = K / 32;
    prefetch(0, 0);
    int buf = 0;
    for (int ch = 0; ch < NC; ch++) {
        cpa_wait<0>();
        __syncthreads();
        if (ch + 1 < NC) prefetch(ch + 1, buf ^ 1);

        const uint32_t sbb = sb + buf * STG;
        #pragma unroll
        for (int s = 0; s < 2; s++) {
            const int kb = s * 16;
            uint32_t ah[2][4], al[2][4];
            #pragma unroll
            for (int mi = 0; mi < 2; mi++) {
                uint32_t off = (uint32_t)((wm * 32 + mi * 16 + arow) * 80 + (kb + acol) * 2);
                ldsm4(ah[mi], sbb + A_HI + off);
                ldsm4(al[mi], sbb + A_LO + off);
            }
            #pragma unroll
            for (int np = 0; np < 2; np++) {
                uint32_t bh[4], bl[4];
                uint32_t off = (uint32_t)((wn * 32 + np * 16 + brow) * 80 + (kb + bcol) * 2);
                ldsm4(bh, sbb + B_HI + off);
                ldsm4(bl, sbb + B_LO + off);
                // pass-major ordering: each accumulator revisited at distance 4
                #pragma unroll
                for (int mi = 0; mi < 2; mi++) {
                    mma_bf(cacc[mi][np * 2],     ah[mi], bh[0], bh[1]);
                    mma_bf(cacc[mi][np * 2 + 1], ah[mi], bh[2], bh[3]);
                }
                #pragma unroll
                for (int mi = 0; mi < 2; mi++) {
                    mma_bf(cacc[mi][np * 2],     al[mi], bh[0], bh[1]);
                    mma_bf(cacc[mi][np * 2 + 1], al[mi], bh[2], bh[3]);
                }
                #pragma unroll
                for (int mi = 0; mi < 2; mi++) {
                    mma_bf(cacc[mi][np * 2],     ah[mi], bl[0], bl[1]);
                    mma_bf(cacc[mi][np * 2 + 1], ah[mi], bl[2], bl[3]);
                }
            }
        }
        buf ^= 1;
    }

    // ---- epilogue ----
    const int g = lane >> 2, tg = lane & 3;
    if (MODE != 3) {
        __nv_bfloat16* ohg = (MODE == 1 ? gh1_hi : gh2_hi);
        __nv_bfloat16* olg = (MODE == 1 ? gh1_lo : gh2_lo);
        float lsum[8];
        #pragma unroll
        for (int i = 0; i < 8; i++) lsum[i] = 0.f;
        #pragma unroll
        for (int mi = 0; mi < 2; mi++) {
            #pragma unroll
            for (int h = 0; h < 2; h++) {
                int pl = wm * 32 + mi * 16 + g + h * 8;
                int n  = m0 + pl;
                bool store = (MODE == 2) ? (n < cnt) : (n < HW);
                if (store) {
                    int p = (MODE == 2) ? pidx[pl] : n;
                    float pmx = pmv[pl];
                    size_t rowoff = ((size_t)b * HW + p) * WID;
                    #pragma unroll
                    for (int nf = 0; nf < 4; nf++) {
                        int ocl = wn * 32 + nf * 8 + tg * 2;
                        float v0 = fmaxf(cacc[mi][nf][h*2+0] + bb[ocl],   0.f) * cmb[ocl]   * pmx;
                        float v1 = fmaxf(cacc[mi][nf][h*2+1] + bb[ocl+1], 0.f) * cmb[ocl+1] * pmx;
                        lsum[nf*2 + 0] += v0;
                        lsum[nf*2 + 1] += v1;
                        __nv_bfloat16 h0 = __float2bfloat16(v0);
                        __nv_bfloat16 h1 = __float2bfloat16(v1);
                        __nv_bfloat162 hp; hp.x = h0; hp.y = h1;
                        *(__nv_bfloat162*)(ohg + rowoff + n0g + ocl) = hp;
                        __nv_bfloat162 lp;
                        lp.x = __float2bfloat16(v0 - __bfloat162float(h0));
                        lp.y = __float2bfloat16(v1 - __bfloat162float(h1));
                        *(__nv_bfloat162*)(olg + rowoff + n0g + ocl) = lp;
                    }
                }
            }
        }
        #pragma unroll
        for (int nf = 0; nf < 4; nf++) {
            int ocl = wn * 32 + nf * 8 + tg * 2;
            atomicAdd(&pool[ocl],     lsum[nf*2 + 0]);
            atomicAdd(&pool[ocl + 1], lsum[nf*2 + 1]);
        }
        __syncthreads();
        float* gpool = (MODE == 1) ? g_pool1 : g_pool2;
        if (tid < 64) atomicAdd(&gpool[b * WID + n0g + tid], pool[tid]);
    } else {
        float* tf = (float*)dsm;          // reuse: [64 oc][132 p] = 33.8KB
        __syncthreads();
        #pragma unroll
        for (int mi = 0; mi < 2; mi++)
            #pragma unroll
            for (int h = 0; h < 2; h++) {
                int pl = wm * 32 + mi * 16 + g + h * 8;
                float pmx = pmv[pl];
                #pragma unroll
                for (int nf = 0; nf < 4; nf++) {
                    int ocl = wn * 32 + nf * 8 + tg * 2;
                    tf[ocl * 132 + pl]       = (cacc[mi][nf][h*2+0] + bb[ocl])   * cmb[ocl]   * pmx;
                    tf[(ocl + 1) * 132 + pl] = (cacc[mi][nf][h*2+1] + bb[ocl+1]) * cmb[ocl+1] * pmx;
                }
            }
        __syncthreads();
        int ocl = tid >> 2, q = tid & 3;
        if (m0 + q * 32 < HW) {
            float* orow = xout + ((size_t)b * OUP + n0g + ocl) * HW + m0 + q * 32;
            const float* src = tf + ocl * 132 + q * 32;
            #pragma unroll
            for (int gi = 0; gi < 8; gi++)
                *(float4*)(orow + gi * 4) = *(const float4*)(src + gi * 4);
        }
    }
}

// ---------------------------------------------------------------------------
// kH: row/col means of h3 (in d_out) -> s_xh, s_xw (smem-staged)
// ---------------------------------------------------------------------------
__global__ __launch_bounds__(256) void kH_rowcol(const float* __restrict__ h3)
{
    __shared__ float img[HW];
    int bc = blockIdx.x;
    const float* src = h3 + (size_t)bc * HW;
    for (int i = threadIdx.x; i < HW; i += 256) img[i] = src[i];
    __syncthreads();
    int t = threadIdx.x;
    if (t < WW) {
        float s = 0.f;
        #pragma unroll 8
        for (int h = 0; h < HH; h++) s += img[h * WW + t];
        s_xw[bc * WW + t] = s * (1.f / HH);
    } else if (t >= 64 && t < 64 + HH) {
        int r = t - 64;
        float s = 0.f;
        #pragma unroll 8
        for (int w = 0; w < WW; w++) s += img[r * WW + w];
        s_xh[bc * HH + r] = s * (1.f / WW);
    }
}

// ---------------------------------------------------------------------------
// kI1: coord-att squeeze conv (512->16) + hswish -> g_ys.  grid (NB, 14).
// ---------------------------------------------------------------------------
__global__ __launch_bounds__(256) void kI1(const float* __restrict__ w1,
                                           const float* __restrict__ b1)
{
    __shared__ float w1s[MIP * OUP];            // 32KB
    const int b = blockIdx.x;
    const int t = threadIdx.x;
    for (int i = t; i < MIP * OUP; i += 256) w1s[i] = w1[i];
    __syncthreads();
    const int wid = t >> 5, lane = t & 31;
    const int ti = blockIdx.y * 8 + wid;        // 0..111
    const float* src = (ti < HH)
        ? (s_xh + (size_t)b * OUP * HH + ti)
        : (s_xw + (size_t)b * OUP * WW + (ti - HH));
    float acc[MIP];
    #pragma unroll
    for (int m = 0; m < MIP; m++) acc[m] = 0.f;
    #pragma unroll 4
    for (int cc = 0; cc < 16; cc++) {
        int c = cc * 32 + lane;
        float v = src[(size_t)c * HH];
        #pragma unroll
        for (int m = 0; m < MIP; m++) acc[m] += v * w1s[m * OUP + c];
    }
    #pragma unroll
    for (int off = 16; off > 0; off >>= 1)
        #pragma unroll
        for (int m = 0; m < MIP; m++) acc[m] += __shfl_xor_sync(0xffffffffu, acc[m], off);
    if (lane == 0) {
        #pragma unroll
        for (int m = 0; m < MIP; m++) {
            float u = acc[m] + b1[m];
            float r6 = fminf(fmaxf(u + 3.f, 0.f), 6.f);
            g_ys[((size_t)b * 2 * HH + ti) * MIP + m] = u * r6 * (1.f / 6.f);
        }
    }
}

// ---------------------------------------------------------------------------
// kI2: coord-att excite convs (16->512) + sigmoid -> s_ah, s_aw. grid (NB, 8).
// ---------------------------------------------------------------------------
__global__ __launch_bounds__(256) void kI2(const float* __restrict__ wh,
                                           const float* __restrict__ bh,
                                           const float* __restrict__ ww,
                                           const float* __restrict__ bw)
{
    __shared__ float ys[2 * HH * MIP];          // 7KB
    const int b  = blockIdx.x;
    const int c0 = blockIdx.y * 64;
    const int t  = threadIdx.x;
    for (int i = t; i < 2 * HH * MIP; i += 256) ys[i] = g_ys[(size_t)b * 2 * HH * MIP + i];
    __syncthreads();
    const int cl = t >> 2, jq = t & 3;
    const int c  = c0 + cl;
    float whr[MIP], wwr[MIP];
    #pragma unroll
    for (int m = 0; m < MIP; m++) { whr[m] = wh[c*MIP + m]; wwr[m] = ww[c*MIP + m]; }
    const float bhc = bh[c], bwc = bw[c];
    #pragma unroll 2
    for (int jj = 0; jj < 14; jj++) {
        int j = jq * 14 + jj;
        float sh = bhc, sw = bwc;
        #pragma unroll
        for (int m = 0; m < MIP; m++) {
            sh += ys[j * MIP + m]        * whr[m];
            sw += ys[(HH + j) * MIP + m] * wwr[m];
        }
        s_ah[((size_t)b * OUP + c) * HH + j] = 1.f / (1.f + expf(-sh));
        s_aw[((size_t)b * OUP + c) * WW + j] = 1.f / (1.f + expf(-sw));
    }
}

// ---------------------------------------------------------------------------
// final: out = relu(h3 * ah * aw + x), in place on d_out
// ---------------------------------------------------------------------------
__global__ void kJ_final(const float* __restrict__ x, float* __restrict__ out)
{
    size_t i = (size_t)blockIdx.x * blockDim.x + threadIdx.x;
    const size_t total4 = (size_t)NB * OUP * HW / 4;
    if (i >= total4) return;
    size_t e   = i * 4;
    size_t row = e / WW;
    int    w   = (int)(e - row * WW);
    size_t bc  = row / HH;
    float a_h  = s_ah[row];
    const float* awp = s_aw + bc * WW + w;
    float4 hv = *(float4*)(out + e);
    float4 xv = *(const float4*)(x + e);
    float4 r;
    r.x = fmaxf(hv.x * a_h * awp[0] + xv.x, 0.f);
    r.y = fmaxf(hv.y * a_h * awp[1] + xv.y, 0.f);
    r.z = fmaxf(hv.z * a_h * awp[2] + xv.z, 0.f);
    r.w = fmaxf(hv.w * a_h * awp[3] + xv.w, 0.f);
    *(float4*)(out + e) = r;
}

// ---------------------------------------------------------------------------
// Launch — only harness pointers cross the host/device boundary.
// ---------------------------------------------------------------------------
extern "C" void kernel_launch(void* const* d_in, const int* in_sizes, int n_in,
                              void* d_out, int out_size)
{
    const float* x     = (const float*)d_in[0];
    const float* sm_w  = (const float*)d_in[1];
    const float* sm_b  = (const float*)d_in[2];
    const float* cm1_w = (const float*)d_in[3];
    const float* cm1_b = (const float*)d_in[4];
    const float* cm2_w = (const float*)d_in[5];
    const float* cm2_b = (const float*)d_in[6];
    const float* cm3_w = (const float*)d_in[7];
    const float* cm3_b = (const float*)d_in[8];
    const float* w1    = (const float*)d_in[9];
    const float* b1    = (const float*)d_in[10];
    const float* w2    = (const float*)d_in[11];
    const float* b2    = (const float*)d_in[12];
    const float* w3    = (const float*)d_in[13];
    const float* b3    = (const float*)d_in[14];
    const float* ca_w1 = (const float*)d_in[15];
    const float* ca_b1 = (const float*)d_in[16];
    const float* ca_wh = (const float*)d_in[17];
    const float* ca_bh = (const float*)d_in[18];
    const float* ca_ww = (const float*)d_in[19];
    const float* ca_bw = (const float*)d_in[20];
    float* out = (float*)d_out;

    cudaFuncSetAttribute(conv_mma<1, WID, CIN,  CIN>, cudaFuncAttributeMaxDynamicSharedMemorySize, CONV_DSM);
    cudaFuncSetAttribute(conv_mma<2, WID, 1152, WID>, cudaFuncAttributeMaxDynamicSharedMemorySize, CONV_DSM);
    cudaFuncSetAttribute(conv_mma<3, OUP, WID,  WID>, cudaFuncAttributeMaxDynamicSharedMemorySize, CONV_DSM);

    kZ_zero<<<(NB*HW + 255)/256, 256>>>();
    kT_transx<<<dim3(HW/64, CIN/64, NB), 256>>>(x, sm_w);
    kW_split<1><<<(WID*CIN  + 255)/256, 256>>>(w1);
    kB_dilate<<<dim3(NB, 7), 256>>>(sm_b);
    kL_list<<<NB, 256>>>();
    kD_cmask<1><<<dim3(NB, WID/64), 256>>>(cm1_w, cm1_b);

    conv_mma<1, WID, CIN, CIN><<<dim3(25, 2, NB), 256, CONV_DSM>>>(b1, out);

    kW_split<2><<<(WID*1152 + 255)/256, 256>>>(w2);
    kD_cmask<2><<<dim3(NB, WID/64), 256>>>(cm2_w, cm2_b);

    conv_mma<2, WID, 1152, WID><<<dim3(25, 2, NB), 256, CONV_DSM>>>(b2, out);

    kW_split<3><<<(OUP*WID  + 255)/256, 256>>>(w3);
    kD_cmask<3><<<dim3(NB, OUP/64), 256>>>(cm3_w, cm3_b);

    conv_mma<3, OUP, WID, WID><<<dim3(25, 8, NB), 256, CONV_DSM>>>(b3, out);

    kH_rowcol<<<NB * OUP, 256>>>(out);
    kI1<<<dim3(NB, 14), 256>>>(ca_w1, ca_b1);
    kI2<<<dim3(NB, 8),  256>>>(ca_wh, ca_bh, ca_ww, ca_bw);

    {
        size_t total4 = (size_t)NB * OUP * HW / 4;
        kJ_final<<<(unsigned)((total4 + 255) / 256), 256>>>(x, out);
    }
}

// round 15
// speedup vs baseline: 8.6216x; 1.0404x over previous
#include <cuda_runtime.h>
#include <cuda_bf16.h>
#include <math.h>
#include <stdint.h>

// ---------------------------------------------------------------------------
#define NB   16
#define CIN  512
#define WID  128
#define OUP  512
#define HH   56
#define WW   56
#define HW   (HH*WW)
#define MIP  16

union U8 { __nv_bfloat16 h[8]; uint4 u; };

__device__ __forceinline__ uint32_t smem_u32(const void* p) {
    uint32_t a;
    asm("{ .reg .u64 t; cvta.to.shared.u64 t, %1; cvt.u32.u64 %0, t; }" : "=r"(a) : "l"(p));
    return a;
}
__device__ __forceinline__ void ldsm4(uint32_t* r, uint32_t a) {
    asm volatile("ldmatrix.sync.aligned.m8n8.x4.shared.b16 {%0,%1,%2,%3}, [%4];"
                 : "=r"(r[0]), "=r"(r[1]), "=r"(r[2]), "=r"(r[3]) : "r"(a));
}
__device__ __forceinline__ void mma_bf(float* c, const uint32_t* a, uint32_t b0, uint32_t b1) {
    asm volatile("mma.sync.aligned.m16n8k16.row.col.f32.bf16.bf16.f32 "
                 "{%0,%1,%2,%3}, {%4,%5,%6,%7}, {%8,%9}, {%0,%1,%2,%3};"
                 : "+f"(c[0]), "+f"(c[1]), "+f"(c[2]), "+f"(c[3])
                 : "r"(a[0]), "r"(a[1]), "r"(a[2]), "r"(a[3]), "r"(b0), "r"(b1));
}
__device__ __forceinline__ void cpa16(uint32_t d, const void* s, uint32_t srcsz) {
    asm volatile("cp.async.cg.shared.global [%0], [%1], 16, %2;"
                 :: "r"(d), "l"(s), "r"(srcsz) : "memory");
}
__device__ __forceinline__ void cpa_commit() { asm volatile("cp.async.commit_group;" ::: "memory"); }
template<int N> __device__ __forceinline__ void cpa_wait() {
    asm volatile("cp.async.wait_group %0;" :: "n"(N) : "memory");
}

// ---------------------------------------------------------------------------
// Scratch — __device__ globals, referenced ONLY inside device code.
// gh1/gh2 DENSE [b][p][128]; unlisted channels stay zero (never written).
// ---------------------------------------------------------------------------
__device__ __align__(128) __nv_bfloat16 gx_hi [NB*HW*CIN];
__device__ __align__(128) __nv_bfloat16 gx_lo [NB*HW*CIN];
__device__ __align__(128) __nv_bfloat16 gh1_hi[NB*HW*WID];
__device__ __align__(128) __nv_bfloat16 gh1_lo[NB*HW*WID];
__device__ __align__(128) __nv_bfloat16 gh2_hi[NB*HW*WID];
__device__ __align__(128) __nv_bfloat16 gh2_lo[NB*HW*WID];
__device__ __align__(128) __nv_bfloat16 gw1h[WID*CIN],  gw1l[WID*CIN];
__device__ __align__(128) __nv_bfloat16 gw2h[WID*1152], gw2l[WID*1152];
__device__ __align__(128) __nv_bfloat16 gw3h[OUP*WID],  gw3l[OUP*WID];
__device__ __align__(16) float g_smlog[NB*HW];
__device__ __align__(16) float g_poolx[NB*CIN];
__device__ __align__(16) float g_pool1[NB*WID];
__device__ __align__(16) float g_pool2[NB*WID];
__device__ __align__(16) float g_ys   [NB*2*HH*MIP];
__device__ __align__(16) int   g_idx  [NB*HW];
__device__ __align__(16) int   g_cnt  [NB];
__device__ __align__(16) int   g_ocl1 [NB*WID];
__device__ __align__(16) int   g_ocl3 [NB*OUP];
__device__ __align__(16) int   g_occ1 [NB];
__device__ __align__(16) int   g_occ3 [NB];
__device__ __align__(16) float s_sm [NB*HW];
__device__ __align__(16) float s_smd[NB*HW];
__device__ __align__(16) float s_c1 [NB*WID];
__device__ __align__(16) float s_c2 [NB*WID];
__device__ __align__(16) float s_c3 [NB*OUP];
__device__ __align__(16) float s_xh [NB*OUP*HH];
__device__ __align__(16) float s_xw [NB*OUP*WW];
__device__ __align__(16) float s_ah [NB*OUP*HH];
__device__ __align__(16) float s_aw [NB*OUP*WW];

// ---------------------------------------------------------------------------
__global__ void kZ_zero()
{
    int i = blockIdx.x * 256 + threadIdx.x;
    if (i < NB*HW)  g_smlog[i] = 0.f;
    if (i < NB*CIN) g_poolx[i] = 0.f;
    if (i < NB*WID) { g_pool1[i] = 0.f; g_pool2[i] = 0.f; }
}

// ---------------------------------------------------------------------------
// kT: transpose + bf16-split x -> gx [b,p,c] + fused smask-logit/channel sums
// ---------------------------------------------------------------------------
__global__ __launch_bounds__(256) void kT_transx(const float* __restrict__ x,
                                                 const float* __restrict__ smw)
{
    __shared__ float ts[64][65];
    __shared__ float wsh[64];
    __shared__ float red[4][64];
    const int b  = blockIdx.z;
    const int c0 = blockIdx.y * 64;
    const int p0 = blockIdx.x * 64;
    const int t  = threadIdx.x;

    if (t < 64) wsh[t] = smw[c0 + t];
    {
        int ci = t >> 2, jg = (t & 3) * 16;
        const float* src = x + ((size_t)b * CIN + c0 + ci) * HW + p0 + jg;
        #pragma unroll
        for (int q = 0; q < 4; q++) {
            float4 f = *(const float4*)(src + q * 4);
            ts[ci][jg + q*4 + 0] = f.x; ts[ci][jg + q*4 + 1] = f.y;
            ts[ci][jg + q*4 + 2] = f.z; ts[ci][jg + q*4 + 3] = f.w;
        }
    }
    __syncthreads();
    {
        int g = t >> 6, pi = t & 63;
        float s = 0.f;
        #pragma unroll
        for (int cc = 0; cc < 16; cc++) s += ts[g*16 + cc][pi] * wsh[g*16 + cc];
        red[g][pi] = s;
    }
    __syncthreads();
    if (t < 64)
        atomicAdd(&g_smlog[b * HW + p0 + t], red[0][t] + red[1][t] + red[2][t] + red[3][t]);
    __syncthreads();
    {
        int c = t & 63, pg = t >> 6;
        float s = 0.f;
        #pragma unroll
        for (int i = 0; i < 16; i++) s += ts[c][pg*16 + i];
        red[pg][c] = s;
    }
    __syncthreads();
    if (t < 64)
        atomicAdd(&g_poolx[b * CIN + c0 + t], red[0][t] + red[1][t] + red[2][t] + red[3][t]);
    {
        int pi = t >> 2, cg = (t & 3) * 16;
        __nv_bfloat16* oh = gx_hi + ((size_t)b * HW + p0 + pi) * CIN + c0 + cg;
        __nv_bfloat16* ol = gx_lo + ((size_t)b * HW + p0 + pi) * CIN + c0 + cg;
        #pragma unroll
        for (int g = 0; g < 2; g++) {
            U8 hh, ll;
            #pragma unroll
            for (int j = 0; j < 8; j++) {
                float v = ts[cg + g*8 + j][pi];
                __nv_bfloat16 h = __float2bfloat16(v);
                hh.h[j] = h;
                ll.h[j] = __float2bfloat16(v - __bfloat162float(h));
            }
            *(uint4*)(oh + g*8) = hh.u;
            *(uint4*)(ol + g*8) = ll.u;
        }
    }
}

// ---------------------------------------------------------------------------
// kW: weight fp32 -> split bf16 (+ conv2 reorder k = r*128+c from [o][c*9+r])
// ---------------------------------------------------------------------------
template<int MODE>
__global__ void kW_split(const float* __restrict__ W)
{
    constexpr int M = (MODE == 3) ? OUP : WID;
    constexpr int K = (MODE == 1) ? CIN : ((MODE == 2) ? 1152 : WID);
    __nv_bfloat16* oh = (MODE == 1) ? gw1h : (MODE == 2 ? gw2h : gw3h);
    __nv_bfloat16* ol = (MODE == 1) ? gw1l : (MODE == 2 ? gw2l : gw3l);
    int i = blockIdx.x * 256 + threadIdx.x;
    if (i >= M * K) return;
    int o = i / K, k = i - o * K;
    float v;
    if (MODE == 2) {
        int r = k >> 7, c = k & 127;
        v = W[(size_t)o * 1152 + c * 9 + r];
    } else v = W[i];
    __nv_bfloat16 h = __float2bfloat16(v);
    oh[i] = h;
    ol[i] = __float2bfloat16(v - __bfloat162float(h));
}

// ---------------------------------------------------------------------------
// kB: threshold smask logits + 3x3 dilation.  grid (NB, 7).
// ---------------------------------------------------------------------------
__global__ __launch_bounds__(256) void kB_dilate(const float* __restrict__ smb)
{
    __shared__ float s[10][WW];
    int b  = blockIdx.x;
    int r0 = blockIdx.y * 8;
    float sb0 = smb[0];
    for (int i = threadIdx.x; i < 10 * WW; i += 256) {
        int rr = i / WW, cc = i - rr * WW;
        int gr = r0 + rr - 1;
        float m = 0.f;
        if (gr >= 0 && gr < HH)
            m = (g_smlog[b*HW + gr*WW + cc] + sb0) > 0.f ? 1.f : 0.f;
        s[rr][cc] = m;
    }
    __syncthreads();
    for (int i = threadIdx.x; i < 8 * WW; i += 256) {
        int rr = i / WW, cc = i - rr * WW;
        s_sm[b*HW + (r0+rr)*WW + cc] = s[rr+1][cc];
        float m = 0.f;
        #pragma unroll
        for (int dy = 0; dy < 3; dy++) {
            #pragma unroll
            for (int dx = -1; dx <= 1; dx++) {
                int xx = cc + dx; if (xx < 0 || xx >= WW) continue;
                m = fmaxf(m, s[rr+dy][xx]);
            }
        }
        s_smd[b*HW + (r0+rr)*WW + cc] = m;
    }
}

// ---------------------------------------------------------------------------
// Ordered ballot compaction: pixels (kL_list) and channels (kLc<S>, S=1|3).
// ---------------------------------------------------------------------------
__global__ __launch_bounds__(256) void kL_list()
{
    __shared__ int wsum[8], wbase[8], total;
    const int b = blockIdx.x, t = threadIdx.x;
    const int wrp = t >> 5, lane = t & 31;
    if (t == 0) total = 0;
    __syncthreads();
    for (int i0 = 0; i0 < HW; i0 += 256) {
        int i = i0 + t;
        int f = (i < HW) ? (s_sm[b*HW + i] > 0.5f ? 1 : 0) : 0;
        unsigned bal = __ballot_sync(0xffffffffu, f);
        int wp = __popc(bal & ((1u << lane) - 1u));
        if (lane == 0) wsum[wrp] = __popc(bal);
        __syncthreads();
        if (t == 0) {
            int acc = total;
            #pragma unroll
            for (int w = 0; w < 8; w++) { wbase[w] = acc; acc += wsum[w]; }
            total = acc;
        }
        __syncthreads();
        if (f) g_idx[b*HW + wbase[wrp] + wp] = i;
        __syncthreads();
    }
    if (t == 0) g_cnt[b] = total;
}

template<int STAGE>
__global__ __launch_bounds__(256) void kLc()
{
    constexpr int CO = (STAGE == 3) ? OUP : WID;
    const float* mask = (STAGE == 1) ? s_c1 : s_c3;
    int* list = (STAGE == 1) ? g_ocl1 : g_ocl3;
    int* cnto = (STAGE == 1) ? g_occ1 : g_occ3;
    __shared__ int wsum[8], wbase[8], total;
    const int b = blockIdx.x, t = threadIdx.x;
    const int wrp = t >> 5, lane = t & 31;
    if (t == 0) total = 0;
    __syncthreads();
    for (int i0 = 0; i0 < CO; i0 += 256) {
        int i = i0 + t;
        int f = (i < CO) ? (mask[b*CO + i] > 0.5f ? 1 : 0) : 0;
        unsigned bal = __ballot_sync(0xffffffffu, f);
        int wp = __popc(bal & ((1u << lane) - 1u));
        if (lane == 0) wsum[wrp] = __popc(bal);
        __syncthreads();
        if (t == 0) {
            int acc = total;
            #pragma unroll
            for (int w = 0; w < 8; w++) { wbase[w] = acc; acc += wsum[w]; }
            total = acc;
        }
        __syncthreads();
        if (f) list[b*CO + wbase[wrp] + wp] = i;
        __syncthreads();
    }
    if (t == 0) cnto[b] = total;
}

// ---------------------------------------------------------------------------
// kD: channel mask from accumulated sums.  grid (NB, CO/64).
// ---------------------------------------------------------------------------
template<int STAGE>
__global__ __launch_bounds__(256) void kD_cmask(const float* __restrict__ w,
                                                const float* __restrict__ bias)
{
    constexpr int CI = (STAGE == 1) ? CIN : WID;
    constexpr int CO = (STAGE == 3) ? OUP : WID;
    const float* psum = (STAGE == 1) ? g_poolx : (STAGE == 2 ? g_pool1 : g_pool2);
    float*       mask = (STAGE == 1) ? s_c1 : (STAGE == 2 ? s_c2 : s_c3);
    int b  = blockIdx.x;
    int o0 = blockIdx.y * 64;
    __shared__ float pr[CI];
    for (int i = threadIdx.x; i < CI; i += 256)
        pr[i] = psum[b*CI + i] * (1.f / HW);
    __syncthreads();
    int wrp = threadIdx.x >> 5, lane = threadIdx.x & 31;
    #pragma unroll
    for (int i = 0; i < 8; i++) {
        int o = o0 + wrp * 8 + i;
        const float* wr = w + (size_t)o * CI;
        float s = 0.f;
        #pragma unroll 4
        for (int c = lane; c < CI; c += 32) s += pr[c] * wr[c];
        #pragma unroll
        for (int off = 16; off > 0; off >>= 1) s += __shfl_xor_sync(0xffffffffu, s, off);
        if (lane == 0) mask[b*CO + o] = (s + bias[o]) > 0.f ? 1.f : 0.f;
    }
}

// ---------------------------------------------------------------------------
// conv_mma: bf16-split GEMM, cp.async double-buffered, one barrier per chunk.
// Tile 128px x 64oc, K chunk 32, 2 stages -> 3 CTAs/SM.
// MODE 1: conv1 K=512, M-compacted by list1, DENSE gh1 scatter stores; pm=smd
// MODE 2: conv2 K=1152, pixel-compacted, dense oc + cm2 (round-12 exact)
// MODE 3: conv3 K=128,  M-compacted by list3 -> d_out rows list3; pm=s_sm
// ---------------------------------------------------------------------------
#define A_HI 0
#define A_LO 10240
#define B_HI 20480
#define B_LO 25600
#define STG  30720
#define CONV_DSM (2*STG)

template<int MODE, int NOC, int K, int CI>
__global__ __launch_bounds__(256, 3)
void conv_mma(const float* __restrict__ bias, float* __restrict__ xout)
{
    extern __shared__ char dsm[];
    const uint32_t sb = smem_u32(dsm);
    __shared__ float pmv[128], cmb[64], bb[64];
    __shared__ float pool[64];
    __shared__ int   pidx[128];
    __shared__ int   ocl_s[64];

    const int tid  = threadIdx.x;
    const int wid  = tid >> 5;
    const int lane = tid & 31;
    const int b    = blockIdx.z;
    const int m0   = blockIdx.x * 128;
    const int n0g  = blockIdx.y * 64;

    const int ocnt = (MODE == 1) ? g_occ1[b] : (MODE == 3 ? g_occ3[b] : NOC);
    if (n0g >= ocnt) return;
    const int cntpx = (MODE == 2) ? g_cnt[b] : HW;
    if (MODE == 2 && m0 >= cntpx) return;

    const __nv_bfloat16* act_h = (MODE == 1) ? gx_hi : (MODE == 2 ? gh1_hi : gh2_hi);
    const __nv_bfloat16* act_l = (MODE == 1) ? gx_lo : (MODE == 2 ? gh1_lo : gh2_lo);
    const __nv_bfloat16* wt_h  = (MODE == 1) ? gw1h : (MODE == 2 ? gw2h : gw3h);
    const __nv_bfloat16* wt_l  = (MODE == 1) ? gw1l : (MODE == 2 ? gw2l : gw3l);

    if (tid < 128) {
        int n = m0 + tid;
        if (MODE == 2) {
            pidx[tid] = (n < cntpx) ? g_idx[b * HW + n] : 0;
            pmv[tid]  = 1.f;
        } else {
            const float* pm = (MODE == 1) ? s_smd : s_sm;
            pmv[tid] = (n < HW) ? pm[b * HW + n] : 0.f;
        }
    }
    if (tid < 64) {
        if (MODE == 2) {
            cmb[tid] = s_c2[b * WID + n0g + tid];
            bb[tid]  = bias[n0g + tid];
            ocl_s[tid] = n0g + tid;
        } else {
            int oc = n0g + tid;
            bool v = (oc < ocnt);
            const int* list = (MODE == 1) ? g_ocl1 : g_ocl3;
            int tc = v ? list[b * ((MODE == 3) ? OUP : WID) + oc] : 0;
            ocl_s[tid] = tc;
            bb[tid]  = v ? bias[tc] : 0.f;
            cmb[tid] = v ? 1.f : 0.f;
        }
        pool[tid] = 0.f;
    }
    __syncthreads();

    const int prow = tid >> 1;
    const int u0   = (tid & 1) * 2;
    const int brow2 = tid >> 2;
    const int bu    = tid & 3;

    auto prefetch = [&](int ch, int st) {
        const uint32_t sbase = sb + st * STG;
        const int k0 = ch * 32;
        // A
        {
            int n = m0 + prow;
            bool valid; int q, c0;
            if (MODE == 2) {
                bool vrow = (n < cntpx);
                int p = vrow ? pidx[prow] : 0;
                int r  = ch >> 2;
                int ky = r / 3 - 1, kx = r % 3 - 1;
                int py = p / WW, px = p - py * WW;
                int iy = py + ky, ix = px + kx;
                valid = vrow && iy >= 0 && iy < HH && ix >= 0 && ix < WW;
                q = iy * WW + ix;
                c0 = (ch & 3) * 32;
            } else { valid = (n < HW); q = n; c0 = k0; }
            uint32_t sz = valid ? 16u : 0u;
            const __nv_bfloat16* ah = act_h + ((size_t)b * HW + (valid ? q : 0)) * CI + c0 + u0 * 8;
            const __nv_bfloat16* al = act_l + ((size_t)b * HW + (valid ? q : 0)) * CI + c0 + u0 * 8;
            uint32_t dh = sbase + A_HI + prow * 80 + u0 * 16;
            uint32_t dl = sbase + A_LO + prow * 80 + u0 * 16;
            #pragma unroll
            for (int u = 0; u < 2; u++) {
                cpa16(dh + u * 16, ah + u * 8, sz);
                cpa16(dl + u * 16, al + u * 8, sz);
            }
        }
        // B (weights; MODE 1/3 gather rows by original channel via list)
        {
            size_t rowoff;
            if (MODE == 2) rowoff = (size_t)(n0g + brow2) * K;
            else           rowoff = (size_t)ocl_s[brow2] * K;
            cpa16(sbase + B_HI + brow2 * 80 + bu * 16, wt_h + rowoff + k0 + bu * 8, 16u);
            cpa16(sbase + B_LO + brow2 * 80 + bu * 16, wt_l + rowoff + k0 + bu * 8, 16u);
        }
        cpa_commit();
    };

    float cacc[2][4][4];
    #pragma unroll
    for (int i = 0; i < 2; i++)
        #pragma unroll
        for (int j = 0; j < 4; j++)
            #pragma unroll
            for (int q = 0; q < 4; q++) cacc[i][j][q] = 0.f;

    const int wm = wid >> 1, wn = wid & 1;
    const int lr = lane & 7, s23 = lane >> 3;
    const int arow = (s23 & 1) * 8 + lr, acol = (s23 >> 1) * 8;
    const int brow = (s23 >> 1) * 8 + lr, bcol = (s23 & 1) * 8;

    constexpr int NC = K / 32;
    prefetch(0, 0);
    int buf = 0;
    for (int ch = 0; ch < NC; ch++) {
        cpa_wait<0>();
        __syncthreads();
        if (ch + 1 < NC) prefetch(ch + 1, buf ^ 1);

        const uint32_t sbb = sb + buf * STG;
        #pragma unroll
        for (int s = 0; s < 2; s++) {
            const int kb = s * 16;
            uint32_t ah[2][4], al[2][4];
            #pragma unroll
            for (int mi = 0; mi < 2; mi++) {
                uint32_t off = (uint32_t)((wm * 32 + mi * 16 + arow) * 80 + (kb + acol) * 2);
                ldsm4(ah[mi], sbb + A_HI + off);
                ldsm4(al[mi], sbb + A_LO + off);
            }
            #pragma unroll
            for (int np = 0; np < 2; np++) {
                uint32_t bh[4], bl[4];
                uint32_t off = (uint32_t)((wn * 32 + np * 16 + brow) * 80 + (kb + bcol) * 2);
                ldsm4(bh, sbb + B_HI + off);
                ldsm4(bl, sbb + B_LO + off);
                #pragma unroll
                for (int mi = 0; mi < 2; mi++) {
                    mma_bf(cacc[mi][np * 2],     ah[mi], bh[0], bh[1]);
                    mma_bf(cacc[mi][np * 2 + 1], ah[mi], bh[2], bh[3]);
                }
                #pragma unroll
                for (int mi = 0; mi < 2; mi++) {
                    mma_bf(cacc[mi][np * 2],     al[mi], bh[0], bh[1]);
                    mma_bf(cacc[mi][np * 2 + 1], al[mi], bh[2], bh[3]);
                }
                #pragma unroll
                for (int mi = 0; mi < 2; mi++) {
                    mma_bf(cacc[mi][np * 2],     ah[mi], bl[0], bl[1]);
                    mma_bf(cacc[mi][np * 2 + 1], ah[mi], bl[2], bl[3]);
                }
            }
        }
        buf ^= 1;
    }

    // ---- epilogue ----
    const int g = lane >> 2, tg = lane & 3;
    if (MODE != 3) {
        __nv_bfloat16* ohg = (MODE == 1 ? gh1_hi : gh2_hi);
        __nv_bfloat16* olg = (MODE == 1 ? gh1_lo : gh2_lo);
        float lsum[8];
        #pragma unroll
        for (int i = 0; i < 8; i++) lsum[i] = 0.f;
        #pragma unroll
        for (int mi = 0; mi < 2; mi++) {
            #pragma unroll
            for (int h = 0; h < 2; h++) {
                int pl = wm * 32 + mi * 16 + g + h * 8;
                int n  = m0 + pl;
                bool store = (MODE == 2) ? (n < cntpx) : (n < HW);
                if (store) {
                    int p = (MODE == 2) ? pidx[pl] : n;
                    float pmx = pmv[pl];
                    size_t rowoff = ((size_t)b * HW + p) * WID;   // DENSE stride
                    #pragma unroll
                    for (int nf = 0; nf < 4; nf++) {
                        int ocl = wn * 32 + nf * 8 + tg * 2;
                        float v0 = fmaxf(cacc[mi][nf][h*2+0] + bb[ocl],   0.f) * cmb[ocl]   * pmx;
                        float v1 = fmaxf(cacc[mi][nf][h*2+1] + bb[ocl+1], 0.f) * cmb[ocl+1] * pmx;
                        lsum[nf*2 + 0] += v0;
                        lsum[nf*2 + 1] += v1;
                        if (MODE == 2) {
                            __nv_bfloat16 h0 = __float2bfloat16(v0);
                            __nv_bfloat16 h1 = __float2bfloat16(v1);
                            __nv_bfloat162 hp; hp.x = h0; hp.y = h1;
                            *(__nv_bfloat162*)(ohg + rowoff + n0g + ocl) = hp;
                            __nv_bfloat162 lp;
                            lp.x = __float2bfloat16(v0 - __bfloat162float(h0));
                            lp.y = __float2bfloat16(v1 - __bfloat162float(h1));
                            *(__nv_bfloat162*)(olg + rowoff + n0g + ocl) = lp;
                        } else {
                            // MODE 1: scatter to original channel positions
                            if (n0g + ocl < ocnt) {
                                int c = ocl_s[ocl];
                                __nv_bfloat16 h0 = __float2bfloat16(v0);
                                ohg[rowoff + c] = h0;
                                olg[rowoff + c] = __float2bfloat16(v0 - __bfloat162float(h0));
                            }
                            if (n0g + ocl + 1 < ocnt) {
                                int c = ocl_s[ocl + 1];
                                __nv_bfloat16 h1 = __float2bfloat16(v1);
                                ohg[rowoff + c] = h1;
                                olg[rowoff + c] = __float2bfloat16(v1 - __bfloat162float(h1));
                            }
                        }
                    }
                }
            }
        }
        #pragma unroll
        for (int nf = 0; nf < 4; nf++) {
            int ocl = wn * 32 + nf * 8 + tg * 2;
            atomicAdd(&pool[ocl],     lsum[nf*2 + 0]);
            atomicAdd(&pool[ocl + 1], lsum[nf*2 + 1]);
        }
        __syncthreads();
        if (MODE == 2) {
            if (tid < 64) atomicAdd(&g_pool2[b * WID + n0g + tid], pool[tid]);
        } else {
            if (tid < 64 && n0g + tid < ocnt)
                atomicAdd(&g_pool1[b * WID + ocl_s[tid]], pool[tid]);
        }
    } else {
        float* tf = (float*)dsm;
        __syncthreads();
        #pragma unroll
        for (int mi = 0; mi < 2; mi++)
            #pragma unroll
            for (int h = 0; h < 2; h++) {
                int pl = wm * 32 + mi * 16 + g + h * 8;
                float pmx = pmv[pl];
                #pragma unroll
                for (int nf = 0; nf < 4; nf++) {
                    int ocl = wn * 32 + nf * 8 + tg * 2;
                    tf[ocl * 132 + pl]       = (cacc[mi][nf][h*2+0] + bb[ocl])   * cmb[ocl]   * pmx;
                    tf[(ocl + 1) * 132 + pl] = (cacc[mi][nf][h*2+1] + bb[ocl+1]) * cmb[ocl+1] * pmx;
                }
            }
        __syncthreads();
        int ocl = tid >> 2, q = tid & 3;
        if (n0g + ocl < ocnt && m0 + q * 32 < HW) {
            float* orow = xout + ((size_t)b * OUP + ocl_s[ocl]) * HW + m0 + q * 32;
            const float* src = tf + ocl * 132 + q * 32;
            #pragma unroll
            for (int gi = 0; gi < 8; gi++)
                *(float4*)(orow + gi * 4) = *(const float4*)(src + gi * 4);
        }
    }
}

// ---------------------------------------------------------------------------
// kH: row/col means; cm3=0 rows are zero without touching d_out (unwritten).
// ---------------------------------------------------------------------------
__global__ __launch_bounds__(256) void kH_rowcol(const float* __restrict__ h3)
{
    __shared__ float img[HW];
    int bc = blockIdx.x;
    int t = threadIdx.x;
    if (s_c3[bc] < 0.5f) {
        if (t < WW) s_xw[bc * WW + t] = 0.f;
        if (t >= 64 && t < 64 + HH) s_xh[bc * HH + t - 64] = 0.f;
        return;
    }
    const float* src = h3 + (size_t)bc * HW;
    for (int i = t; i < HW; i += 256) img[i] = src[i];
    __syncthreads();
    if (t < WW) {
        float s = 0.f;
        #pragma unroll 8
        for (int h = 0; h < HH; h++) s += img[h * WW + t];
        s_xw[bc * WW + t] = s * (1.f / HH);
    } else if (t >= 64 && t < 64 + HH) {
        int r = t - 64;
        float s = 0.f;
        #pragma unroll 8
        for (int w = 0; w < WW; w++) s += img[r * WW + w];
        s_xh[bc * HH + r] = s * (1.f / WW);
    }
}

// ---------------------------------------------------------------------------
__global__ __launch_bounds__(256) void kI1(const float* __restrict__ w1,
                                           const float* __restrict__ b1)
{
    __shared__ float w1s[MIP * OUP];
    const int b = blockIdx.x;
    const int t = threadIdx.x;
    for (int i = t; i < MIP * OUP; i += 256) w1s[i] = w1[i];
    __syncthreads();
    const int wid = t >> 5, lane = t & 31;
    const int ti = blockIdx.y * 8 + wid;
    const float* src = (ti < HH)
        ? (s_xh + (size_t)b * OUP * HH + ti)
        : (s_xw + (size_t)b * OUP * WW + (ti - HH));
    float acc[MIP];
    #pragma unroll
    for (int m = 0; m < MIP; m++) acc[m] = 0.f;
    #pragma unroll 4
    for (int cc = 0; cc < 16; cc++) {
        int c = cc * 32 + lane;
        float v = src[(size_t)c * HH];
        #pragma unroll
        for (int m = 0; m < MIP; m++) acc[m] += v * w1s[m * OUP + c];
    }
    #pragma unroll
    for (int off = 16; off > 0; off >>= 1)
        #pragma unroll
        for (int m = 0; m < MIP; m++) acc[m] += __shfl_xor_sync(0xffffffffu, acc[m], off);
    if (lane == 0) {
        #pragma unroll
        for (int m = 0; m < MIP; m++) {
            float u = acc[m] + b1[m];
            float r6 = fminf(fmaxf(u + 3.f, 0.f), 6.f);
            g_ys[((size_t)b * 2 * HH + ti) * MIP + m] = u * r6 * (1.f / 6.f);
        }
    }
}

__global__ __launch_bounds__(256) void kI2(const float* __restrict__ wh,
                                           const float* __restrict__ bh,
                                           const float* __restrict__ ww,
                                           const float* __restrict__ bw)
{
    __shared__ float ys[2 * HH * MIP];
    const int b  = blockIdx.x;
    const int c0 = blockIdx.y * 64;
    const int t  = threadIdx.x;
    for (int i = t; i < 2 * HH * MIP; i += 256) ys[i] = g_ys[(size_t)b * 2 * HH * MIP + i];
    __syncthreads();
    const int cl = t >> 2, jq = t & 3;
    const int c  = c0 + cl;
    float whr[MIP], wwr[MIP];
    #pragma unroll
    for (int m = 0; m < MIP; m++) { whr[m] = wh[c*MIP + m]; wwr[m] = ww[c*MIP + m]; }
    const float bhc = bh[c], bwc = bw[c];
    #pragma unroll 2
    for (int jj = 0; jj < 14; jj++) {
        int j = jq * 14 + jj;
        float sh = bhc, sw = bwc;
        #pragma unroll
        for (int m = 0; m < MIP; m++) {
            sh += ys[j * MIP + m]        * whr[m];
            sw += ys[(HH + j) * MIP + m] * wwr[m];
        }
        s_ah[((size_t)b * OUP + c) * HH + j] = 1.f / (1.f + expf(-sh));
        s_aw[((size_t)b * OUP + c) * WW + j] = 1.f / (1.f + expf(-sw));
    }
}

// ---------------------------------------------------------------------------
// kJ: out = relu(h3*m3*ah*aw + x); m3 masks rows conv3 never wrote (poison).
// ---------------------------------------------------------------------------
__global__ void kJ_final(const float* __restrict__ x, float* __restrict__ out)
{
    size_t i = (size_t)blockIdx.x * blockDim.x + threadIdx.x;
    const size_t total4 = (size_t)NB * OUP * HW / 4;
    if (i >= total4) return;
    size_t e   = i * 4;
    size_t row = e / WW;
    int    w   = (int)(e - row * WW);
    size_t bc  = row / HH;
    float m3   = s_c3[bc];
    float a_h  = s_ah[row] * m3;
    const float* awp = s_aw + bc * WW + w;
    float4 hv = *(float4*)(out + e);
    float4 xv = *(const float4*)(x + e);
    float4 r;
    r.x = fmaxf(hv.x * a_h * awp[0] + xv.x, 0.f);
    r.y = fmaxf(hv.y * a_h * awp[1] + xv.y, 0.f);
    r.z = fmaxf(hv.z * a_h * awp[2] + xv.z, 0.f);
    r.w = fmaxf(hv.w * a_h * awp[3] + xv.w, 0.f);
    *(float4*)(out + e) = r;
}

// ---------------------------------------------------------------------------
extern "C" void kernel_launch(void* const* d_in, const int* in_sizes, int n_in,
                              void* d_out, int out_size)
{
    const float* x     = (const float*)d_in[0];
    const float* sm_w  = (const float*)d_in[1];
    const float* sm_b  = (const float*)d_in[2];
    const float* cm1_w = (const float*)d_in[3];
    const float* cm1_b = (const float*)d_in[4];
    const float* cm2_w = (const float*)d_in[5];
    const float* cm2_b = (const float*)d_in[6];
    const float* cm3_w = (const float*)d_in[7];
    const float* cm3_b = (const float*)d_in[8];
    const float* w1    = (const float*)d_in[9];
    const float* b1    = (const float*)d_in[10];
    const float* w2    = (const float*)d_in[11];
    const float* b2    = (const float*)d_in[12];
    const float* w3    = (const float*)d_in[13];
    const float* b3    = (const float*)d_in[14];
    const float* ca_w1 = (const float*)d_in[15];
    const float* ca_b1 = (const float*)d_in[16];
    const float* ca_wh = (const float*)d_in[17];
    const float* ca_bh = (const float*)d_in[18];
    const float* ca_ww = (const float*)d_in[19];
    const float* ca_bw = (const float*)d_in[20];
    float* out = (float*)d_out;

    cudaFuncSetAttribute(conv_mma<1, WID, CIN,  CIN>, cudaFuncAttributeMaxDynamicSharedMemorySize, CONV_DSM);
    cudaFuncSetAttribute(conv_mma<2, WID, 1152, WID>, cudaFuncAttributeMaxDynamicSharedMemorySize, CONV_DSM);
    cudaFuncSetAttribute(conv_mma<3, OUP, WID,  WID>, cudaFuncAttributeMaxDynamicSharedMemorySize, CONV_DSM);

    kZ_zero<<<(NB*HW + 255)/256, 256>>>();
    kT_transx<<<dim3(HW/64, CIN/64, NB), 256>>>(x, sm_w);
    kW_split<1><<<(WID*CIN + 255)/256, 256>>>(w1);
    kB_dilate<<<dim3(NB, 7), 256>>>(sm_b);
    kL_list<<<NB, 256>>>();
    kD_cmask<1><<<dim3(NB, WID/64), 256>>>(cm1_w, cm1_b);
    kLc<1><<<NB, 256>>>();

    conv_mma<1, WID, CIN, CIN><<<dim3(25, 2, NB), 256, CONV_DSM>>>(b1, out);

    kW_split<2><<<(WID*1152 + 255)/256, 256>>>(w2);
    kD_cmask<2><<<dim3(NB, WID/64), 256>>>(cm2_w, cm2_b);

    conv_mma<2, WID, 1152, WID><<<dim3(25, 2, NB), 256, CONV_DSM>>>(b2, out);

    kW_split<3><<<(OUP*WID + 255)/256, 256>>>(w3);
    kD_cmask<3><<<dim3(NB, OUP/64), 256>>>(cm3_w, cm3_b);
    kLc<3><<<NB, 256>>>();

    conv_mma<3, OUP, WID, WID><<<dim3(25, 8, NB), 256, CONV_DSM>>>(b3, out);

    kH_rowcol<<<NB * OUP, 256>>>(out);
    kI1<<<dim3(NB, 14), 256>>>(ca_w1, ca_b1);
    kI2<<<dim3(NB, 8),  256>>>(ca_wh, ca_bh, ca_ww, ca_bw);

    {
        size_t total4 = (size_t)NB * OUP * HW / 4;
        kJ_final<<<(unsigned)((total4 + 255) / 256), 256>>>(x, out);
    }
}

// round 16
// speedup vs baseline: 9.7542x; 1.1314x over previous
#include <cuda_runtime.h>
#include <cuda_bf16.h>
#include <math.h>
#include <stdint.h>

// ---------------------------------------------------------------------------
#define NB   16
#define CIN  512
#define WID  128
#define OUP  512
#define HH   56
#define WW   56
#define HW   (HH*WW)
#define MIP  16

union U8 { __nv_bfloat16 h[8]; uint4 u; };

__device__ __forceinline__ uint32_t smem_u32(const void* p) {
    uint32_t a;
    asm("{ .reg .u64 t; cvta.to.shared.u64 t, %1; cvt.u32.u64 %0, t; }" : "=r"(a) : "l"(p));
    return a;
}
__device__ __forceinline__ void ldsm4(uint32_t* r, uint32_t a) {
    asm volatile("ldmatrix.sync.aligned.m8n8.x4.shared.b16 {%0,%1,%2,%3}, [%4];"
                 : "=r"(r[0]), "=r"(r[1]), "=r"(r[2]), "=r"(r[3]) : "r"(a));
}
__device__ __forceinline__ void mma_bf(float* c, const uint32_t* a, uint32_t b0, uint32_t b1) {
    asm volatile("mma.sync.aligned.m16n8k16.row.col.f32.bf16.bf16.f32 "
                 "{%0,%1,%2,%3}, {%4,%5,%6,%7}, {%8,%9}, {%0,%1,%2,%3};"
                 : "+f"(c[0]), "+f"(c[1]), "+f"(c[2]), "+f"(c[3])
                 : "r"(a[0]), "r"(a[1]), "r"(a[2]), "r"(a[3]), "r"(b0), "r"(b1));
}
__device__ __forceinline__ void cpa16(uint32_t d, const void* s, uint32_t srcsz) {
    asm volatile("cp.async.cg.shared.global [%0], [%1], 16, %2;"
                 :: "r"(d), "l"(s), "r"(srcsz) : "memory");
}
__device__ __forceinline__ void cpa_commit() { asm volatile("cp.async.commit_group;" ::: "memory"); }
template<int N> __device__ __forceinline__ void cpa_wait() {
    asm volatile("cp.async.wait_group %0;" :: "n"(N) : "memory");
}

// ---------------------------------------------------------------------------
// Scratch — __device__ globals, referenced ONLY inside device code.
// gh1/gh2: DENSE stride 128 rows; COMPACT values at cols 0..cnt-1, zeros after
// (never written -> static zero-init).
// ---------------------------------------------------------------------------
__device__ __align__(128) __nv_bfloat16 gx_hi [NB*HW*CIN];
__device__ __align__(128) __nv_bfloat16 gx_lo [NB*HW*CIN];
__device__ __align__(128) __nv_bfloat16 gh1_hi[NB*HW*WID];
__device__ __align__(128) __nv_bfloat16 gh1_lo[NB*HW*WID];
__device__ __align__(128) __nv_bfloat16 gh2_hi[NB*HW*WID];
__device__ __align__(128) __nv_bfloat16 gh2_lo[NB*HW*WID];
__device__ __align__(128) __nv_bfloat16 gw1h[WID*CIN],  gw1l[WID*CIN];
__device__ __align__(128) __nv_bfloat16 gw2bh[NB*WID*1152], gw2bl[NB*WID*1152]; // [b][om][r*128+cc]
__device__ __align__(128) __nv_bfloat16 gw3bh[NB*OUP*WID],  gw3bl[NB*OUP*WID];  // [b][om][cc]
__device__ __align__(16) float g_smlog[NB*HW];
__device__ __align__(16) float g_poolx[NB*CIN];
__device__ __align__(16) float g_pool1[NB*WID];
__device__ __align__(16) float g_pool2[NB*WID];
__device__ __align__(16) float g_ys   [NB*2*HH*MIP];
__device__ __align__(16) int   g_idx  [NB*HW];
__device__ __align__(16) int   g_cnt  [NB];
__device__ __align__(16) int   g_ocl1 [NB*WID];
__device__ __align__(16) int   g_ocl2 [NB*WID];
__device__ __align__(16) int   g_ocl3 [NB*OUP];
__device__ __align__(16) int   g_occ1 [NB];
__device__ __align__(16) int   g_occ2 [NB];
__device__ __align__(16) int   g_occ3 [NB];
__device__ __align__(16) float s_sm [NB*HW];
__device__ __align__(16) float s_smd[NB*HW];
__device__ __align__(16) float s_c1 [NB*WID];
__device__ __align__(16) float s_c2 [NB*WID];
__device__ __align__(16) float s_c3 [NB*OUP];
__device__ __align__(16) float s_xh [NB*OUP*HH];
__device__ __align__(16) float s_xw [NB*OUP*WW];
__device__ __align__(16) float s_ah [NB*OUP*HH];
__device__ __align__(16) float s_aw [NB*OUP*WW];

// ---------------------------------------------------------------------------
__global__ void kZ_zero()
{
    int i = blockIdx.x * 256 + threadIdx.x;
    if (i < NB*HW)  g_smlog[i] = 0.f;
    if (i < NB*CIN) g_poolx[i] = 0.f;
    if (i < NB*WID) { g_pool1[i] = 0.f; g_pool2[i] = 0.f; }
}

// ---------------------------------------------------------------------------
// kT: transpose + bf16-split x -> gx [b,p,c] + fused smask-logit/channel sums
// ---------------------------------------------------------------------------
__global__ __launch_bounds__(256) void kT_transx(const float* __restrict__ x,
                                                 const float* __restrict__ smw)
{
    __shared__ float ts[64][65];
    __shared__ float wsh[64];
    __shared__ float red[4][64];
    const int b  = blockIdx.z;
    const int c0 = blockIdx.y * 64;
    const int p0 = blockIdx.x * 64;
    const int t  = threadIdx.x;

    if (t < 64) wsh[t] = smw[c0 + t];
    {
        int ci = t >> 2, jg = (t & 3) * 16;
        const float* src = x + ((size_t)b * CIN + c0 + ci) * HW + p0 + jg;
        #pragma unroll
        for (int q = 0; q < 4; q++) {
            float4 f = *(const float4*)(src + q * 4);
            ts[ci][jg + q*4 + 0] = f.x; ts[ci][jg + q*4 + 1] = f.y;
            ts[ci][jg + q*4 + 2] = f.z; ts[ci][jg + q*4 + 3] = f.w;
        }
    }
    __syncthreads();
    {
        int g = t >> 6, pi = t & 63;
        float s = 0.f;
        #pragma unroll
        for (int cc = 0; cc < 16; cc++) s += ts[g*16 + cc][pi] * wsh[g*16 + cc];
        red[g][pi] = s;
    }
    __syncthreads();
    if (t < 64)
        atomicAdd(&g_smlog[b * HW + p0 + t], red[0][t] + red[1][t] + red[2][t] + red[3][t]);
    __syncthreads();
    {
        int c = t & 63, pg = t >> 6;
        float s = 0.f;
        #pragma unroll
        for (int i = 0; i < 16; i++) s += ts[c][pg*16 + i];
        red[pg][c] = s;
    }
    __syncthreads();
    if (t < 64)
        atomicAdd(&g_poolx[b * CIN + c0 + t], red[0][t] + red[1][t] + red[2][t] + red[3][t]);
    {
        int pi = t >> 2, cg = (t & 3) * 16;
        __nv_bfloat16* oh = gx_hi + ((size_t)b * HW + p0 + pi) * CIN + c0 + cg;
        __nv_bfloat16* ol = gx_lo + ((size_t)b * HW + p0 + pi) * CIN + c0 + cg;
        #pragma unroll
        for (int g = 0; g < 2; g++) {
            U8 hh, ll;
            #pragma unroll
            for (int j = 0; j < 8; j++) {
                float v = ts[cg + g*8 + j][pi];
                __nv_bfloat16 h = __float2bfloat16(v);
                hh.h[j] = h;
                ll.h[j] = __float2bfloat16(v - __bfloat162float(h));
            }
            *(uint4*)(oh + g*8) = hh.u;
            *(uint4*)(ol + g*8) = ll.u;
        }
    }
}

// ---------------------------------------------------------------------------
// kW1: conv1 weights fp32 -> split bf16 (dense, batch-independent)
// ---------------------------------------------------------------------------
__global__ void kW1_split(const float* __restrict__ W)
{
    int i = blockIdx.x * 256 + threadIdx.x;
    if (i >= WID * CIN) return;
    float v = W[i];
    __nv_bfloat16 h = __float2bfloat16(v);
    gw1h[i] = h;
    gw1l[i] = __float2bfloat16(v - __bfloat162float(h));
}

// ---------------------------------------------------------------------------
// kB: threshold smask logits + 3x3 dilation.  grid (NB, 7).
// ---------------------------------------------------------------------------
__global__ __launch_bounds__(256) void kB_dilate(const float* __restrict__ smb)
{
    __shared__ float s[10][WW];
    int b  = blockIdx.x;
    int r0 = blockIdx.y * 8;
    float sb0 = smb[0];
    for (int i = threadIdx.x; i < 10 * WW; i += 256) {
        int rr = i / WW, cc = i - rr * WW;
        int gr = r0 + rr - 1;
        float m = 0.f;
        if (gr >= 0 && gr < HH)
            m = (g_smlog[b*HW + gr*WW + cc] + sb0) > 0.f ? 1.f : 0.f;
        s[rr][cc] = m;
    }
    __syncthreads();
    for (int i = threadIdx.x; i < 8 * WW; i += 256) {
        int rr = i / WW, cc = i - rr * WW;
        s_sm[b*HW + (r0+rr)*WW + cc] = s[rr+1][cc];
        float m = 0.f;
        #pragma unroll
        for (int dy = 0; dy < 3; dy++) {
            #pragma unroll
            for (int dx = -1; dx <= 1; dx++) {
                int xx = cc + dx; if (xx < 0 || xx >= WW) continue;
                m = fmaxf(m, s[rr+dy][xx]);
            }
        }
        s_smd[b*HW + (r0+rr)*WW + cc] = m;
    }
}

// ---------------------------------------------------------------------------
// Ordered ballot compaction: pixels (kL_list) and channels (kLc<S>).
// ---------------------------------------------------------------------------
__global__ __launch_bounds__(256) void kL_list()
{
    __shared__ int wsum[8], wbase[8], total;
    const int b = blockIdx.x, t = threadIdx.x;
    const int wrp = t >> 5, lane = t & 31;
    if (t == 0) total = 0;
    __syncthreads();
    for (int i0 = 0; i0 < HW; i0 += 256) {
        int i = i0 + t;
        int f = (i < HW) ? (s_sm[b*HW + i] > 0.5f ? 1 : 0) : 0;
        unsigned bal = __ballot_sync(0xffffffffu, f);
        int wp = __popc(bal & ((1u << lane) - 1u));
        if (lane == 0) wsum[wrp] = __popc(bal);
        __syncthreads();
        if (t == 0) {
            int acc = total;
            #pragma unroll
            for (int w = 0; w < 8; w++) { wbase[w] = acc; acc += wsum[w]; }
            total = acc;
        }
        __syncthreads();
        if (f) g_idx[b*HW + wbase[wrp] + wp] = i;
        __syncthreads();
    }
    if (t == 0) g_cnt[b] = total;
}

template<int STAGE>
__global__ __launch_bounds__(256) void kLc()
{
    constexpr int CO = (STAGE == 3) ? OUP : WID;
    const float* mask = (STAGE == 1) ? s_c1 : (STAGE == 2 ? s_c2 : s_c3);
    int* list = (STAGE == 1) ? g_ocl1 : (STAGE == 2 ? g_ocl2 : g_ocl3);
    int* cnto = (STAGE == 1) ? g_occ1 : (STAGE == 2 ? g_occ2 : g_occ3);
    __shared__ int wsum[8], wbase[8], total;
    const int b = blockIdx.x, t = threadIdx.x;
    const int wrp = t >> 5, lane = t & 31;
    if (t == 0) total = 0;
    __syncthreads();
    for (int i0 = 0; i0 < CO; i0 += 256) {
        int i = i0 + t;
        int f = (i < CO) ? (mask[b*CO + i] > 0.5f ? 1 : 0) : 0;
        unsigned bal = __ballot_sync(0xffffffffu, f);
        int wp = __popc(bal & ((1u << lane) - 1u));
        if (lane == 0) wsum[wrp] = __popc(bal);
        __syncthreads();
        if (t == 0) {
            int acc = total;
            #pragma unroll
            for (int w = 0; w < 8; w++) { wbase[w] = acc; acc += wsum[w]; }
            total = acc;
        }
        __syncthreads();
        if (f) list[b*CO + wbase[wrp] + wp] = i;
        __syncthreads();
    }
    if (t == 0) cnto[b] = total;
}

// ---------------------------------------------------------------------------
// kD: channel mask from accumulated sums.  grid (NB, CO/64).
// ---------------------------------------------------------------------------
template<int STAGE>
__global__ __launch_bounds__(256) void kD_cmask(const float* __restrict__ w,
                                                const float* __restrict__ bias)
{
    constexpr int CI = (STAGE == 1) ? CIN : WID;
    constexpr int CO = (STAGE == 3) ? OUP : WID;
    const float* psum = (STAGE == 1) ? g_poolx : (STAGE == 2 ? g_pool1 : g_pool2);
    float*       mask = (STAGE == 1) ? s_c1 : (STAGE == 2 ? s_c2 : s_c3);
    int b  = blockIdx.x;
    int o0 = blockIdx.y * 64;
    __shared__ float pr[CI];
    for (int i = threadIdx.x; i < CI; i += 256)
        pr[i] = psum[b*CI + i] * (1.f / HW);
    __syncthreads();
    int wrp = threadIdx.x >> 5, lane = threadIdx.x & 31;
    #pragma unroll
    for (int i = 0; i < 8; i++) {
        int o = o0 + wrp * 8 + i;
        const float* wr = w + (size_t)o * CI;
        float s = 0.f;
        #pragma unroll 4
        for (int c = lane; c < CI; c += 32) s += pr[c] * wr[c];
        #pragma unroll
        for (int off = 16; off > 0; off >>= 1) s += __shfl_xor_sync(0xffffffffu, s, off);
        if (lane == 0) mask[b*CO + o] = (s + bias[o]) > 0.f ? 1.f : 0.f;
    }
}

// ---------------------------------------------------------------------------
// kG2: gathered conv2 weights [b][om][r*128+cc]; om by list2, cc by list1.
// Fixed strides (1152 per om, 128 per r); zeros outside valid region.
// ---------------------------------------------------------------------------
__global__ __launch_bounds__(256) void kG2(const float* __restrict__ W2)
{
    const int b  = blockIdx.y;
    const int c1 = g_occ1[b];
    const int c2 = g_occ2[b];
    const int M2p = (c2 + 63) & ~63;
    const int tot = M2p * 1152;
    for (int e = blockIdx.x * 256 + threadIdx.x; e < tot; e += gridDim.x * 256) {
        int om = e / 1152, rem = e - om * 1152;
        int r = rem >> 7, cc = rem & 127;
        float v = 0.f;
        if (om < c2 && cc < c1) {
            int o = g_ocl2[b*WID + om];
            int c = g_ocl1[b*WID + cc];
            v = W2[(size_t)o * 1152 + c * 9 + r];
        }
        __nv_bfloat16 h = __float2bfloat16(v);
        gw2bh[(size_t)b*WID*1152 + e] = h;
        gw2bl[(size_t)b*WID*1152 + e] = __float2bfloat16(v - __bfloat162float(h));
    }
}

// ---------------------------------------------------------------------------
// kG3: gathered conv3 weights [b][om][cc]; om by list3, cc by list2. Stride 128.
// ---------------------------------------------------------------------------
__global__ __launch_bounds__(256) void kG3(const float* __restrict__ W3)
{
    const int b  = blockIdx.y;
    const int c2 = g_occ2[b];
    const int c3 = g_occ3[b];
    const int M3p = (c3 + 63) & ~63;
    const int tot = M3p * 128;
    for (int e = blockIdx.x * 256 + threadIdx.x; e < tot; e += gridDim.x * 256) {
        int om = e >> 7, cc = e & 127;
        float v = 0.f;
        if (om < c3 && cc < c2) {
            int o = g_ocl3[b*OUP + om];
            int c = g_ocl2[b*WID + cc];
            v = W3[(size_t)o * WID + c];
        }
        __nv_bfloat16 h = __float2bfloat16(v);
        gw3bh[(size_t)b*OUP*WID + e] = h;
        gw3bl[(size_t)b*OUP*WID + e] = __float2bfloat16(v - __bfloat162float(h));
    }
}

// ---------------------------------------------------------------------------
// conv_mma: fully compacted bf16-split GEMM, dense-stride gh layouts.
// MODE 1: K=512 static; oc by list1 -> gh1 compact cols [p][<cnt1>]; pm=smd
// MODE 2: chunks r(0..8)xKC1; px by g_idx; oc by list2 -> gh2 compact; pm=1
// MODE 3: chunks KC2; oc by list3 -> d_out rows list3; pm=s_sm
// ---------------------------------------------------------------------------
#define A_HI 0
#define A_LO 10240
#define B_HI 20480
#define B_LO 25600
#define STG  30720
#define CONV_DSM (2*STG)

template<int MODE>
__global__ __launch_bounds__(256, 3)
void conv_mma(const float* __restrict__ bias, float* __restrict__ xout)
{
    extern __shared__ char dsm[];
    const uint32_t sb = smem_u32(dsm);
    __shared__ float pmv[128], cmb[64], bb[64];
    __shared__ float pool[64];
    __shared__ int   pidx[128];
    __shared__ int   ocl_s[64];

    const int tid  = threadIdx.x;
    const int wid  = tid >> 5;
    const int lane = tid & 31;
    const int b    = blockIdx.z;
    const int m0   = blockIdx.x * 128;
    const int n0g  = blockIdx.y * 64;

    const int cnt1 = g_occ1[b];
    const int cnt2 = (MODE >= 2) ? g_occ2[b] : 0;
    const int KC1  = (cnt1 + 31) >> 5;
    const int KC2  = (cnt2 + 31) >> 5;

    const int ocnt = (MODE == 1) ? cnt1 : (MODE == 2 ? cnt2 : g_occ3[b]);
    if (n0g >= ocnt) return;
    const int cntpx = (MODE == 2) ? g_cnt[b] : HW;
    if (MODE == 2 && m0 >= cntpx) return;

    const int NCr = (MODE == 1) ? 16 : (MODE == 2 ? 9 * KC1 : (KC2 > 0 ? KC2 : 1));

    const __nv_bfloat16* act_h = (MODE == 1) ? gx_hi : (MODE == 2 ? gh1_hi : gh2_hi);
    const __nv_bfloat16* act_l = (MODE == 1) ? gx_lo : (MODE == 2 ? gh1_lo : gh2_lo);
    const __nv_bfloat16* wt_h  = (MODE == 1) ? gw1h : (MODE == 2 ? gw2bh + (size_t)b*WID*1152
                                                                 : gw3bh + (size_t)b*OUP*WID);
    const __nv_bfloat16* wt_l  = (MODE == 1) ? gw1l : (MODE == 2 ? gw2bl + (size_t)b*WID*1152
                                                                 : gw3bl + (size_t)b*OUP*WID);
    const int Astr = (MODE == 1) ? CIN : WID;     // gh rows are dense 128
    const int Bstr = (MODE == 1) ? CIN : (MODE == 2 ? 1152 : 128);

    if (tid < 128) {
        int n = m0 + tid;
        if (MODE == 2) {
            pidx[tid] = (n < cntpx) ? g_idx[b * HW + n] : 0;
            pmv[tid]  = 1.f;
        } else {
            const float* pm = (MODE == 1) ? s_smd : s_sm;
            pmv[tid] = (n < HW) ? pm[b * HW + n] : 0.f;
        }
    }
    if (tid < 64) {
        int oc = n0g + tid;
        bool v = (oc < ocnt);
        const int* list = (MODE == 1) ? g_ocl1 : (MODE == 2 ? g_ocl2 : g_ocl3);
        int tc = v ? list[b * ((MODE == 3) ? OUP : WID) + oc] : 0;
        ocl_s[tid] = tc;
        bb[tid]  = v ? bias[tc] : 0.f;
        cmb[tid] = v ? 1.f : 0.f;
        pool[tid] = 0.f;
    }
    __syncthreads();

    const int prow = tid >> 1;
    const int u0   = (tid & 1) * 2;
    const int brow2 = tid >> 2;
    const int bu    = tid & 3;

    auto prefetch = [&](int ch, int st) {
        const uint32_t sbase = sb + st * STG;
        int c0, koff;
        int r = 0;
        if (MODE == 1)      { c0 = ch * 32; koff = c0; }
        else if (MODE == 2) { r = ch / KC1; int kc = ch - r * KC1; c0 = kc * 32; koff = r * 128 + c0; }
        else                { c0 = ch * 32; koff = c0; }
        // A
        {
            int n = m0 + prow;
            bool valid; int q;
            if (MODE == 2) {
                bool vrow = (n < cntpx);
                int p = vrow ? pidx[prow] : 0;
                int ky = r / 3 - 1, kx = r % 3 - 1;
                int py = p / WW, px = p - py * WW;
                int iy = py + ky, ix = px + kx;
                valid = vrow && iy >= 0 && iy < HH && ix >= 0 && ix < WW;
                q = iy * WW + ix;
            } else { valid = (n < HW); q = n; }
            uint32_t sz = valid ? 16u : 0u;
            const __nv_bfloat16* ah = act_h + ((size_t)b * HW + (valid ? q : 0)) * Astr + c0 + u0 * 8;
            const __nv_bfloat16* al = act_l + ((size_t)b * HW + (valid ? q : 0)) * Astr + c0 + u0 * 8;
            uint32_t dh = sbase + A_HI + prow * 80 + u0 * 16;
            uint32_t dl = sbase + A_LO + prow * 80 + u0 * 16;
            #pragma unroll
            for (int u = 0; u < 2; u++) {
                cpa16(dh + u * 16, ah + u * 8, sz);
                cpa16(dl + u * 16, al + u * 8, sz);
            }
        }
        // B
        {
            size_t rowoff;
            if (MODE == 1) rowoff = (size_t)ocl_s[brow2] * CIN;
            else           rowoff = (size_t)(n0g + brow2) * Bstr;
            cpa16(sbase + B_HI + brow2 * 80 + bu * 16, wt_h + rowoff + koff + bu * 8, 16u);
            cpa16(sbase + B_LO + brow2 * 80 + bu * 16, wt_l + rowoff + koff + bu * 8, 16u);
        }
        cpa_commit();
    };

    float cacc[2][4][4];
    #pragma unroll
    for (int i = 0; i < 2; i++)
        #pragma unroll
        for (int j = 0; j < 4; j++)
            #pragma unroll
            for (int q = 0; q < 4; q++) cacc[i][j][q] = 0.f;

    const int wm = wid >> 1, wn = wid & 1;
    const int lr = lane & 7, s23 = lane >> 3;
    const int arow = (s23 & 1) * 8 + lr, acol = (s23 >> 1) * 8;
    const int brow = (s23 >> 1) * 8 + lr, bcol = (s23 & 1) * 8;

    prefetch(0, 0);
    int buf = 0;
    for (int ch = 0; ch < NCr; ch++) {
        cpa_wait<0>();
        __syncthreads();
        if (ch + 1 < NCr) prefetch(ch + 1, buf ^ 1);

        const uint32_t sbb = sb + buf * STG;
        #pragma unroll
        for (int s = 0; s < 2; s++) {
            const int kb = s * 16;
            uint32_t ah[2][4], al[2][4];
            #pragma unroll
            for (int mi = 0; mi < 2; mi++) {
                uint32_t off = (uint32_t)((wm * 32 + mi * 16 + arow) * 80 + (kb + acol) * 2);
                ldsm4(ah[mi], sbb + A_HI + off);
                ldsm4(al[mi], sbb + A_LO + off);
            }
            #pragma unroll
            for (int np = 0; np < 2; np++) {
                uint32_t bh[4], bl[4];
                uint32_t off = (uint32_t)((wn * 32 + np * 16 + brow) * 80 + (kb + bcol) * 2);
                ldsm4(bh, sbb + B_HI + off);
                ldsm4(bl, sbb + B_LO + off);
                #pragma unroll
                for (int mi = 0; mi < 2; mi++) {
                    mma_bf(cacc[mi][np * 2],     ah[mi], bh[0], bh[1]);
                    mma_bf(cacc[mi][np * 2 + 1], ah[mi], bh[2], bh[3]);
                }
                #pragma unroll
                for (int mi = 0; mi < 2; mi++) {
                    mma_bf(cacc[mi][np * 2],     al[mi], bh[0], bh[1]);
                    mma_bf(cacc[mi][np * 2 + 1], al[mi], bh[2], bh[3]);
                }
                #pragma unroll
                for (int mi = 0; mi < 2; mi++) {
                    mma_bf(cacc[mi][np * 2],     ah[mi], bl[0], bl[1]);
                    mma_bf(cacc[mi][np * 2 + 1], ah[mi], bl[2], bl[3]);
                }
            }
        }
        buf ^= 1;
    }

    // ---- epilogue ----
    const int g = lane >> 2, tg = lane & 3;
    if (MODE != 3) {
        __nv_bfloat16* ohg = (MODE == 1 ? gh1_hi : gh2_hi);
        __nv_bfloat16* olg = (MODE == 1 ? gh1_lo : gh2_lo);
        float lsum[8];
        #pragma unroll
        for (int i = 0; i < 8; i++) lsum[i] = 0.f;
        #pragma unroll
        for (int mi = 0; mi < 2; mi++) {
            #pragma unroll
            for (int h = 0; h < 2; h++) {
                int pl = wm * 32 + mi * 16 + g + h * 8;
                int n  = m0 + pl;
                bool store = (MODE == 2) ? (n < cntpx) : (n < HW);
                if (store) {
                    int p = (MODE == 2) ? pidx[pl] : n;
                    float pmx = pmv[pl];
                    size_t rowoff = ((size_t)b * HW + p) * WID;    // dense stride
                    #pragma unroll
                    for (int nf = 0; nf < 4; nf++) {
                        int ocl = wn * 32 + nf * 8 + tg * 2;
                        float v0 = fmaxf(cacc[mi][nf][h*2+0] + bb[ocl],   0.f) * cmb[ocl]   * pmx;
                        float v1 = fmaxf(cacc[mi][nf][h*2+1] + bb[ocl+1], 0.f) * cmb[ocl+1] * pmx;
                        lsum[nf*2 + 0] += v0;
                        lsum[nf*2 + 1] += v1;
                        // compact-position pair store; invalid slots write exact 0
                        __nv_bfloat16 h0 = __float2bfloat16(v0);
                        __nv_bfloat16 h1 = __float2bfloat16(v1);
                        __nv_bfloat162 hp; hp.x = h0; hp.y = h1;
                        *(__nv_bfloat162*)(ohg + rowoff + n0g + ocl) = hp;
                        __nv_bfloat162 lp;
                        lp.x = __float2bfloat16(v0 - __bfloat162float(h0));
                        lp.y = __float2bfloat16(v1 - __bfloat162float(h1));
                        *(__nv_bfloat162*)(olg + rowoff + n0g + ocl) = lp;
                    }
                }
            }
        }
        #pragma unroll
        for (int nf = 0; nf < 4; nf++) {
            int ocl = wn * 32 + nf * 8 + tg * 2;
            atomicAdd(&pool[ocl],     lsum[nf*2 + 0]);
            atomicAdd(&pool[ocl + 1], lsum[nf*2 + 1]);
        }
        __syncthreads();
        float* gpool = (MODE == 1) ? g_pool1 : g_pool2;
        if (tid < 64 && n0g + tid < ocnt)
            atomicAdd(&gpool[b * WID + ocl_s[tid]], pool[tid]);
    } else {
        float* tf = (float*)dsm;
        __syncthreads();
        #pragma unroll
        for (int mi = 0; mi < 2; mi++)
            #pragma unroll
            for (int h = 0; h < 2; h++) {
                int pl = wm * 32 + mi * 16 + g + h * 8;
                float pmx = pmv[pl];
                #pragma unroll
                for (int nf = 0; nf < 4; nf++) {
                    int ocl = wn * 32 + nf * 8 + tg * 2;
                    tf[ocl * 132 + pl]       = (cacc[mi][nf][h*2+0] + bb[ocl])   * cmb[ocl]   * pmx;
                    tf[(ocl + 1) * 132 + pl] = (cacc[mi][nf][h*2+1] + bb[ocl+1]) * cmb[ocl+1] * pmx;
                }
            }
        __syncthreads();
        int ocl = tid >> 2, q = tid & 3;
        if (n0g + ocl < ocnt && m0 + q * 32 < HW) {
            float* orow = xout + ((size_t)b * OUP + ocl_s[ocl]) * HW + m0 + q * 32;
            const float* src = tf + ocl * 132 + q * 32;
            #pragma unroll
            for (int gi = 0; gi < 8; gi++)
                *(float4*)(orow + gi * 4) = *(const float4*)(src + gi * 4);
        }
    }
}

// ---------------------------------------------------------------------------
// kH: row/col means; cm3=0 rows are zero without touching d_out (unwritten).
// ---------------------------------------------------------------------------
__global__ __launch_bounds__(256) void kH_rowcol(const float* __restrict__ h3)
{
    __shared__ float img[HW];
    int bc = blockIdx.x;
    int t = threadIdx.x;
    if (s_c3[bc] < 0.5f) {
        if (t < WW) s_xw[bc * WW + t] = 0.f;
        if (t >= 64 && t < 64 + HH) s_xh[bc * HH + t - 64] = 0.f;
        return;
    }
    const float* src = h3 + (size_t)bc * HW;
    for (int i = t; i < HW; i += 256) img[i] = src[i];
    __syncthreads();
    if (t < WW) {
        float s = 0.f;
        #pragma unroll 8
        for (int h = 0; h < HH; h++) s += img[h * WW + t];
        s_xw[bc * WW + t] = s * (1.f / HH);
    } else if (t >= 64 && t < 64 + HH) {
        int r = t - 64;
        float s = 0.f;
        #pragma unroll 8
        for (int w = 0; w < WW; w++) s += img[r * WW + w];
        s_xh[bc * HH + r] = s * (1.f / WW);
    }
}

// ---------------------------------------------------------------------------
__global__ __launch_bounds__(256) void kI1(const float* __restrict__ w1,
                                           const float* __restrict__ b1)
{
    __shared__ float w1s[MIP * OUP];
    const int b = blockIdx.x;
    const int t = threadIdx.x;
    for (int i = t; i < MIP * OUP; i += 256) w1s[i] = w1[i];
    __syncthreads();
    const int wid = t >> 5, lane = t & 31;
    const int ti = blockIdx.y * 8 + wid;
    const float* src = (ti < HH)
        ? (s_xh + (size_t)b * OUP * HH + ti)
        : (s_xw + (size_t)b * OUP * WW + (ti - HH));
    float acc[MIP];
    #pragma unroll
    for (int m = 0; m < MIP; m++) acc[m] = 0.f;
    #pragma unroll 4
    for (int cc = 0; cc < 16; cc++) {
        int c = cc * 32 + lane;
        float v = src[(size_t)c * HH];
        #pragma unroll
        for (int m = 0; m < MIP; m++) acc[m] += v * w1s[m * OUP + c];
    }
    #pragma unroll
    for (int off = 16; off > 0; off >>= 1)
        #pragma unroll
        for (int m = 0; m < MIP; m++) acc[m] += __shfl_xor_sync(0xffffffffu, acc[m], off);
    if (lane == 0) {
        #pragma unroll
        for (int m = 0; m < MIP; m++) {
            float u = acc[m] + b1[m];
            float r6 = fminf(fmaxf(u + 3.f, 0.f), 6.f);
            g_ys[((size_t)b * 2 * HH + ti) * MIP + m] = u * r6 * (1.f / 6.f);
        }
    }
}

__global__ __launch_bounds__(256) void kI2(const float* __restrict__ wh,
                                           const float* __restrict__ bh,
                                           const float* __restrict__ ww,
                                           const float* __restrict__ bw)
{
    __shared__ float ys[2 * HH * MIP];
    const int b  = blockIdx.x;
    const int c0 = blockIdx.y * 64;
    const int t  = threadIdx.x;
    for (int i = t; i < 2 * HH * MIP; i += 256) ys[i] = g_ys[(size_t)b * 2 * HH * MIP + i];
    __syncthreads();
    const int cl = t >> 2, jq = t & 3;
    const int c  = c0 + cl;
    float whr[MIP], wwr[MIP];
    #pragma unroll
    for (int m = 0; m < MIP; m++) { whr[m] = wh[c*MIP + m]; wwr[m] = ww[c*MIP + m]; }
    const float bhc = bh[c], bwc = bw[c];
    #pragma unroll 2
    for (int jj = 0; jj < 14; jj++) {
        int j = jq * 14 + jj;
        float sh = bhc, sw = bwc;
        #pragma unroll
        for (int m = 0; m < MIP; m++) {
            sh += ys[j * MIP + m]        * whr[m];
            sw += ys[(HH + j) * MIP + m] * wwr[m];
        }
        s_ah[((size_t)b * OUP + c) * HH + j] = 1.f / (1.f + expf(-sh));
        s_aw[((size_t)b * OUP + c) * WW + j] = 1.f / (1.f + expf(-sw));
    }
}

// ---------------------------------------------------------------------------
// kJ: out = relu(h3*m3*ah*aw + x); m3 masks rows conv3 never wrote (poison).
// ---------------------------------------------------------------------------
__global__ void kJ_final(const float* __restrict__ x, float* __restrict__ out)
{
    size_t i = (size_t)blockIdx.x * blockDim.x + threadIdx.x;
    const size_t total4 = (size_t)NB * OUP * HW / 4;
    if (i >= total4) return;
    size_t e   = i * 4;
    size_t row = e / WW;
    int    w   = (int)(e - row * WW);
    size_t bc  = row / HH;
    float m3   = s_c3[bc];
    float a_h  = s_ah[row] * m3;
    const float* awp = s_aw + bc * WW + w;
    float4 hv = *(float4*)(out + e);
    float4 xv = *(const float4*)(x + e);
    float4 r;
    r.x = fmaxf(hv.x * a_h * awp[0] + xv.x, 0.f);
    r.y = fmaxf(hv.y * a_h * awp[1] + xv.y, 0.f);
    r.z = fmaxf(hv.z * a_h * awp[2] + xv.z, 0.f);
    r.w = fmaxf(hv.w * a_h * awp[3] + xv.w, 0.f);
    *(float4*)(out + e) = r;
}

// ---------------------------------------------------------------------------
extern "C" void kernel_launch(void* const* d_in, const int* in_sizes, int n_in,
                              void* d_out, int out_size)
{
    const float* x     = (const float*)d_in[0];
    const float* sm_w  = (const float*)d_in[1];
    const float* sm_b  = (const float*)d_in[2];
    const float* cm1_w = (const float*)d_in[3];
    const float* cm1_b = (const float*)d_in[4];
    const float* cm2_w = (const float*)d_in[5];
    const float* cm2_b = (const float*)d_in[6];
    const float* cm3_w = (const float*)d_in[7];
    const float* cm3_b = (const float*)d_in[8];
    const float* w1    = (const float*)d_in[9];
    const float* b1    = (const float*)d_in[10];
    const float* w2    = (const float*)d_in[11];
    const float* b2    = (const float*)d_in[12];
    const float* w3    = (const float*)d_in[13];
    const float* b3    = (const float*)d_in[14];
    const float* ca_w1 = (const float*)d_in[15];
    const float* ca_b1 = (const float*)d_in[16];
    const float* ca_wh = (const float*)d_in[17];
    const float* ca_bh = (const float*)d_in[18];
    const float* ca_ww = (const float*)d_in[19];
    const float* ca_bw = (const float*)d_in[20];
    float* out = (float*)d_out;

    cudaFuncSetAttribute(conv_mma<1>, cudaFuncAttributeMaxDynamicSharedMemorySize, CONV_DSM);
    cudaFuncSetAttribute(conv_mma<2>, cudaFuncAttributeMaxDynamicSharedMemorySize, CONV_DSM);
    cudaFuncSetAttribute(conv_mma<3>, cudaFuncAttributeMaxDynamicSharedMemorySize, CONV_DSM);

    kZ_zero<<<(NB*HW + 255)/256, 256>>>();
    kT_transx<<<dim3(HW/64, CIN/64, NB), 256>>>(x, sm_w);
    kW1_split<<<(WID*CIN + 255)/256, 256>>>(w1);
    kB_dilate<<<dim3(NB, 7), 256>>>(sm_b);
    kL_list<<<NB, 256>>>();
    kD_cmask<1><<<dim3(NB, WID/64), 256>>>(cm1_w, cm1_b);
    kLc<1><<<NB, 256>>>();

    conv_mma<1><<<dim3(25, 2, NB), 256, CONV_DSM>>>(b1, out);

    kD_cmask<2><<<dim3(NB, WID/64), 256>>>(cm2_w, cm2_b);
    kLc<2><<<NB, 256>>>();
    kG2<<<dim3(64, NB), 256>>>(w2);

    conv_mma<2><<<dim3(25, 2, NB), 256, CONV_DSM>>>(b2, out);

    kD_cmask<3><<<dim3(NB, OUP/64), 256>>>(cm3_w, cm3_b);
    kLc<3><<<NB, 256>>>();
    kG3<<<dim3(32, NB), 256>>>(w3);

    conv_mma<3><<<dim3(25, 8, NB), 256, CONV_DSM>>>(b3, out);

    kH_rowcol<<<NB * OUP, 256>>>(out);
    kI1<<<dim3(NB, 14), 256>>>(ca_w1, ca_b1);
    kI2<<<dim3(NB, 8),  256>>>(ca_wh, ca_bh, ca_ww, ca_bw);

    {
        size_t total4 = (size_t)NB * OUP * HW / 4;
        kJ_final<<<(unsigned)((total4 + 255) / 256), 256>>>(x, out);
    }
}